// round 7
// baseline (speedup 1.0000x reference)
#include <cuda_runtime.h>
#include <math.h>

#define NN      3072
#define TWO_N   6144
#define DIM     128
#define SEQ     16
#define EE      196608
#define CC      100
#define HH      4
#define HD      32
#define INV_SQRT_HD 0.17677669529663687f
#define DELTA_T 0.1f
#define PRESERVE 0.1f

#define OUT_CAT   0
#define OUT_SKILL (TWO_N * DIM)
#define OUT_PRED  (2 * TWO_N * DIM)
#define OUT_LOSS  (2 * TWO_N * DIM + TWO_N * TWO_N)

// ----------------------------- device scratch -----------------------------
__device__ float g_dsum[DIM];
__device__ float g_ssum[DIM];
__device__ float g_cat2[(size_t)TWO_N * 2 * DIM];
__device__ float g_fused[(size_t)TWO_N * DIM];
__device__ float g_s1[(size_t)TWO_N * DIM];
__device__ float g_s2[(size_t)TWO_N * DIM];
__device__ float g_scores[(size_t)TWO_N * TWO_N];   // general path only
__device__ float g_Adense[(size_t)TWO_N * TWO_N];   // zero between launches (exch trick)
__device__ float g_deg[TWO_N];
__device__ float g_degsp[TWO_N];
__device__ float g_xw[(size_t)TWO_N * DIM];
__device__ float g_agg[(size_t)TWO_N * DIM];
__device__ float g_tmpA[(size_t)TWO_N * DIM];
__device__ float g_tmpB[(size_t)TWO_N * DIM];
__device__ float g_emb[(size_t)TWO_N * DIM];
__device__ float g_sm[(size_t)TWO_N * CC];
__device__ float g_pooled[CC * DIM];
__device__ float g_G[CC * CC];
__device__ float g_kp2[CC * DIM];
__device__ float g_vp2[CC * DIM];
__device__ float g_qp2[(size_t)TWO_N * DIM];
__device__ float g_wt[DIM * DIM];
__device__ float g_acc[8];   // [0]=||A||^2 [1]=<A,SS^T> [2]=ent_sum [3]=||S^T S||^2
__device__ int   g_flag;     // 1 if sender == receiver -> scores == 0 exactly

// MHA1 GEMM-chain buffers
__device__ float g_qv[(size_t)TWO_N * DIM];
__device__ float g_qp1[(size_t)TWO_N * DIM];
__device__ float g_U[(size_t)TWO_N * 4 * DIM];   // [2N, 512]
__device__ float g_c[(size_t)TWO_N * 4 * DIM];   // [2N, 512]
__device__ float g_wqt[DIM * DIM];
__device__ float g_Mk[DIM * 4 * DIM];            // [128, 512]
__device__ float g_Zcat[4 * DIM * DIM];          // [512, 128]
__device__ float g_zb[DIM];

// CSR for sparse GCN (gather form)
__device__ int   g_csr_cnt[TWO_N];      // counts, then cursors
__device__ int   g_csr_off[TWO_N + 1];
__device__ int   g_csr_src[EE];
__device__ float g_csr_coef[EE];

// ----------------------------- helpers -----------------------------
__device__ __forceinline__ float blockReduceSum(float v, float* sh) {
    int t = threadIdx.x;
    sh[t] = v; __syncthreads();
    for (int s = blockDim.x >> 1; s > 0; s >>= 1) {
        if (t < s) sh[t] += sh[t + s];
        __syncthreads();
    }
    float r = sh[0]; __syncthreads();
    return r;
}
__device__ __forceinline__ float blockReduceMax(float v, float* sh) {
    int t = threadIdx.x;
    sh[t] = v; __syncthreads();
    for (int s = blockDim.x >> 1; s > 0; s >>= 1) {
        if (t < s) sh[t] = fmaxf(sh[t], sh[t + s]);
        __syncthreads();
    }
    float r = sh[0]; __syncthreads();
    return r;
}

// ----------------------------- init -----------------------------
__global__ void k_init(const float* __restrict__ sender, const float* __restrict__ receiver) {
    int i = blockIdx.x * blockDim.x + threadIdx.x;
    if (i < TWO_N) { g_deg[i] = 1.0f; g_degsp[i] = 1.0f; g_csr_cnt[i] = 0; }
    if (i < CC * DIM) g_pooled[i] = 0.f;
    if (i < CC * CC) g_G[i] = 0.f;
    if (i < 2 * DIM) (i < DIM ? g_dsum : g_ssum)[i & 127] = 0.f;
    if (i < 8) g_acc[i] = 0.f;
    if (i == 0) g_flag = (sender[0] == receiver[0]) ? 1 : 0;
}

// ----------------------------- seq last-step sums (atomic partials) -----------------------------
__global__ void k_seqsum(const float* __restrict__ demand, const float* __restrict__ supply) {
    int tensor = blockIdx.x, chunk = blockIdx.y, d = threadIdx.x;
    const float* base = tensor ? supply : demand;
    float acc = 0.f;
    int n0 = chunk * 128;
    for (int n = n0; n < n0 + 128; n++)
        acc += base[(size_t)n * SEQ * DIM + (size_t)(SEQ - 1) * DIM + d];
    atomicAdd(&(tensor ? g_ssum : g_dsum)[d], acc);
}

// ----------------------------- fused weight precompute (one launch) -----------------------------
__global__ void k_prep(const float* __restrict__ m1wi, const float* __restrict__ m1wo,
                       const float* __restrict__ m1bo, const float* __restrict__ m1bi,
                       const float* __restrict__ m2wi) {
    int b = blockIdx.x;
    int t = threadIdx.x;  // 128
    if (b < 128) {                       // WqT
        int i = b * 128 + t;
        int k = i >> 7, tt = i & 127;
        g_wqt[i] = m1wi[(size_t)tt * DIM + k];
    } else if (b < 640) {                // Mk
        int i = (b - 128) * 128 + t;
        int j = i >> 9, col = i & 511;
        int h = col >> 7, d = col & 127;
        const float* wk = m1wi + (size_t)DIM * DIM;
        g_Mk[i] = ((j >> 5) == h) ? wk[(size_t)j * DIM + d] : 0.f;
    } else if (b < 1152) {               // Zcat
        int row = b - 640;               // 0..511
        int h = row >> 7, d = row & 127;
        const float* wv = m1wi + (size_t)2 * DIM * DIM;
        float acc = 0.f;
        #pragma unroll 8
        for (int j = 0; j < 32; j++)
            acc += m1wo[(size_t)t * DIM + h * 32 + j] * wv[(size_t)(h * 32 + j) * DIM + d];
        g_Zcat[(size_t)row * DIM + t] = acc;
    } else if (b == 1152) {              // zb
        const float* bv = m1bi + 2 * DIM;
        float acc = m1bo[t];
        #pragma unroll 8
        for (int k = 0; k < DIM; k++) acc += m1wo[(size_t)t * DIM + k] * bv[k];
        g_zb[t] = acc;
    } else {                             // m2wi transpose -> g_wt
        int i = (b - 1153) * 128 + t;
        int n = i >> 7, k = i & 127;
        g_wt[(size_t)k * DIM + n] = m2wi[(size_t)n * DIM + k];
    }
}

// ----------------------------- qv build + cat2 first half + out_cat -----------------------------
__global__ void k_qv(const float* __restrict__ skill, float* __restrict__ out_cat) {
    int i = blockIdx.x * 256 + threadIdx.x;
    if (i >= TWO_N * DIM) return;
    int b = i >> 7, t = i & 127;
    bool dem = b < NN;
    int idx = dem ? b : b - NN;
    float sv = skill[(size_t)idx * DIM + t];
    g_qv[i] = sv + (dem ? g_dsum : g_ssum)[t];
    g_cat2[(size_t)b * 2 * DIM + t] = sv;
    out_cat[i] = sv;
}

// ----------------------------- MHA1 attention core (per batch row) -----------------------------
__global__ void k_attn1(const float* __restrict__ demand, const float* __restrict__ supply,
                        const float* __restrict__ bi) {
    int b = blockIdx.x;
    int t = threadIdx.x;  // 128
    int w = t >> 5, lane = t & 31;
    bool dem = b < NN;
    int idx = dem ? b : b - NN;
    const float* seq = (dem ? demand : supply) + (size_t)idx * SEQ * DIM;

    __shared__ float sh_seq[SEQ][DIM + 1];
    __shared__ float sh_U[HH][DIM];
    __shared__ float sh_p[HH][SEQ];

    for (int i = t; i < SEQ * DIM; i += 128) sh_seq[i >> 7][i & 127] = seq[i];
    for (int i = t; i < HH * DIM; i += 128) sh_U[i >> 7][i & 127] = g_U[(size_t)b * 512 + i];
    __syncthreads();

    const float* bk = bi + DIM;
    float qb = g_qp1[(size_t)b * DIM + w * HD + lane] * bk[w * HD + lane];
    #pragma unroll
    for (int o = 16; o > 0; o >>= 1) qb += __shfl_xor_sync(0xffffffff, qb, o);

    float myl = -1e30f;
    if (lane < SEQ) {
        float acc = 0.f;
        #pragma unroll 16
        for (int d = 0; d < DIM; d++) acc += sh_U[w][d] * sh_seq[lane][d];
        myl = (acc + qb) * INV_SQRT_HD;
    }
    float mx = myl;
    #pragma unroll
    for (int o = 8; o > 0; o >>= 1) mx = fmaxf(mx, __shfl_xor_sync(0xffffffff, mx, o));
    float e = (lane < SEQ) ? expf(myl - mx) : 0.f;
    float sm = e;
    #pragma unroll
    for (int o = 8; o > 0; o >>= 1) sm += __shfl_xor_sync(0xffffffff, sm, o);
    if (lane < SEQ) sh_p[w][lane] = e / sm;
    __syncthreads();

    #pragma unroll
    for (int k = 0; k < 4; k++) {
        int d = lane + 32 * k;
        float acc = 0.f;
        #pragma unroll
        for (int s = 0; s < SEQ; s++) acc += sh_p[w][s] * sh_seq[s][d];
        g_c[(size_t)b * 512 + w * DIM + d] = acc;
    }
}

// ----------------------------- generic SGEMM: C = A[MxK] @ B[KxN] (+bias) -----------------------------
__global__ void k_sgemm(const float* __restrict__ A, const float* __restrict__ B,
                        const float* __restrict__ bias, float* __restrict__ Cmat,
                        int M, int Nn, int K, int ldc) {
    const int BM = 64, BN = 128, BK = 16;
    __shared__ float As[BK][BM];
    __shared__ float Bs[BK][BN];
    int bm = blockIdx.y * BM;
    int bn = blockIdx.x * BN;
    int tid = threadIdx.x;
    int tr = tid >> 4;
    int tc = tid & 15;
    float acc[4][8];
    #pragma unroll
    for (int r = 0; r < 4; r++)
        #pragma unroll
        for (int c = 0; c < 8; c++) acc[r][c] = 0.f;

    for (int k0 = 0; k0 < K; k0 += BK) {
        #pragma unroll
        for (int j = 0; j < 4; j++) {
            int idx = tid + 256 * j;
            int m = idx >> 4, kk = idx & 15;
            As[kk][m] = A[(size_t)(bm + m) * K + k0 + kk];
        }
        #pragma unroll
        for (int j = 0; j < 8; j++) {
            int idx = tid + 256 * j;
            int kk = idx >> 7, n = idx & 127;
            float v = 0.f;
            if (bn + n < Nn) v = B[(size_t)(k0 + kk) * Nn + bn + n];
            Bs[kk][n] = v;
        }
        __syncthreads();
        #pragma unroll
        for (int kk = 0; kk < BK; kk++) {
            float a[4], bb[8];
            #pragma unroll
            for (int r = 0; r < 4; r++) a[r] = As[kk][tr * 4 + r];
            #pragma unroll
            for (int c = 0; c < 8; c++) bb[c] = Bs[kk][tc * 8 + c];
            #pragma unroll
            for (int r = 0; r < 4; r++)
                #pragma unroll
                for (int c = 0; c < 8; c++) acc[r][c] += a[r] * bb[c];
        }
        __syncthreads();
    }
    #pragma unroll
    for (int r = 0; r < 4; r++) {
        int m = bm + tr * 4 + r;
        if (m >= M) continue;
        #pragma unroll
        for (int c = 0; c < 8; c++) {
            int n = bn + tc * 8 + c;
            if (n < Nn) {
                float v = acc[r][c];
                if (bias) v += bias[n];
                Cmat[(size_t)m * ldc + n] = v;
            }
        }
    }
}

// ----------------------------- tanh prep (general path only) -----------------------------
__global__ void k_tanhprep(const float* __restrict__ sender, const float* __restrict__ receiver) {
    if (g_flag) return;
    int i = blockIdx.x * 256 + threadIdx.x;
    if (i >= TWO_N * DIM) return;
    float f = g_fused[i];
    g_s1[i] = tanhf(sender[0] * f);
    g_s2[i] = tanhf(receiver[0] * f);
}

// ----------------------------- scores (general path only; grid-stride) -----------------------------
__global__ void k_scores() {
    if (g_flag) return;
    __shared__ float A1[16][DIM], A2[16][DIM], B1[16][DIM], B2[16][DIM];
    int t = threadIdx.x;  // 256
    const int TILES = TWO_N / 16;
    for (int tile = blockIdx.x; tile < TILES * TILES; tile += gridDim.x) {
        int i0 = (tile / TILES) * 16, j0 = (tile % TILES) * 16;
        __syncthreads();
        for (int j = 0; j < 8; j++) {
            int idx = t + 256 * j;
            int r = idx >> 7, c = idx & 127;
            A1[r][c] = g_s1[(size_t)(i0 + r) * DIM + c];
            A2[r][c] = g_s2[(size_t)(i0 + r) * DIM + c];
            B1[r][c] = g_s1[(size_t)(j0 + r) * DIM + c];
            B2[r][c] = g_s2[(size_t)(j0 + r) * DIM + c];
        }
        __syncthreads();
        int ti = t >> 4, tj = t & 15;
        float acc = 0.f;
        for (int k = 0; k < DIM; k++)
            acc += A1[ti][k] * B2[tj][k] - A2[ti][k] * B1[tj][k];
        g_scores[(size_t)(i0 + ti) * TWO_N + j0 + tj] = acc;
    }
}

// ----------------------------- row softmax -> pred_g (+ col-deg), or zero-fill -----------------------------
__global__ void k_predg(float* __restrict__ out_pred) {
    int row = blockIdx.x;
    int t = threadIdx.x;  // 256
    __shared__ float sh[256];
    float4* outr = reinterpret_cast<float4*>(out_pred + (size_t)row * TWO_N);
    if (g_flag) {
        float4 z = make_float4(0.f, 0.f, 0.f, 0.f);
        for (int i = t; i < TWO_N / 4; i += 256) outr[i] = z;
        return;
    }
    float* sr = g_scores + (size_t)row * TWO_N;
    float mx = 0.f;
    for (int i = t; i < TWO_N; i += 256) mx = fmaxf(mx, fmaxf(sr[i], 0.f));
    mx = blockReduceMax(mx, sh);
    float sum = 0.f;
    for (int i = t; i < TWO_N; i += 256) sum += expf(fmaxf(sr[i], 0.f) - mx);
    sum = blockReduceSum(sum, sh);
    float inv = 1.f / sum;
    for (int i = t; i < TWO_N; i += 256) {
        float p = expf(fmaxf(sr[i], 0.f) - mx) * inv;
        float pr = fmaxf(p - DELTA_T, 0.f);
        sr[i] = pr;
        out_pred[(size_t)row * TWO_N + i] = pr;
        if (pr != 0.f) atomicAdd(&g_deg[i], pr);
    }
}

// ----------------------------- dense GCN pieces (dinv inline) -----------------------------
__global__ void k_dense_agg() {    // general path: agg = predT@(dinv.*xw) + dinv_i*xw_i
    if (g_flag) return;
    int i0 = blockIdx.x * 32;
    int t = threadIdx.x;  // 256
    __shared__ float pcol[32];
    __shared__ float xrow[DIM];
    int dbase = t & 127, half = t >> 7;
    float acc[16];
    #pragma unroll
    for (int r = 0; r < 16; r++) acc[r] = 0.f;
    for (int j = 0; j < TWO_N; j++) {
        if (t < 32) pcol[t] = g_scores[(size_t)j * TWO_N + i0 + t];
        else if (t >= 128 && t < 256) {
            float sj = rsqrtf(g_deg[j]);
            xrow[t - 128] = sj * g_xw[(size_t)j * DIM + (t - 128)];
        }
        __syncthreads();
        #pragma unroll
        for (int r = 0; r < 16; r++) acc[r] += pcol[half + 2 * r] * xrow[dbase];
        __syncthreads();
    }
    #pragma unroll
    for (int r = 0; r < 16; r++) {
        int i = i0 + half + 2 * r;
        float di = rsqrtf(g_deg[i]);
        g_agg[(size_t)i * DIM + dbase] = acc[r] + di * g_xw[(size_t)i * DIM + dbase];
    }
}

__global__ void k_dense_combine(const float* __restrict__ prev, float* __restrict__ dst,
                                const float* __restrict__ b0, int layer) {
    int i = blockIdx.x * 256 + threadIdx.x;
    if (i >= TWO_N * DIM) return;
    float di = rsqrtf(g_deg[i >> 7]);
    float v = g_flag ? (di * di * g_xw[i]) : (di * g_agg[i]);
    float out = v + b0[layer * DIM + (i & 127)];
    dst[i] = (1.f - PRESERVE) * out + PRESERVE * prev[i];
}

// ----------------------------- sparse GCN: CSR build + gather -----------------------------
__global__ void k_edge1(const int* __restrict__ dst, const float* __restrict__ w) {
    int e = blockIdx.x * 256 + threadIdx.x;
    if (e < EE) {
        int q = dst[e];
        atomicAdd(&g_degsp[q], w[e]);
        atomicAdd(&g_csr_cnt[q], 1);
    }
}
// single block of 1024 threads, 6 counts per thread -> exclusive scan
__global__ void k_scan() {
    __shared__ int sh[1024];
    int tid = threadIdx.x;
    int base = tid * 6;
    int loc[6];
    int s = 0;
    #pragma unroll
    for (int k = 0; k < 6; k++) { loc[k] = s; s += g_csr_cnt[base + k]; }
    sh[tid] = s;
    __syncthreads();
    for (int off = 1; off < 1024; off <<= 1) {
        int add = (tid >= off) ? sh[tid - off] : 0;
        __syncthreads();
        sh[tid] += add;
        __syncthreads();
    }
    int excl = sh[tid] - s;
    #pragma unroll
    for (int k = 0; k < 6; k++) {
        int o = excl + loc[k];
        g_csr_off[base + k] = o;
        g_csr_cnt[base + k] = o;
    }
    if (tid == 1023) g_csr_off[TWO_N] = sh[1023];
}
__global__ void k_fillcsr(const int* __restrict__ src, const int* __restrict__ dst,
                          const float* __restrict__ w) {
    int e = blockIdx.x * 256 + threadIdx.x;
    if (e >= EE) return;
    int s = src[e], q = dst[e];
    int pos = atomicAdd(&g_csr_cnt[q], 1);
    g_csr_src[pos] = s;
    g_csr_coef[pos] = rsqrtf(g_degsp[s]) * rsqrtf(g_degsp[q]) * w[e];
}
// gather; final layer writes emb = tmpA + blend
__global__ void k_spgather(const float* __restrict__ prev, float* __restrict__ dstb,
                           const float* __restrict__ b1, int layer, int addA) {
    int q = blockIdx.x;
    int t = threadIdx.x;  // 128
    float dv = rsqrtf(g_degsp[q]);
    float acc = dv * dv * g_xw[(size_t)q * DIM + t];
    int beg = g_csr_off[q], end = g_csr_off[q + 1];
    int j = beg;
    for (; j + 1 < end; j += 2) {
        float c0 = g_csr_coef[j],     c1 = g_csr_coef[j + 1];
        int   s0 = g_csr_src[j],      s1 = g_csr_src[j + 1];
        acc += c0 * g_xw[(size_t)s0 * DIM + t] + c1 * g_xw[(size_t)s1 * DIM + t];
    }
    if (j < end) acc += g_csr_coef[j] * g_xw[(size_t)g_csr_src[j] * DIM + t];
    float outv = acc + b1[layer * DIM + t];
    float blend = (1.f - PRESERVE) * outv + PRESERVE * prev[(size_t)q * DIM + t];
    if (addA) blend += g_tmpA[(size_t)q * DIM + t];
    dstb[(size_t)q * DIM + t] = blend;
}

// ----------------------------- pooling assignment softmax + entropy -----------------------------
__global__ void k_softmax_s() {
    int r = blockIdx.x, t = threadIdx.x;  // 128
    __shared__ float sh[128];
    float v = (t < CC) ? g_sm[(size_t)r * CC + t] : -1e30f;
    float mx = blockReduceMax(v, sh);
    float e = (t < CC) ? expf(v - mx) : 0.f;
    float sum = blockReduceSum(e, sh);
    float p = e / sum;
    float ent = (t < CC) ? (-p * logf(p + 1e-15f)) : 0.f;
    float es = blockReduceSum(ent, sh);
    if (t < CC) g_sm[(size_t)r * CC + t] = p;
    if (t == 0) atomicAdd(&g_acc[2], es);
}

__global__ void k_pooled() {
    int c4 = blockIdx.x * 4;
    int i0 = blockIdx.y * 768;
    int t = threadIdx.x;  // 128
    float acc[4] = {0.f, 0.f, 0.f, 0.f};
    for (int i = i0; i < i0 + 768; i++) {
        float ev = g_emb[(size_t)i * DIM + t];
        #pragma unroll
        for (int cc = 0; cc < 4; cc++)
            acc[cc] += g_sm[(size_t)i * CC + c4 + cc] * ev;
    }
    #pragma unroll
    for (int cc = 0; cc < 4; cc++)
        atomicAdd(&g_pooled[(size_t)(c4 + cc) * DIM + t], acc[cc]);
}

// ----------------------------- link loss pieces -----------------------------
// fused: scatterA (lane 0) + cross <A,SS^T> (warp per edge)
__global__ void k_edge2(const int* __restrict__ src, const int* __restrict__ dst,
                        const float* __restrict__ w) {
    __shared__ float sh[8];
    int warp = threadIdx.x >> 5, lane = threadIdx.x & 31;
    int e = blockIdx.x * 8 + warp;
    float acc = 0.f;
    if (e < EE) {
        int s = src[e], q = dst[e];
        float we = w[e];
        if (lane == 0) atomicAdd(&g_Adense[(size_t)s * TWO_N + q], we);
        for (int c = lane; c < CC; c += 32)
            acc += g_sm[(size_t)s * CC + c] * g_sm[(size_t)q * CC + c];
        acc *= we;
    }
    for (int o = 16; o > 0; o >>= 1) acc += __shfl_down_sync(0xffffffff, acc, o);
    if (lane == 0) sh[warp] = acc;
    __syncthreads();
    if (threadIdx.x == 0) {
        float s = 0.f;
        for (int i = 0; i < 8; i++) s += sh[i];
        atomicAdd(&g_acc[1], s);
    }
}
__global__ void k_normA(const int* __restrict__ src, const int* __restrict__ dst) {
    __shared__ float sh[256];
    int e = blockIdx.x * 256 + threadIdx.x;
    float v = 0.f;
    if (e < EE) {
        float old = atomicExch(&g_Adense[(size_t)src[e] * TWO_N + dst[e]], 0.f);
        v = old * old;
    }
    float s = blockReduceSum(v, sh);
    if (threadIdx.x == 0 && s != 0.f) atomicAdd(&g_acc[0], s);
}
__global__ void k_gram() {   // 4 classes per block
    int c4 = blockIdx.x * 4;
    int i0 = blockIdx.y * 768;
    int t = threadIdx.x;  // 128
    if (t >= CC) return;
    float acc[4] = {0.f, 0.f, 0.f, 0.f};
    for (int i = i0; i < i0 + 768; i++) {
        float st = g_sm[(size_t)i * CC + t];
        #pragma unroll
        for (int k = 0; k < 4; k++)
            acc[k] += g_sm[(size_t)i * CC + c4 + k] * st;
    }
    #pragma unroll
    for (int k = 0; k < 4; k++)
        atomicAdd(&g_G[(c4 + k) * CC + t], acc[k]);
}
__global__ void k_gramfin(float* __restrict__ out_loss) {
    __shared__ float sh[256];
    int t = threadIdx.x;
    float acc = 0.f;
    for (int i = t; i < CC * CC; i += 256) { float g = g_G[i]; acc += g * g; }
    float s = blockReduceSum(acc, sh);
    if (t == 0) {
        float n2 = g_acc[0] - 2.f * g_acc[1] + s;
        float link = sqrtf(fmaxf(n2, 0.f)) / ((float)TWO_N * (float)TWO_N);
        out_loss[0] = link + g_acc[2] / (float)TWO_N;
    }
}

// ----------------------------- MHA2 -----------------------------
__global__ void k_kvproj(const float* __restrict__ wi, const float* __restrict__ bi) {
    int c = blockIdx.x;
    int which = blockIdx.y;
    int t = threadIdx.x;  // 128
    __shared__ float prow[DIM];
    prow[t] = g_pooled[(size_t)c * DIM + t];
    __syncthreads();
    const float4* row4 = reinterpret_cast<const float4*>(wi + (size_t)(DIM + which * DIM + t) * DIM);
    float acc = bi[DIM + which * DIM + t];
    #pragma unroll
    for (int k = 0; k < 32; k++) {
        float4 r = row4[k];
        acc += r.x * prow[4 * k] + r.y * prow[4 * k + 1]
             + r.z * prow[4 * k + 2] + r.w * prow[4 * k + 3];
    }
    (which ? g_vp2 : g_kp2)[(size_t)c * DIM + t] = acc;
}

#define K_LD 129
__global__ void k_mha2(const float* __restrict__ wo, const float* __restrict__ bo,
                       float* __restrict__ out_skill) {
    extern __shared__ float kp_s[];     // [CC][K_LD]
    __shared__ float qrow[DIM];
    __shared__ float lg[HH][CC];
    __shared__ float o_s[DIM];
    int t = threadIdx.x;  // 128
    int w = t >> 5, lane = t & 31;
    for (int i = t; i < CC * DIM; i += 128) {
        int j = i >> 7, d = i & 127;
        kp_s[j * K_LD + d] = g_kp2[i];
    }
    __syncthreads();
    int n0 = blockIdx.x * 16;
    for (int q = 0; q < 16; q++) {
        int n = n0 + q;
        qrow[t] = g_qp2[(size_t)n * DIM + t];
        __syncthreads();
        for (int pos = t; pos < HH * CC; pos += 128) {
            int h = pos / CC, j = pos % CC;
            float acc = 0.f;
            #pragma unroll 8
            for (int d = 0; d < HD; d++)
                acc += qrow[h * HD + d] * kp_s[j * K_LD + h * HD + d];
            lg[h][j] = acc * INV_SQRT_HD;
        }
        __syncthreads();
        {
            float mx = -1e30f;
            for (int j = lane; j < CC; j += 32) mx = fmaxf(mx, lg[w][j]);
            #pragma unroll
            for (int o = 16; o > 0; o >>= 1) mx = fmaxf(mx, __shfl_xor_sync(0xffffffff, mx, o));
            float sm = 0.f;
            for (int j = lane; j < CC; j += 32) { float e = expf(lg[w][j] - mx); lg[w][j] = e; sm += e; }
            #pragma unroll
            for (int o = 16; o > 0; o >>= 1) sm += __shfl_xor_sync(0xffffffff, sm, o);
            float inv = 1.f / sm;
            for (int j = lane; j < CC; j += 32) lg[w][j] *= inv;
        }
        __syncthreads();
        {
            float acc = 0.f;
            for (int j = 0; j < CC; j++) acc += lg[w][j] * g_vp2[(size_t)j * DIM + t];
            o_s[t] = acc;
        }
        __syncthreads();
        {
            const float4* row4 = reinterpret_cast<const float4*>(wo + (size_t)t * DIM);
            float acc = bo[t];
            #pragma unroll
            for (int k = 0; k < 32; k++) {
                float4 r = row4[k];
                acc += r.x * o_s[4 * k] + r.y * o_s[4 * k + 1]
                     + r.z * o_s[4 * k + 2] + r.w * o_s[4 * k + 3];
            }
            out_skill[(size_t)n * DIM + t] = 2.f * g_emb[(size_t)n * DIM + t] + acc;
        }
        __syncthreads();
    }
}

// ----------------------------- host launch -----------------------------
extern "C" void kernel_launch(void* const* d_in, const int* in_sizes, int n_in,
                              void* d_out, int out_size) {
    const float* demand = (const float*)d_in[0];
    const float* supply = (const float*)d_in[1];
    const float* skill  = (const float*)d_in[2];
    const int*   eidx   = (const int*)d_in[3];
    const float* eattr  = (const float*)d_in[4];
    const float* w_fuse = (const float*)d_in[5];
    const float* b_fuse = (const float*)d_in[6];
    const float* m1wi   = (const float*)d_in[7];
    const float* m1bi   = (const float*)d_in[8];
    const float* m1wo   = (const float*)d_in[9];
    const float* m1bo   = (const float*)d_in[10];
    const float* m2wi   = (const float*)d_in[11];
    const float* m2bi   = (const float*)d_in[12];
    const float* m2wo   = (const float*)d_in[13];
    const float* m2bo   = (const float*)d_in[14];
    const float* sender = (const float*)d_in[15];
    const float* recv   = (const float*)d_in[16];
    const float* W0     = (const float*)d_in[17];
    const float* b0     = (const float*)d_in[18];
    const float* W1     = (const float*)d_in[19];
    const float* b1     = (const float*)d_in[20];
    const float* Wp     = (const float*)d_in[21];
    const float* bp     = (const float*)d_in[22];
    float* out = (float*)d_out;
    const int* src = eidx;
    const int* dst = eidx + EE;

    cudaFuncSetAttribute(k_mha2, cudaFuncAttributeMaxDynamicSharedMemorySize,
                         CC * K_LD * (int)sizeof(float) + 1024);

    float *p_cat2, *p_fused, *p_xw, *p_tmpA, *p_tmpB, *p_emb, *p_sm, *p_wt, *p_qp2;
    float *p_qv, *p_qp1, *p_U, *p_c, *p_wqt, *p_Mk, *p_Zcat, *p_zb;
    cudaGetSymbolAddress((void**)&p_cat2, g_cat2);
    cudaGetSymbolAddress((void**)&p_fused, g_fused);
    cudaGetSymbolAddress((void**)&p_xw, g_xw);
    cudaGetSymbolAddress((void**)&p_tmpA, g_tmpA);
    cudaGetSymbolAddress((void**)&p_tmpB, g_tmpB);
    cudaGetSymbolAddress((void**)&p_emb, g_emb);
    cudaGetSymbolAddress((void**)&p_sm, g_sm);
    cudaGetSymbolAddress((void**)&p_wt, g_wt);
    cudaGetSymbolAddress((void**)&p_qp2, g_qp2);
    cudaGetSymbolAddress((void**)&p_qv, g_qv);
    cudaGetSymbolAddress((void**)&p_qp1, g_qp1);
    cudaGetSymbolAddress((void**)&p_U, g_U);
    cudaGetSymbolAddress((void**)&p_c, g_c);
    cudaGetSymbolAddress((void**)&p_wqt, g_wqt);
    cudaGetSymbolAddress((void**)&p_Mk, g_Mk);
    cudaGetSymbolAddress((void**)&p_Zcat, g_Zcat);
    cudaGetSymbolAddress((void**)&p_zb, g_zb);

    k_init<<<64, 256>>>(sender, recv);
    k_seqsum<<<dim3(2, 24), 128>>>(demand, supply);
    k_prep<<<1281, 128>>>(m1wi, m1wo, m1bo, m1bi, m2wi);
    k_qv<<<TWO_N * DIM / 256, 256>>>(skill, out + OUT_CAT);

    // MHA1 GEMM chain (output lands directly in cat2 second half, ldc=256)
    k_sgemm<<<dim3(1, TWO_N / 64), 256>>>(p_qv, p_wqt, m1bi, p_qp1, TWO_N, DIM, DIM, DIM);
    k_sgemm<<<dim3(4, TWO_N / 64), 256>>>(p_qp1, p_Mk, nullptr, p_U, TWO_N, 4 * DIM, DIM, 4 * DIM);
    k_attn1<<<TWO_N, 128>>>(demand, supply, m1bi);
    k_sgemm<<<dim3(1, TWO_N / 64), 256>>>(p_c, p_Zcat, p_zb, p_cat2 + DIM, TWO_N, DIM, 4 * DIM, 2 * DIM);

    k_sgemm<<<dim3(1, TWO_N / 64), 256>>>(p_cat2, w_fuse, b_fuse, p_fused, TWO_N, DIM, 2 * DIM, DIM);
    k_tanhprep<<<TWO_N * DIM / 256, 256>>>(sender, recv);
    k_scores<<<1184, 256>>>();
    k_predg<<<TWO_N, 256>>>(out + OUT_PRED);

    // dense GCN (2 layers)
    for (int l = 0; l < 2; l++) {
        const float* srcbuf = (l == 0) ? p_fused : p_tmpA;
        k_sgemm<<<dim3(1, TWO_N / 64), 256>>>(srcbuf, W0 + (size_t)l * DIM * DIM, nullptr, p_xw,
                                              TWO_N, DIM, DIM, DIM);
        k_dense_agg<<<TWO_N / 32, 256>>>();
        k_dense_combine<<<TWO_N * DIM / 256, 256>>>(srcbuf, p_tmpA, b0, l);
    }

    // sparse GCN: CSR build once, then 2 gather layers (final writes emb)
    k_edge1<<<EE / 256, 256>>>(dst, eattr);
    k_scan<<<1, 1024>>>();
    k_fillcsr<<<EE / 256, 256>>>(src, dst, eattr);
    k_sgemm<<<dim3(1, TWO_N / 64), 256>>>(p_fused, W1, nullptr, p_xw, TWO_N, DIM, DIM, DIM);
    k_spgather<<<TWO_N, 128>>>(p_fused, p_tmpB, b1, 0, 0);
    k_sgemm<<<dim3(1, TWO_N / 64), 256>>>(p_tmpB, W1 + (size_t)DIM * DIM, nullptr, p_xw, TWO_N, DIM, DIM, DIM);
    k_spgather<<<TWO_N, 128>>>(p_tmpB, p_emb, b1, 1, 1);

    // diff-pool
    k_sgemm<<<dim3(1, TWO_N / 64), 256>>>(p_emb, Wp, bp, p_sm, TWO_N, CC, DIM, CC);
    k_softmax_s<<<TWO_N, 128>>>();
    k_pooled<<<dim3(25, 8), 128>>>();
    k_edge2<<<EE / 8, 256>>>(src, dst, eattr);
    k_normA<<<EE / 256, 256>>>(src, dst);
    k_gram<<<dim3(25, 8), 128>>>();
    k_gramfin<<<1, 256>>>(out + OUT_LOSS);

    // MHA2
    k_sgemm<<<dim3(1, TWO_N / 64), 256>>>(p_emb, p_wt, m2bi, p_qp2, TWO_N, DIM, DIM, DIM);
    k_kvproj<<<dim3(CC, 2), 128>>>(m2wi, m2bi);
    k_mha2<<<TWO_N / 16, 128, CC * K_LD * sizeof(float) + 1024>>>(m2wo, m2bo, out + OUT_SKILL);
}

// round 9
// speedup vs baseline: 1.1466x; 1.1466x over previous
#include <cuda_runtime.h>
#include <math.h>

#define NN      3072
#define TWO_N   6144
#define DIM     128
#define SEQ     16
#define EE      196608
#define CC      100
#define HH      4
#define HD      32
#define INV_SQRT_HD 0.17677669529663687f
#define DELTA_T 0.1f
#define PRESERVE 0.1f

#define OUT_CAT   0
#define OUT_SKILL (TWO_N * DIM)
#define OUT_PRED  (2 * TWO_N * DIM)
#define OUT_LOSS  (2 * TWO_N * DIM + TWO_N * TWO_N)

// ----------------------------- device scratch -----------------------------
__device__ float g_dsum[DIM];
__device__ float g_ssum[DIM];
__device__ float g_cat2[(size_t)TWO_N * 2 * DIM];
__device__ float g_fused[(size_t)TWO_N * DIM];
__device__ float g_s1[(size_t)TWO_N * DIM];
__device__ float g_s2[(size_t)TWO_N * DIM];
__device__ float g_scores[(size_t)TWO_N * TWO_N];   // general path only
__device__ float g_Adense[(size_t)TWO_N * TWO_N];   // zero between launches (exch trick)
__device__ float g_deg[TWO_N];
__device__ float g_degsp[TWO_N];
__device__ float g_xw[(size_t)TWO_N * DIM];     // dense chain
__device__ float g_xw2[(size_t)TWO_N * DIM];    // sparse chain
__device__ float g_agg[(size_t)TWO_N * DIM];
__device__ float g_tmpA[(size_t)TWO_N * DIM];
__device__ float g_tmpB[(size_t)TWO_N * DIM];
__device__ float g_emb[(size_t)TWO_N * DIM];
__device__ float g_sm[(size_t)TWO_N * CC];
__device__ float g_pooled[CC * DIM];
__device__ float g_G[CC * CC];
__device__ float g_kp2[CC * DIM];
__device__ float g_vp2[CC * DIM];
__device__ float g_qp2[(size_t)TWO_N * DIM];
__device__ float g_wt[DIM * DIM];
__device__ float g_acc[8];   // [0]=||A||^2 [1]=<A,SS^T> [2]=ent_sum
__device__ int   g_flag;

// MHA1 GEMM-chain buffers
__device__ float g_qv[(size_t)TWO_N * DIM];
__device__ float g_qp1[(size_t)TWO_N * DIM];
__device__ float g_U[(size_t)TWO_N * 4 * DIM];
__device__ float g_c[(size_t)TWO_N * 4 * DIM];
__device__ float g_wqt[DIM * DIM];
__device__ float g_Mk[DIM * 4 * DIM];
__device__ float g_Zcat[4 * DIM * DIM];
__device__ float g_zb[DIM];

// CSR for sparse GCN
__device__ int   g_csr_cnt[TWO_N];
__device__ int   g_csr_off[TWO_N + 1];
__device__ int   g_csr_src[EE];
__device__ float g_csr_coef[EE];

// ----------------------------- helpers -----------------------------
__device__ __forceinline__ float blockReduceSum(float v, float* sh) {
    int t = threadIdx.x;
    sh[t] = v; __syncthreads();
    for (int s = blockDim.x >> 1; s > 0; s >>= 1) {
        if (t < s) sh[t] += sh[t + s];
        __syncthreads();
    }
    float r = sh[0]; __syncthreads();
    return r;
}
__device__ __forceinline__ float blockReduceMax(float v, float* sh) {
    int t = threadIdx.x;
    sh[t] = v; __syncthreads();
    for (int s = blockDim.x >> 1; s > 0; s >>= 1) {
        if (t < s) sh[t] = fmaxf(sh[t], sh[t + s]);
        __syncthreads();
    }
    float r = sh[0]; __syncthreads();
    return r;
}

// ---------------- SGEMM as device block-function (256 threads) ----------------
__device__ void sgemm_block(const float* __restrict__ A, const float* __restrict__ B,
                            const float* __restrict__ bias, float* __restrict__ Cmat,
                            int M, int Nn, int K, int ldc, int bmi, int bni) {
    __shared__ float As[16][64];
    __shared__ float Bs[16][128];
    int bm = bmi * 64;
    int bn = bni * 128;
    int tid = threadIdx.x;
    int tr = tid >> 4;
    int tc = tid & 15;
    float acc[4][8];
    #pragma unroll
    for (int r = 0; r < 4; r++)
        #pragma unroll
        for (int c = 0; c < 8; c++) acc[r][c] = 0.f;

    for (int k0 = 0; k0 < K; k0 += 16) {
        #pragma unroll
        for (int j = 0; j < 4; j++) {
            int idx = tid + 256 * j;
            int m = idx >> 4, kk = idx & 15;
            As[kk][m] = A[(size_t)(bm + m) * K + k0 + kk];
        }
        #pragma unroll
        for (int j = 0; j < 8; j++) {
            int idx = tid + 256 * j;
            int kk = idx >> 7, n = idx & 127;
            float v = 0.f;
            if (bn + n < Nn) v = B[(size_t)(k0 + kk) * Nn + bn + n];
            Bs[kk][n] = v;
        }
        __syncthreads();
        #pragma unroll
        for (int kk = 0; kk < 16; kk++) {
            float a[4], bb[8];
            #pragma unroll
            for (int r = 0; r < 4; r++) a[r] = As[kk][tr * 4 + r];
            #pragma unroll
            for (int c = 0; c < 8; c++) bb[c] = Bs[kk][tc * 8 + c];
            #pragma unroll
            for (int r = 0; r < 4; r++)
                #pragma unroll
                for (int c = 0; c < 8; c++) acc[r][c] += a[r] * bb[c];
        }
        __syncthreads();
    }
    #pragma unroll
    for (int r = 0; r < 4; r++) {
        int m = bm + tr * 4 + r;
        if (m >= M) continue;
        #pragma unroll
        for (int c = 0; c < 8; c++) {
            int n = bn + tc * 8 + c;
            if (n < Nn) {
                float v = acc[r][c];
                if (bias) v += bias[n];
                Cmat[(size_t)m * ldc + n] = v;
            }
        }
    }
}

__global__ void k_sgemm(const float* __restrict__ A, const float* __restrict__ B,
                        const float* __restrict__ bias, float* __restrict__ Cmat,
                        int M, int Nn, int K, int ldc) {
    sgemm_block(A, B, bias, Cmat, M, Nn, K, ldc, blockIdx.y, blockIdx.x);
}

// ----------------------------- init -----------------------------
__global__ void k_init(const float* __restrict__ sender, const float* __restrict__ receiver) {
    int i = blockIdx.x * blockDim.x + threadIdx.x;
    if (i < TWO_N) { g_deg[i] = 1.0f; g_degsp[i] = 1.0f; g_csr_cnt[i] = 0; }
    if (i < CC * DIM) g_pooled[i] = 0.f;
    if (i < CC * CC) g_G[i] = 0.f;
    if (i < 2 * DIM) (i < DIM ? g_dsum : g_ssum)[i & 127] = 0.f;
    if (i < 8) g_acc[i] = 0.f;
    if (i == 0) g_flag = (sender[0] == receiver[0]) ? 1 : 0;
}

// ----------------------------- stage1: prep + seqsum + edge1 (merged) -----------------------------
__global__ void k_stage1(const float* __restrict__ m1wi, const float* __restrict__ m1wo,
                         const float* __restrict__ m1bo, const float* __restrict__ m1bi,
                         const float* __restrict__ m2wi,
                         const float* __restrict__ demand, const float* __restrict__ supply,
                         const int* __restrict__ dst, const float* __restrict__ w) {
    int b = blockIdx.x;
    int t = threadIdx.x;  // 256
    if (b < 64) {                         // WqT
        int i = b * 256 + t;
        int k = i >> 7, tt = i & 127;
        g_wqt[i] = m1wi[(size_t)tt * DIM + k];
    } else if (b < 320) {                 // Mk
        int i = (b - 64) * 256 + t;
        int j = i >> 9, col = i & 511;
        int h = col >> 7, d = col & 127;
        const float* wk = m1wi + (size_t)DIM * DIM;
        g_Mk[i] = ((j >> 5) == h) ? wk[(size_t)j * DIM + d] : 0.f;
    } else if (b < 576) {                 // Zcat
        int i = (b - 320) * 256 + t;
        int row = i >> 7, tt = i & 127;
        int h = row >> 7, d = row & 127;
        const float* wv = m1wi + (size_t)2 * DIM * DIM;
        float acc = 0.f;
        #pragma unroll 8
        for (int j = 0; j < 32; j++)
            acc += m1wo[(size_t)tt * DIM + h * 32 + j] * wv[(size_t)(h * 32 + j) * DIM + d];
        g_Zcat[(size_t)row * DIM + tt] = acc;
    } else if (b == 576) {                // zb
        if (t < DIM) {
            const float* bv = m1bi + 2 * DIM;
            float acc = m1bo[t];
            #pragma unroll 8
            for (int k = 0; k < DIM; k++) acc += m1wo[(size_t)t * DIM + k] * bv[k];
            g_zb[t] = acc;
        }
    } else if (b < 641) {                 // m2wi transpose
        int i = (b - 577) * 256 + t;
        int n = i >> 7, k = i & 127;
        g_wt[(size_t)k * DIM + n] = m2wi[(size_t)n * DIM + k];
    } else if (b < 689) {                 // seqsum (48 blocks)
        if (t < DIM) {
            int sb = b - 641;
            int tensor = sb / 24, chunk = sb % 24;
            const float* base = tensor ? supply : demand;
            float acc = 0.f;
            int n0 = chunk * 128;
            for (int n = n0; n < n0 + 128; n++)
                acc += base[(size_t)n * SEQ * DIM + (size_t)(SEQ - 1) * DIM + t];
            atomicAdd(&(tensor ? g_ssum : g_dsum)[t], acc);
        }
    } else {                              // edge1 (768 blocks)
        int e = (b - 689) * 256 + t;
        if (e < EE) {
            int q = dst[e];
            atomicAdd(&g_degsp[q], w[e]);
            atomicAdd(&g_csr_cnt[q], 1);
        }
    }
}

// ----------------------------- stage2: scan (b0) + qv (merged, 1024 threads) ----------------------
__global__ void k_stage2(const float* __restrict__ skill, float* __restrict__ out_cat) {
    int b = blockIdx.x;
    int t = threadIdx.x;  // 1024
    if (b == 0) {         // scan
        __shared__ int sh[1024];
        int base = t * 6;
        int loc[6];
        int s = 0;
        #pragma unroll
        for (int k = 0; k < 6; k++) { loc[k] = s; s += g_csr_cnt[base + k]; }
        sh[t] = s;
        __syncthreads();
        for (int off = 1; off < 1024; off <<= 1) {
            int add = (t >= off) ? sh[t - off] : 0;
            __syncthreads();
            sh[t] += add;
            __syncthreads();
        }
        int excl = sh[t] - s;
        #pragma unroll
        for (int k = 0; k < 6; k++) {
            int o = excl + loc[k];
            g_csr_off[base + k] = o;
            g_csr_cnt[base + k] = o;
        }
        if (t == 1023) g_csr_off[TWO_N] = sh[1023];
    } else {              // qv + cat2 first half + out_cat
        int i = (b - 1) * 1024 + t;
        int bb = i >> 7, tt = i & 127;
        bool dem = bb < NN;
        int idx = dem ? bb : bb - NN;
        float sv = skill[(size_t)idx * DIM + tt];
        g_qv[i] = sv + (dem ? g_dsum : g_ssum)[tt];
        g_cat2[(size_t)bb * 2 * DIM + tt] = sv;
        out_cat[i] = sv;
    }
}

// ----------------------------- stage3: fillcsr + qp1 GEMM (merged) --------------------------------
__global__ void k_stage3(const int* __restrict__ src, const int* __restrict__ dst,
                         const float* __restrict__ w, const float* __restrict__ m1bi) {
    int b = blockIdx.x;
    if (b < 768) {
        int e = b * 256 + threadIdx.x;
        if (e < EE) {
            int s = src[e], q = dst[e];
            int pos = atomicAdd(&g_csr_cnt[q], 1);
            g_csr_src[pos] = s;
            g_csr_coef[pos] = rsqrtf(g_degsp[s]) * rsqrtf(g_degsp[q]) * w[e];
        }
    } else {
        sgemm_block(g_qv, g_wqt, m1bi, g_qp1, TWO_N, DIM, DIM, DIM, b - 768, 0);
    }
}

// ----------------------------- MHA1 attention core -----------------------------
__global__ void k_attn1(const float* __restrict__ demand, const float* __restrict__ supply,
                        const float* __restrict__ bi) {
    int b = blockIdx.x;
    int t = threadIdx.x;  // 128
    int w = t >> 5, lane = t & 31;
    bool dem = b < NN;
    int idx = dem ? b : b - NN;
    const float* seq = (dem ? demand : supply) + (size_t)idx * SEQ * DIM;

    __shared__ float sh_seq[SEQ][DIM + 1];
    __shared__ float sh_U[HH][DIM];
    __shared__ float sh_p[HH][SEQ];

    for (int i = t; i < SEQ * DIM; i += 128) sh_seq[i >> 7][i & 127] = seq[i];
    for (int i = t; i < HH * DIM; i += 128) sh_U[i >> 7][i & 127] = g_U[(size_t)b * 512 + i];
    __syncthreads();

    const float* bk = bi + DIM;
    float qb = g_qp1[(size_t)b * DIM + w * HD + lane] * bk[w * HD + lane];
    #pragma unroll
    for (int o = 16; o > 0; o >>= 1) qb += __shfl_xor_sync(0xffffffff, qb, o);

    float myl = -1e30f;
    if (lane < SEQ) {
        float acc = 0.f;
        #pragma unroll 16
        for (int d = 0; d < DIM; d++) acc += sh_U[w][d] * sh_seq[lane][d];
        myl = (acc + qb) * INV_SQRT_HD;
    }
    float mx = myl;
    #pragma unroll
    for (int o = 8; o > 0; o >>= 1) mx = fmaxf(mx, __shfl_xor_sync(0xffffffff, mx, o));
    float e = (lane < SEQ) ? expf(myl - mx) : 0.f;
    float sm = e;
    #pragma unroll
    for (int o = 8; o > 0; o >>= 1) sm += __shfl_xor_sync(0xffffffff, sm, o);
    if (lane < SEQ) sh_p[w][lane] = e / sm;
    __syncthreads();

    #pragma unroll
    for (int k = 0; k < 4; k++) {
        int d = lane + 32 * k;
        float acc = 0.f;
        #pragma unroll
        for (int s = 0; s < SEQ; s++) acc += sh_p[w][s] * sh_seq[s][d];
        g_c[(size_t)b * 512 + w * DIM + d] = acc;
    }
}

// ----------------------------- stage8: tanhprep + dense-l0 GEMM + sparse-l0 GEMM -------------------
__global__ void k_stage8(const float* __restrict__ sender, const float* __restrict__ receiver,
                         const float* __restrict__ W0, const float* __restrict__ W1) {
    int b = blockIdx.x;
    if (b < 3072) {
        if (g_flag) return;
        int i = b * 256 + threadIdx.x;
        float f = g_fused[i];
        g_s1[i] = tanhf(sender[0] * f);
        g_s2[i] = tanhf(receiver[0] * f);
    } else if (b < 3168) {
        sgemm_block(g_fused, W0, nullptr, g_xw, TWO_N, DIM, DIM, DIM, b - 3072, 0);
    } else {
        sgemm_block(g_fused, W1, nullptr, g_xw2, TWO_N, DIM, DIM, DIM, b - 3168, 0);
    }
}

// ----------------------------- scores (general path; grid-stride) -----------------------------
__global__ void k_scores() {
    if (g_flag) return;
    __shared__ float A1[16][DIM], A2[16][DIM], B1[16][DIM], B2[16][DIM];
    int t = threadIdx.x;  // 256
    const int TILES = TWO_N / 16;
    for (int tile = blockIdx.x; tile < TILES * TILES; tile += gridDim.x) {
        int i0 = (tile / TILES) * 16, j0 = (tile % TILES) * 16;
        __syncthreads();
        for (int j = 0; j < 8; j++) {
            int idx = t + 256 * j;
            int r = idx >> 7, c = idx & 127;
            A1[r][c] = g_s1[(size_t)(i0 + r) * DIM + c];
            A2[r][c] = g_s2[(size_t)(i0 + r) * DIM + c];
            B1[r][c] = g_s1[(size_t)(j0 + r) * DIM + c];
            B2[r][c] = g_s2[(size_t)(j0 + r) * DIM + c];
        }
        __syncthreads();
        int ti = t >> 4, tj = t & 15;
        float acc = 0.f;
        for (int k = 0; k < DIM; k++)
            acc += A1[ti][k] * B2[tj][k] - A2[ti][k] * B1[tj][k];
        g_scores[(size_t)(i0 + ti) * TWO_N + j0 + tj] = acc;
    }
}

// ----------------------------- predg general (softmax+threshold+deg) ------------------------------
__global__ void k_predg_general(float* __restrict__ out_pred) {
    if (g_flag) return;
    int row = blockIdx.x;
    int t = threadIdx.x;  // 256
    __shared__ float sh[256];
    float* sr = g_scores + (size_t)row * TWO_N;
    float mx = 0.f;
    for (int i = t; i < TWO_N; i += 256) mx = fmaxf(mx, fmaxf(sr[i], 0.f));
    mx = blockReduceMax(mx, sh);
    float sum = 0.f;
    for (int i = t; i < TWO_N; i += 256) sum += expf(fmaxf(sr[i], 0.f) - mx);
    sum = blockReduceSum(sum, sh);
    float inv = 1.f / sum;
    for (int i = t; i < TWO_N; i += 256) {
        float p = expf(fmaxf(sr[i], 0.f) - mx) * inv;
        float pr = fmaxf(p - DELTA_T, 0.f);
        sr[i] = pr;
        out_pred[(size_t)row * TWO_N + i] = pr;
        if (pr != 0.f) atomicAdd(&g_deg[i], pr);
    }
}

// ----------------------------- dense agg (general path) -----------------------------
__global__ void k_dense_agg() {
    if (g_flag) return;
    int i0 = blockIdx.x * 32;
    int t = threadIdx.x;  // 256
    __shared__ float pcol[32];
    __shared__ float xrow[DIM];
    int dbase = t & 127, half = t >> 7;
    float acc[16];
    #pragma unroll
    for (int r = 0; r < 16; r++) acc[r] = 0.f;
    for (int j = 0; j < TWO_N; j++) {
        if (t < 32) pcol[t] = g_scores[(size_t)j * TWO_N + i0 + t];
        else if (t >= 128 && t < 256) {
            float sj = rsqrtf(g_deg[j]);
            xrow[t - 128] = sj * g_xw[(size_t)j * DIM + (t - 128)];
        }
        __syncthreads();
        #pragma unroll
        for (int r = 0; r < 16; r++) acc[r] += pcol[half + 2 * r] * xrow[dbase];
        __syncthreads();
    }
    #pragma unroll
    for (int r = 0; r < 16; r++) {
        int i = i0 + half + 2 * r;
        float di = rsqrtf(g_deg[i]);
        g_agg[(size_t)i * DIM + dbase] = acc[r] + di * g_xw[(size_t)i * DIM + dbase];
    }
}

// ---------------- device bodies: dense combine / sparse gather ----------------
__device__ __forceinline__ void dense_combine_elem(int i, const float* prev, float* dst,
                                                   const float* b0, int layer) {
    float di = rsqrtf(g_deg[i >> 7]);
    float v = g_flag ? (di * di * g_xw[i]) : (di * g_agg[i]);
    float out = v + b0[layer * DIM + (i & 127)];
    dst[i] = (1.f - PRESERVE) * out + PRESERVE * prev[i];
}
__device__ __forceinline__ void spgather_node(int q, int tt, const float* xw, const float* prev,
                                              float* dstb, const float* b1, int layer, int addA) {
    float dv = rsqrtf(g_degsp[q]);
    float acc = dv * dv * xw[(size_t)q * DIM + tt];
    int beg = g_csr_off[q], end = g_csr_off[q + 1];
    int j = beg;
    for (; j + 1 < end; j += 2) {
        float c0 = g_csr_coef[j], c1 = g_csr_coef[j + 1];
        int   s0 = g_csr_src[j],  s1 = g_csr_src[j + 1];
        acc += c0 * xw[(size_t)s0 * DIM + tt] + c1 * xw[(size_t)s1 * DIM + tt];
    }
    if (j < end) acc += g_csr_coef[j] * xw[(size_t)g_csr_src[j] * DIM + tt];
    float outv = acc + b1[layer * DIM + tt];
    float blend = (1.f - PRESERVE) * outv + PRESERVE * prev[(size_t)q * DIM + tt];
    if (addA) blend += g_tmpA[(size_t)q * DIM + tt];
    dstb[(size_t)q * DIM + tt] = blend;
}

// stage12: dense_combine l0 + spgather l0 (merged)
__global__ void k_stage12(const float* __restrict__ b0, const float* __restrict__ b1) {
    int b = blockIdx.x;
    int t = threadIdx.x;  // 256
    if (b < 3072) {
        dense_combine_elem(b * 256 + t, g_fused, g_tmpA, b0, 0);
    } else {
        int q = (b - 3072) * 2 + (t >> 7);
        spgather_node(q, t & 127, g_xw2, g_fused, g_tmpB, b1, 0, 0);
    }
}

// stage13: dense l1 GEMM + sparse l1 GEMM (merged)
__global__ void k_stage13(const float* __restrict__ W0, const float* __restrict__ W1) {
    int b = blockIdx.x;
    if (b < 96) sgemm_block(g_tmpA, W0 + (size_t)DIM * DIM, nullptr, g_xw, TWO_N, DIM, DIM, DIM, b, 0);
    else        sgemm_block(g_tmpB, W1 + (size_t)DIM * DIM, nullptr, g_xw2, TWO_N, DIM, DIM, DIM, b - 96, 0);
}

// stage15: dense_combine l1
__global__ void k_stage15(const float* __restrict__ b0) {
    int i = blockIdx.x * 256 + threadIdx.x;
    if (i < TWO_N * DIM) dense_combine_elem(i, g_tmpA, g_tmpA, b0, 1);
}
// stage16: spgather l1 + add tmpA -> emb
__global__ void k_stage16(const float* __restrict__ b1) {
    int t = threadIdx.x;
    int q = blockIdx.x * 2 + (t >> 7);
    spgather_node(q, t & 127, g_xw2, g_tmpB, g_emb, b1, 1, 1);
}

// ----------------------------- pooling assignment softmax + entropy -----------------------------
__global__ void k_softmax_s() {
    int r = blockIdx.x, t = threadIdx.x;  // 128
    __shared__ float sh[128];
    float v = (t < CC) ? g_sm[(size_t)r * CC + t] : -1e30f;
    float mx = blockReduceMax(v, sh);
    float e = (t < CC) ? expf(v - mx) : 0.f;
    float sum = blockReduceSum(e, sh);
    float p = e / sum;
    float ent = (t < CC) ? (-p * logf(p + 1e-15f)) : 0.f;
    float es = blockReduceSum(ent, sh);
    if (t < CC) g_sm[(size_t)r * CC + t] = p;
    if (t == 0) atomicAdd(&g_acc[2], es);
}

// ----------------------------- stage19: pooled + gram + edge2 + predg_zero + qp2 GEMM -------------
__global__ void k_stage19(const int* __restrict__ src, const int* __restrict__ dst,
                          const float* __restrict__ w, const float* __restrict__ m2bi,
                          float* __restrict__ out_pred) {
    int b = blockIdx.x;
    int t = threadIdx.x;  // 256
    if (b < 200) {            // pooled
        if (t >= 128) return;
        int c4 = (b % 25) * 4;
        int i0 = (b / 25) * 768;
        float acc[4] = {0.f, 0.f, 0.f, 0.f};
        for (int i = i0; i < i0 + 768; i++) {
            float ev = g_emb[(size_t)i * DIM + t];
            #pragma unroll
            for (int cc = 0; cc < 4; cc++)
                acc[cc] += g_sm[(size_t)i * CC + c4 + cc] * ev;
        }
        #pragma unroll
        for (int cc = 0; cc < 4; cc++)
            atomicAdd(&g_pooled[(size_t)(c4 + cc) * DIM + t], acc[cc]);
    } else if (b < 400) {     // gram
        if (t >= CC) return;
        int c4 = ((b - 200) % 25) * 4;
        int i0 = ((b - 200) / 25) * 768;
        float acc[4] = {0.f, 0.f, 0.f, 0.f};
        for (int i = i0; i < i0 + 768; i++) {
            float st = g_sm[(size_t)i * CC + t];
            #pragma unroll
            for (int k = 0; k < 4; k++)
                acc[k] += g_sm[(size_t)i * CC + c4 + k] * st;
        }
        #pragma unroll
        for (int k = 0; k < 4; k++)
            atomicAdd(&g_G[(c4 + k) * CC + t], acc[k]);
    } else if (b < 24976) {   // edge2: scatterA + <A,SS^T>
        __shared__ float sh[8];
        int warp = t >> 5, lane = t & 31;
        int e = (b - 400) * 8 + warp;
        float acc = 0.f;
        if (e < EE) {
            int s = src[e], q = dst[e];
            float we = w[e];
            if (lane == 0) atomicAdd(&g_Adense[(size_t)s * TWO_N + q], we);
            for (int c = lane; c < CC; c += 32)
                acc += g_sm[(size_t)s * CC + c] * g_sm[(size_t)q * CC + c];
            acc *= we;
        }
        for (int o = 16; o > 0; o >>= 1) acc += __shfl_down_sync(0xffffffff, acc, o);
        if (lane == 0) sh[warp] = acc;
        __syncthreads();
        if (t == 0) {
            float s = 0.f;
            for (int i = 0; i < 8; i++) s += sh[i];
            atomicAdd(&g_acc[1], s);
        }
    } else if (b < 27024) {   // predg zero-fill (flag path)
        if (!g_flag) return;
        float4 z = make_float4(0.f, 0.f, 0.f, 0.f);
        float4* o = reinterpret_cast<float4*>(out_pred);
        size_t total = (size_t)TWO_N * TWO_N / 4;
        for (size_t j = (size_t)(b - 24976) * 256 + t; j < total; j += (size_t)2048 * 256)
            o[j] = z;
    } else {                  // qp2 GEMM
        sgemm_block(g_emb, g_wt, m2bi, g_qp2, TWO_N, DIM, DIM, DIM, b - 27024, 0);
    }
}

// ----------------------------- stage20: kvproj + normA (merged) -----------------------------------
__global__ void k_stage20(const float* __restrict__ wi, const float* __restrict__ bi,
                          const int* __restrict__ src, const int* __restrict__ dst) {
    int b = blockIdx.x;
    int t = threadIdx.x;  // 256
    if (b < 200) {
        __shared__ float prow[DIM];
        int c = b >> 1, which = b & 1;
        if (t < 128) prow[t] = g_pooled[(size_t)c * DIM + t];
        __syncthreads();
        if (t >= 128) return;
        const float4* row4 = reinterpret_cast<const float4*>(wi + (size_t)(DIM + which * DIM + t) * DIM);
        float acc = bi[DIM + which * DIM + t];
        #pragma unroll
        for (int k = 0; k < 32; k++) {
            float4 r = row4[k];
            acc += r.x * prow[4 * k] + r.y * prow[4 * k + 1]
                 + r.z * prow[4 * k + 2] + r.w * prow[4 * k + 3];
        }
        (which ? g_vp2 : g_kp2)[(size_t)c * DIM + t] = acc;
    } else {
        __shared__ float sh[256];
        int e = (b - 200) * 256 + t;
        float v = 0.f;
        if (e < EE) {
            float old = atomicExch(&g_Adense[(size_t)src[e] * TWO_N + dst[e]], 0.f);
            v = old * old;
        }
        float s = blockReduceSum(v, sh);
        if (t == 0 && s != 0.f) atomicAdd(&g_acc[0], s);
    }
}

// ----------------------------- stage21: mha2 + gramfin (merged, 128 threads) ----------------------
#define K_LD 129
__global__ void k_stage21(const float* __restrict__ wo, const float* __restrict__ bo,
                          float* __restrict__ out_skill, float* __restrict__ out_loss) {
    extern __shared__ float kp_s[];     // [CC][K_LD] — used by mha2 blocks only
    int t = threadIdx.x;  // 128
    if (blockIdx.x == 384) {            // gramfin
        __shared__ float sh[128];
        float acc = 0.f;
        for (int i = t; i < CC * CC; i += 128) { float g = g_G[i]; acc += g * g; }
        sh[t] = acc; __syncthreads();
        for (int s = 64; s > 0; s >>= 1) {
            if (t < s) sh[t] += sh[t + s];
            __syncthreads();
        }
        if (t == 0) {
            float n2 = g_acc[0] - 2.f * g_acc[1] + sh[0];
            float link = sqrtf(fmaxf(n2, 0.f)) / ((float)TWO_N * (float)TWO_N);
            out_loss[0] = link + g_acc[2] / (float)TWO_N;
        }
        return;
    }
    // mha2
    __shared__ float qrow[DIM];
    __shared__ float lg[HH][CC];
    __shared__ float o_s[DIM];
    int w = t >> 5, lane = t & 31;
    for (int i = t; i < CC * DIM; i += 128) {
        int j = i >> 7, d = i & 127;
        kp_s[j * K_LD + d] = g_kp2[i];
    }
    __syncthreads();
    int n0 = blockIdx.x * 16;
    for (int q = 0; q < 16; q++) {
        int n = n0 + q;
        qrow[t] = g_qp2[(size_t)n * DIM + t];
        __syncthreads();
        for (int pos = t; pos < HH * CC; pos += 128) {
            int h = pos / CC, j = pos % CC;
            float acc = 0.f;
            #pragma unroll 8
            for (int d = 0; d < HD; d++)
                acc += qrow[h * HD + d] * kp_s[j * K_LD + h * HD + d];
            lg[h][j] = acc * INV_SQRT_HD;
        }
        __syncthreads();
        {
            float mx = -1e30f;
            for (int j = lane; j < CC; j += 32) mx = fmaxf(mx, lg[w][j]);
            #pragma unroll
            for (int o = 16; o > 0; o >>= 1) mx = fmaxf(mx, __shfl_xor_sync(0xffffffff, mx, o));
            float sm = 0.f;
            for (int j = lane; j < CC; j += 32) { float e = expf(lg[w][j] - mx); lg[w][j] = e; sm += e; }
            #pragma unroll
            for (int o = 16; o > 0; o >>= 1) sm += __shfl_xor_sync(0xffffffff, sm, o);
            float inv = 1.f / sm;
            for (int j = lane; j < CC; j += 32) lg[w][j] *= inv;
        }
        __syncthreads();
        {
            float acc = 0.f;
            for (int j = 0; j < CC; j++) acc += lg[w][j] * g_vp2[(size_t)j * DIM + t];
            o_s[t] = acc;
        }
        __syncthreads();
        {
            const float4* row4 = reinterpret_cast<const float4*>(wo + (size_t)t * DIM);
            float acc = bo[t];
            #pragma unroll
            for (int k = 0; k < 32; k++) {
                float4 r = row4[k];
                acc += r.x * o_s[4 * k] + r.y * o_s[4 * k + 1]
                     + r.z * o_s[4 * k + 2] + r.w * o_s[4 * k + 3];
            }
            out_skill[(size_t)n * DIM + t] = 2.f * g_emb[(size_t)n * DIM + t] + acc;
        }
        __syncthreads();
    }
}

// ----------------------------- host launch -----------------------------
extern "C" void kernel_launch(void* const* d_in, const int* in_sizes, int n_in,
                              void* d_out, int out_size) {
    const float* demand = (const float*)d_in[0];
    const float* supply = (const float*)d_in[1];
    const float* skill  = (const float*)d_in[2];
    const int*   eidx   = (const int*)d_in[3];
    const float* eattr  = (const float*)d_in[4];
    const float* w_fuse = (const float*)d_in[5];
    const float* b_fuse = (const float*)d_in[6];
    const float* m1wi   = (const float*)d_in[7];
    const float* m1bi   = (const float*)d_in[8];
    const float* m1wo   = (const float*)d_in[9];
    const float* m1bo   = (const float*)d_in[10];
    const float* m2wi   = (const float*)d_in[11];
    const float* m2bi   = (const float*)d_in[12];
    const float* m2wo   = (const float*)d_in[13];
    const float* m2bo   = (const float*)d_in[14];
    const float* sender = (const float*)d_in[15];
    const float* recv   = (const float*)d_in[16];
    const float* W0     = (const float*)d_in[17];
    const float* b0     = (const float*)d_in[18];
    const float* W1     = (const float*)d_in[19];
    const float* b1     = (const float*)d_in[20];
    const float* Wp     = (const float*)d_in[21];
    const float* bp     = (const float*)d_in[22];
    float* out = (float*)d_out;
    const int* src = eidx;
    const int* dst = eidx + EE;

    cudaFuncSetAttribute(k_stage21, cudaFuncAttributeMaxDynamicSharedMemorySize,
                         CC * K_LD * (int)sizeof(float) + 1024);

    float *p_qp1, *p_U, *p_c, *p_Mk, *p_Zcat, *p_zb, *p_cat2, *p_fused, *p_emb, *p_sm;
    cudaGetSymbolAddress((void**)&p_qp1, g_qp1);
    cudaGetSymbolAddress((void**)&p_U, g_U);
    cudaGetSymbolAddress((void**)&p_c, g_c);
    cudaGetSymbolAddress((void**)&p_Mk, g_Mk);
    cudaGetSymbolAddress((void**)&p_Zcat, g_Zcat);
    cudaGetSymbolAddress((void**)&p_zb, g_zb);
    cudaGetSymbolAddress((void**)&p_cat2, g_cat2);
    cudaGetSymbolAddress((void**)&p_fused, g_fused);
    cudaGetSymbolAddress((void**)&p_emb, g_emb);
    cudaGetSymbolAddress((void**)&p_sm, g_sm);

    k_init<<<64, 256>>>(sender, recv);
    k_stage1<<<1457, 256>>>(m1wi, m1wo, m1bo, m1bi, m2wi, demand, supply, dst, eattr);
    k_stage2<<<769, 1024>>>(skill, out + OUT_CAT);
    k_stage3<<<864, 256>>>(src, dst, eattr, m1bi);
    k_sgemm<<<dim3(4, TWO_N / 64), 256>>>(p_qp1, p_Mk, nullptr, p_U, TWO_N, 4 * DIM, DIM, 4 * DIM);
    k_attn1<<<TWO_N, 128>>>(demand, supply, m1bi);
    k_sgemm<<<dim3(1, TWO_N / 64), 256>>>(p_c, p_Zcat, p_zb, p_cat2 + DIM, TWO_N, DIM, 4 * DIM, 2 * DIM);
    k_sgemm<<<dim3(1, TWO_N / 64), 256>>>(p_cat2, w_fuse, b_fuse, p_fused, TWO_N, DIM, 2 * DIM, DIM);

    k_stage8<<<3264, 256>>>(sender, recv, W0, W1);
    k_scores<<<1184, 256>>>();
    k_predg_general<<<TWO_N, 256>>>(out + OUT_PRED);
    k_dense_agg<<<TWO_N / 32, 256>>>();
    k_stage12<<<6144, 256>>>(b0, b1);
    k_stage13<<<192, 256>>>(W0, W1);
    k_dense_agg<<<TWO_N / 32, 256>>>();
    k_stage15<<<3072, 256>>>(b0);
    k_stage16<<<3072, 256>>>(b1);

    k_sgemm<<<dim3(1, TWO_N / 64), 256>>>(p_emb, Wp, bp, p_sm, TWO_N, CC, DIM, CC);
    k_softmax_s<<<TWO_N, 128>>>();
    k_stage19<<<27120, 256>>>(src, dst, eattr, m2bi, out + OUT_PRED);
    k_stage20<<<968, 256>>>(m2wi, m2bi, src, dst);
    k_stage21<<<385, 128, CC * K_LD * sizeof(float) + 1024>>>(m2wo, m2bo, out + OUT_SKILL, out + OUT_LOSS);
}

// round 10
// speedup vs baseline: 1.4116x; 1.2311x over previous
#include <cuda_runtime.h>
#include <math.h>

#define NN      3072
#define TWO_N   6144
#define DIM     128
#define SEQ     16
#define EE      196608
#define CC      100
#define HH      4
#define HD      32
#define INV_SQRT_HD 0.17677669529663687f
#define DELTA_T 0.1f
#define PRESERVE 0.1f

#define OUT_CAT   0
#define OUT_SKILL (TWO_N * DIM)
#define OUT_PRED  (2 * TWO_N * DIM)
#define OUT_LOSS  (2 * TWO_N * DIM + TWO_N * TWO_N)

// ----------------------------- device scratch -----------------------------
__device__ float g_dsum[DIM];
__device__ float g_ssum[DIM];
__device__ float g_cat2[(size_t)TWO_N * 2 * DIM];
__device__ float g_fused[(size_t)TWO_N * DIM];
__device__ float g_s1[(size_t)TWO_N * DIM];
__device__ float g_s2[(size_t)TWO_N * DIM];
__device__ float g_scores[(size_t)TWO_N * TWO_N];   // general path only
__device__ float g_Adense[(size_t)TWO_N * TWO_N];   // zero between launches (exch trick)
__device__ float g_deg[TWO_N];
__device__ float g_degsp[TWO_N];
__device__ float g_xw[(size_t)TWO_N * DIM];     // dense chain
__device__ float g_xw2[(size_t)TWO_N * DIM];    // sparse chain
__device__ float g_agg[(size_t)TWO_N * DIM];
__device__ float g_tmpA[(size_t)TWO_N * DIM];
__device__ float g_tmpB[(size_t)TWO_N * DIM];
__device__ float g_emb[(size_t)TWO_N * DIM];
__device__ float g_sm[(size_t)TWO_N * CC];
__device__ float g_pooled[CC * DIM];
__device__ float g_G[CC * CC];
__device__ float g_kp2[CC * DIM];
__device__ float g_vp2[CC * DIM];
__device__ float g_qp2[(size_t)TWO_N * DIM];
__device__ float g_wt[DIM * DIM];
__device__ float g_acc[8];   // [0]=||A||^2 [1]=<A,SS^T> [2]=ent_sum
__device__ int   g_flag;

// MHA1 GEMM-chain buffers
__device__ float g_qv[(size_t)TWO_N * DIM];
__device__ float g_qp1[(size_t)TWO_N * DIM];
__device__ float g_U[(size_t)TWO_N * 4 * DIM];
__device__ float g_c[(size_t)TWO_N * 4 * DIM];
__device__ float g_wqt[DIM * DIM];
__device__ float g_Mk[DIM * 4 * DIM];
__device__ float g_Zcat[4 * DIM * DIM];
__device__ float g_zb[DIM];

// CSR for sparse GCN
__device__ int   g_csr_cnt[TWO_N];
__device__ int   g_csr_off[TWO_N + 1];
__device__ int   g_csr_src[EE];
__device__ float g_csr_coef[EE];

// ----------------------------- helpers -----------------------------
__device__ __forceinline__ float blockReduceSum(float v, float* sh) {
    int t = threadIdx.x;
    sh[t] = v; __syncthreads();
    for (int s = blockDim.x >> 1; s > 0; s >>= 1) {
        if (t < s) sh[t] += sh[t + s];
        __syncthreads();
    }
    float r = sh[0]; __syncthreads();
    return r;
}
__device__ __forceinline__ float blockReduceMax(float v, float* sh) {
    int t = threadIdx.x;
    sh[t] = v; __syncthreads();
    for (int s = blockDim.x >> 1; s > 0; s >>= 1) {
        if (t < s) sh[t] = fmaxf(sh[t], sh[t + s]);
        __syncthreads();
    }
    float r = sh[0]; __syncthreads();
    return r;
}

// ---------------- SGEMM device block-function: 32x128 tile, double-buffered ----------------
// 256 threads; thread (tr=tid>>5, tc=tid&31) computes rows tr*4..+3, cols tc*4..+3.
// As reads are warp-uniform broadcasts (tr == warp id); Bs reads are float4 conflict-free.
__device__ void sgemm_block(const float* __restrict__ A, const float* __restrict__ B,
                            const float* __restrict__ bias, float* __restrict__ Cmat,
                            int M, int Nn, int K, int ldc, int bmi, int bni) {
    __shared__ float As[2][16][33];
    __shared__ float Bs[2][16][128];
    int bm = bmi * 32;
    int bn = bni * 128;
    int tid = threadIdx.x;
    int tr = tid >> 5, tc = tid & 31;
    float acc[4][4];
    #pragma unroll
    for (int r = 0; r < 4; r++)
        #pragma unroll
        for (int c = 0; c < 4; c++) acc[r][c] = 0.f;

    // preload tile 0
    #pragma unroll
    for (int j = 0; j < 2; j++) {
        int idx = tid + 256 * j;                 // 0..511
        int m = idx >> 4, kk = idx & 15;
        As[0][kk][m] = A[(size_t)(bm + m) * K + kk];
    }
    #pragma unroll
    for (int j = 0; j < 8; j++) {
        int idx = tid + 256 * j;                 // 0..2047
        int kk = idx >> 7, n = idx & 127;
        Bs[0][kk][n] = (bn + n < Nn) ? B[(size_t)kk * Nn + bn + n] : 0.f;
    }
    __syncthreads();

    int buf = 0;
    for (int k0 = 0; k0 < K; k0 += 16) {
        int nb = buf ^ 1;
        if (k0 + 16 < K) {                        // prefetch next tile into other buffer
            #pragma unroll
            for (int j = 0; j < 2; j++) {
                int idx = tid + 256 * j;
                int m = idx >> 4, kk = idx & 15;
                As[nb][kk][m] = A[(size_t)(bm + m) * K + k0 + 16 + kk];
            }
            #pragma unroll
            for (int j = 0; j < 8; j++) {
                int idx = tid + 256 * j;
                int kk = idx >> 7, n = idx & 127;
                Bs[nb][kk][n] = (bn + n < Nn) ? B[(size_t)(k0 + 16 + kk) * Nn + bn + n] : 0.f;
            }
        }
        #pragma unroll
        for (int kk = 0; kk < 16; kk++) {
            float a0 = As[buf][kk][tr * 4 + 0];
            float a1 = As[buf][kk][tr * 4 + 1];
            float a2 = As[buf][kk][tr * 4 + 2];
            float a3 = As[buf][kk][tr * 4 + 3];
            float4 b4 = *reinterpret_cast<const float4*>(&Bs[buf][kk][tc * 4]);
            acc[0][0] += a0 * b4.x; acc[0][1] += a0 * b4.y; acc[0][2] += a0 * b4.z; acc[0][3] += a0 * b4.w;
            acc[1][0] += a1 * b4.x; acc[1][1] += a1 * b4.y; acc[1][2] += a1 * b4.z; acc[1][3] += a1 * b4.w;
            acc[2][0] += a2 * b4.x; acc[2][1] += a2 * b4.y; acc[2][2] += a2 * b4.z; acc[2][3] += a2 * b4.w;
            acc[3][0] += a3 * b4.x; acc[3][1] += a3 * b4.y; acc[3][2] += a3 * b4.z; acc[3][3] += a3 * b4.w;
        }
        __syncthreads();
        buf = nb;
    }
    #pragma unroll
    for (int r = 0; r < 4; r++) {
        int m = bm + tr * 4 + r;
        if (m >= M) continue;
        #pragma unroll
        for (int c = 0; c < 4; c++) {
            int n = bn + tc * 4 + c;
            if (n < Nn) {
                float v = acc[r][c];
                if (bias) v += bias[n];
                Cmat[(size_t)m * ldc + n] = v;
            }
        }
    }
}

__global__ void k_sgemm(const float* __restrict__ A, const float* __restrict__ B,
                        const float* __restrict__ bias, float* __restrict__ Cmat,
                        int M, int Nn, int K, int ldc) {
    sgemm_block(A, B, bias, Cmat, M, Nn, K, ldc, blockIdx.y, blockIdx.x);
}

// ----------------------------- init -----------------------------
__global__ void k_init(const float* __restrict__ sender, const float* __restrict__ receiver) {
    int i = blockIdx.x * blockDim.x + threadIdx.x;
    if (i < TWO_N) { g_deg[i] = 1.0f; g_degsp[i] = 1.0f; g_csr_cnt[i] = 0; }
    if (i < CC * DIM) g_pooled[i] = 0.f;
    if (i < CC * CC) g_G[i] = 0.f;
    if (i < 2 * DIM) (i < DIM ? g_dsum : g_ssum)[i & 127] = 0.f;
    if (i < 8) g_acc[i] = 0.f;
    if (i == 0) g_flag = (sender[0] == receiver[0]) ? 1 : 0;
}

// ----------------------------- stage1: prep + seqsum + edge1 (merged) -----------------------------
__global__ void k_stage1(const float* __restrict__ m1wi, const float* __restrict__ m1wo,
                         const float* __restrict__ m1bo, const float* __restrict__ m1bi,
                         const float* __restrict__ m2wi,
                         const float* __restrict__ demand, const float* __restrict__ supply,
                         const int* __restrict__ dst, const float* __restrict__ w) {
    int b = blockIdx.x;
    int t = threadIdx.x;  // 256
    if (b < 64) {                         // WqT
        int i = b * 256 + t;
        int k = i >> 7, tt = i & 127;
        g_wqt[i] = m1wi[(size_t)tt * DIM + k];
    } else if (b < 320) {                 // Mk
        int i = (b - 64) * 256 + t;
        int j = i >> 9, col = i & 511;
        int h = col >> 7, d = col & 127;
        const float* wk = m1wi + (size_t)DIM * DIM;
        g_Mk[i] = ((j >> 5) == h) ? wk[(size_t)j * DIM + d] : 0.f;
    } else if (b < 576) {                 // Zcat
        int i = (b - 320) * 256 + t;
        int row = i >> 7, tt = i & 127;
        int h = row >> 7, d = row & 127;
        const float* wv = m1wi + (size_t)2 * DIM * DIM;
        float acc = 0.f;
        #pragma unroll 8
        for (int j = 0; j < 32; j++)
            acc += m1wo[(size_t)tt * DIM + h * 32 + j] * wv[(size_t)(h * 32 + j) * DIM + d];
        g_Zcat[(size_t)row * DIM + tt] = acc;
    } else if (b == 576) {                // zb
        if (t < DIM) {
            const float* bv = m1bi + 2 * DIM;
            float acc = m1bo[t];
            #pragma unroll 8
            for (int k = 0; k < DIM; k++) acc += m1wo[(size_t)t * DIM + k] * bv[k];
            g_zb[t] = acc;
        }
    } else if (b < 641) {                 // m2wi transpose
        int i = (b - 577) * 256 + t;
        int n = i >> 7, k = i & 127;
        g_wt[(size_t)k * DIM + n] = m2wi[(size_t)n * DIM + k];
    } else if (b < 689) {                 // seqsum (48 blocks)
        if (t < DIM) {
            int sb = b - 641;
            int tensor = sb / 24, chunk = sb % 24;
            const float* base = tensor ? supply : demand;
            float acc = 0.f;
            int n0 = chunk * 128;
            for (int n = n0; n < n0 + 128; n++)
                acc += base[(size_t)n * SEQ * DIM + (size_t)(SEQ - 1) * DIM + t];
            atomicAdd(&(tensor ? g_ssum : g_dsum)[t], acc);
        }
    } else {                              // edge1 (768 blocks)
        int e = (b - 689) * 256 + t;
        if (e < EE) {
            int q = dst[e];
            atomicAdd(&g_degsp[q], w[e]);
            atomicAdd(&g_csr_cnt[q], 1);
        }
    }
}

// ----------------------------- stage2: scan (b0) + qv (merged, 1024 threads) ----------------------
__global__ void k_stage2(const float* __restrict__ skill, float* __restrict__ out_cat) {
    int b = blockIdx.x;
    int t = threadIdx.x;  // 1024
    if (b == 0) {         // scan
        __shared__ int sh[1024];
        int base = t * 6;
        int loc[6];
        int s = 0;
        #pragma unroll
        for (int k = 0; k < 6; k++) { loc[k] = s; s += g_csr_cnt[base + k]; }
        sh[t] = s;
        __syncthreads();
        for (int off = 1; off < 1024; off <<= 1) {
            int add = (t >= off) ? sh[t - off] : 0;
            __syncthreads();
            sh[t] += add;
            __syncthreads();
        }
        int excl = sh[t] - s;
        #pragma unroll
        for (int k = 0; k < 6; k++) {
            int o = excl + loc[k];
            g_csr_off[base + k] = o;
            g_csr_cnt[base + k] = o;
        }
        if (t == 1023) g_csr_off[TWO_N] = sh[1023];
    } else {              // qv + cat2 first half + out_cat
        int i = (b - 1) * 1024 + t;
        int bb = i >> 7, tt = i & 127;
        bool dem = bb < NN;
        int idx = dem ? bb : bb - NN;
        float sv = skill[(size_t)idx * DIM + tt];
        g_qv[i] = sv + (dem ? g_dsum : g_ssum)[tt];
        g_cat2[(size_t)bb * 2 * DIM + tt] = sv;
        out_cat[i] = sv;
    }
}

// ----------------------------- stage3: fillcsr + qp1 GEMM (merged) --------------------------------
__global__ void k_stage3(const int* __restrict__ src, const int* __restrict__ dst,
                         const float* __restrict__ w, const float* __restrict__ m1bi) {
    int b = blockIdx.x;
    if (b < 768) {
        int e = b * 256 + threadIdx.x;
        if (e < EE) {
            int s = src[e], q = dst[e];
            int pos = atomicAdd(&g_csr_cnt[q], 1);
            g_csr_src[pos] = s;
            g_csr_coef[pos] = rsqrtf(g_degsp[s]) * rsqrtf(g_degsp[q]) * w[e];
        }
    } else {
        sgemm_block(g_qv, g_wqt, m1bi, g_qp1, TWO_N, DIM, DIM, DIM, b - 768, 0);
    }
}

// ----------------------------- MHA1 attention core -----------------------------
__global__ void k_attn1(const float* __restrict__ demand, const float* __restrict__ supply,
                        const float* __restrict__ bi) {
    int b = blockIdx.x;
    int t = threadIdx.x;  // 128
    int w = t >> 5, lane = t & 31;
    bool dem = b < NN;
    int idx = dem ? b : b - NN;
    const float* seq = (dem ? demand : supply) + (size_t)idx * SEQ * DIM;

    __shared__ float sh_seq[SEQ][DIM + 1];
    __shared__ float sh_U[HH][DIM];
    __shared__ float sh_p[HH][SEQ];

    for (int i = t; i < SEQ * DIM; i += 128) sh_seq[i >> 7][i & 127] = seq[i];
    for (int i = t; i < HH * DIM; i += 128) sh_U[i >> 7][i & 127] = g_U[(size_t)b * 512 + i];
    __syncthreads();

    const float* bk = bi + DIM;
    float qb = g_qp1[(size_t)b * DIM + w * HD + lane] * bk[w * HD + lane];
    #pragma unroll
    for (int o = 16; o > 0; o >>= 1) qb += __shfl_xor_sync(0xffffffff, qb, o);

    float myl = -1e30f;
    if (lane < SEQ) {
        float acc = 0.f;
        #pragma unroll 16
        for (int d = 0; d < DIM; d++) acc += sh_U[w][d] * sh_seq[lane][d];
        myl = (acc + qb) * INV_SQRT_HD;
    }
    float mx = myl;
    #pragma unroll
    for (int o = 8; o > 0; o >>= 1) mx = fmaxf(mx, __shfl_xor_sync(0xffffffff, mx, o));
    float e = (lane < SEQ) ? expf(myl - mx) : 0.f;
    float sm = e;
    #pragma unroll
    for (int o = 8; o > 0; o >>= 1) sm += __shfl_xor_sync(0xffffffff, sm, o);
    if (lane < SEQ) sh_p[w][lane] = e / sm;
    __syncthreads();

    #pragma unroll
    for (int k = 0; k < 4; k++) {
        int d = lane + 32 * k;
        float acc = 0.f;
        #pragma unroll
        for (int s = 0; s < SEQ; s++) acc += sh_p[w][s] * sh_seq[s][d];
        g_c[(size_t)b * 512 + w * DIM + d] = acc;
    }
}

// ----------------------------- stage8: tanhprep + dense-l0 GEMM + sparse-l0 GEMM -------------------
__global__ void k_stage8(const float* __restrict__ sender, const float* __restrict__ receiver,
                         const float* __restrict__ W0, const float* __restrict__ W1) {
    int b = blockIdx.x;
    if (b < 3072) {
        if (g_flag) return;
        int i = b * 256 + threadIdx.x;
        float f = g_fused[i];
        g_s1[i] = tanhf(sender[0] * f);
        g_s2[i] = tanhf(receiver[0] * f);
    } else if (b < 3264) {
        sgemm_block(g_fused, W0, nullptr, g_xw, TWO_N, DIM, DIM, DIM, b - 3072, 0);
    } else {
        sgemm_block(g_fused, W1, nullptr, g_xw2, TWO_N, DIM, DIM, DIM, b - 3264, 0);
    }
}

// ----------------------------- scores (general path; grid-stride) -----------------------------
__global__ void k_scores() {
    if (g_flag) return;
    __shared__ float A1[16][DIM], A2[16][DIM], B1[16][DIM], B2[16][DIM];
    int t = threadIdx.x;  // 256
    const int TILES = TWO_N / 16;
    for (int tile = blockIdx.x; tile < TILES * TILES; tile += gridDim.x) {
        int i0 = (tile / TILES) * 16, j0 = (tile % TILES) * 16;
        __syncthreads();
        for (int j = 0; j < 8; j++) {
            int idx = t + 256 * j;
            int r = idx >> 7, c = idx & 127;
            A1[r][c] = g_s1[(size_t)(i0 + r) * DIM + c];
            A2[r][c] = g_s2[(size_t)(i0 + r) * DIM + c];
            B1[r][c] = g_s1[(size_t)(j0 + r) * DIM + c];
            B2[r][c] = g_s2[(size_t)(j0 + r) * DIM + c];
        }
        __syncthreads();
        int ti = t >> 4, tj = t & 15;
        float acc = 0.f;
        for (int k = 0; k < DIM; k++)
            acc += A1[ti][k] * B2[tj][k] - A2[ti][k] * B1[tj][k];
        g_scores[(size_t)(i0 + ti) * TWO_N + j0 + tj] = acc;
    }
}

// ----------------------------- predg general (softmax+threshold+deg) ------------------------------
__global__ void k_predg_general(float* __restrict__ out_pred) {
    if (g_flag) return;
    int row = blockIdx.x;
    int t = threadIdx.x;  // 256
    __shared__ float sh[256];
    float* sr = g_scores + (size_t)row * TWO_N;
    float mx = 0.f;
    for (int i = t; i < TWO_N; i += 256) mx = fmaxf(mx, fmaxf(sr[i], 0.f));
    mx = blockReduceMax(mx, sh);
    float sum = 0.f;
    for (int i = t; i < TWO_N; i += 256) sum += expf(fmaxf(sr[i], 0.f) - mx);
    sum = blockReduceSum(sum, sh);
    float inv = 1.f / sum;
    for (int i = t; i < TWO_N; i += 256) {
        float p = expf(fmaxf(sr[i], 0.f) - mx) * inv;
        float pr = fmaxf(p - DELTA_T, 0.f);
        sr[i] = pr;
        out_pred[(size_t)row * TWO_N + i] = pr;
        if (pr != 0.f) atomicAdd(&g_deg[i], pr);
    }
}

// ----------------------------- dense agg (general path) -----------------------------
__global__ void k_dense_agg() {
    if (g_flag) return;
    int i0 = blockIdx.x * 32;
    int t = threadIdx.x;  // 256
    __shared__ float pcol[32];
    __shared__ float xrow[DIM];
    int dbase = t & 127, half = t >> 7;
    float acc[16];
    #pragma unroll
    for (int r = 0; r < 16; r++) acc[r] = 0.f;
    for (int j = 0; j < TWO_N; j++) {
        if (t < 32) pcol[t] = g_scores[(size_t)j * TWO_N + i0 + t];
        else if (t >= 128 && t < 256) {
            float sj = rsqrtf(g_deg[j]);
            xrow[t - 128] = sj * g_xw[(size_t)j * DIM + (t - 128)];
        }
        __syncthreads();
        #pragma unroll
        for (int r = 0; r < 16; r++) acc[r] += pcol[half + 2 * r] * xrow[dbase];
        __syncthreads();
    }
    #pragma unroll
    for (int r = 0; r < 16; r++) {
        int i = i0 + half + 2 * r;
        float di = rsqrtf(g_deg[i]);
        g_agg[(size_t)i * DIM + dbase] = acc[r] + di * g_xw[(size_t)i * DIM + dbase];
    }
}

// ---------------- device bodies: dense combine / sparse gather ----------------
__device__ __forceinline__ void dense_combine_elem(int i, const float* prev, float* dst,
                                                   const float* b0, int layer) {
    float di = rsqrtf(g_deg[i >> 7]);
    float v = g_flag ? (di * di * g_xw[i]) : (di * g_agg[i]);
    float out = v + b0[layer * DIM + (i & 127)];
    dst[i] = (1.f - PRESERVE) * out + PRESERVE * prev[i];
}
__device__ __forceinline__ void spgather_node(int q, int tt, const float* xw, const float* prev,
                                              float* dstb, const float* b1, int layer, int addA) {
    float dv = rsqrtf(g_degsp[q]);
    float acc = dv * dv * xw[(size_t)q * DIM + tt];
    int beg = g_csr_off[q], end = g_csr_off[q + 1];
    int j = beg;
    for (; j + 1 < end; j += 2) {
        float c0 = g_csr_coef[j], c1 = g_csr_coef[j + 1];
        int   s0 = g_csr_src[j],  s1 = g_csr_src[j + 1];
        acc += c0 * xw[(size_t)s0 * DIM + tt] + c1 * xw[(size_t)s1 * DIM + tt];
    }
    if (j < end) acc += g_csr_coef[j] * xw[(size_t)g_csr_src[j] * DIM + tt];
    float outv = acc + b1[layer * DIM + tt];
    float blend = (1.f - PRESERVE) * outv + PRESERVE * prev[(size_t)q * DIM + tt];
    if (addA) blend += g_tmpA[(size_t)q * DIM + tt];
    dstb[(size_t)q * DIM + tt] = blend;
}

// stage12: dense_combine l0 + spgather l0 (merged)
__global__ void k_stage12(const float* __restrict__ b0, const float* __restrict__ b1) {
    int b = blockIdx.x;
    int t = threadIdx.x;  // 256
    if (b < 3072) {
        dense_combine_elem(b * 256 + t, g_fused, g_tmpA, b0, 0);
    } else {
        int q = (b - 3072) * 2 + (t >> 7);
        spgather_node(q, t & 127, g_xw2, g_fused, g_tmpB, b1, 0, 0);
    }
}

// stage13: dense l1 GEMM + sparse l1 GEMM (merged)
__global__ void k_stage13(const float* __restrict__ W0, const float* __restrict__ W1) {
    int b = blockIdx.x;
    if (b < 192) sgemm_block(g_tmpA, W0 + (size_t)DIM * DIM, nullptr, g_xw, TWO_N, DIM, DIM, DIM, b, 0);
    else         sgemm_block(g_tmpB, W1 + (size_t)DIM * DIM, nullptr, g_xw2, TWO_N, DIM, DIM, DIM, b - 192, 0);
}

// stage15: dense_combine l1
__global__ void k_stage15(const float* __restrict__ b0) {
    int i = blockIdx.x * 256 + threadIdx.x;
    if (i < TWO_N * DIM) dense_combine_elem(i, g_tmpA, g_tmpA, b0, 1);
}
// stage16: spgather l1 + add tmpA -> emb
__global__ void k_stage16(const float* __restrict__ b1) {
    int t = threadIdx.x;
    int q = blockIdx.x * 2 + (t >> 7);
    spgather_node(q, t & 127, g_xw2, g_tmpB, g_emb, b1, 1, 1);
}

// ----------------------------- pooling assignment softmax + entropy -----------------------------
__global__ void k_softmax_s() {
    int r = blockIdx.x, t = threadIdx.x;  // 128
    __shared__ float sh[128];
    float v = (t < CC) ? g_sm[(size_t)r * CC + t] : -1e30f;
    float mx = blockReduceMax(v, sh);
    float e = (t < CC) ? expf(v - mx) : 0.f;
    float sum = blockReduceSum(e, sh);
    float p = e / sum;
    float ent = (t < CC) ? (-p * logf(p + 1e-15f)) : 0.f;
    float es = blockReduceSum(ent, sh);
    if (t < CC) g_sm[(size_t)r * CC + t] = p;
    if (t == 0) atomicAdd(&g_acc[2], es);
}

// ----------------------------- stage19: pooled + gram + edge2 + predg_zero + qp2 GEMM -------------
__global__ void k_stage19(const int* __restrict__ src, const int* __restrict__ dst,
                          const float* __restrict__ w, const float* __restrict__ m2bi,
                          float* __restrict__ out_pred) {
    int b = blockIdx.x;
    int t = threadIdx.x;  // 256
    if (b < 200) {            // pooled
        if (t >= 128) return;
        int c4 = (b % 25) * 4;
        int i0 = (b / 25) * 768;
        float acc[4] = {0.f, 0.f, 0.f, 0.f};
        for (int i = i0; i < i0 + 768; i++) {
            float ev = g_emb[(size_t)i * DIM + t];
            #pragma unroll
            for (int cc = 0; cc < 4; cc++)
                acc[cc] += g_sm[(size_t)i * CC + c4 + cc] * ev;
        }
        #pragma unroll
        for (int cc = 0; cc < 4; cc++)
            atomicAdd(&g_pooled[(size_t)(c4 + cc) * DIM + t], acc[cc]);
    } else if (b < 400) {     // gram
        if (t >= CC) return;
        int c4 = ((b - 200) % 25) * 4;
        int i0 = ((b - 200) / 25) * 768;
        float acc[4] = {0.f, 0.f, 0.f, 0.f};
        for (int i = i0; i < i0 + 768; i++) {
            float st = g_sm[(size_t)i * CC + t];
            #pragma unroll
            for (int k = 0; k < 4; k++)
                acc[k] += g_sm[(size_t)i * CC + c4 + k] * st;
        }
        #pragma unroll
        for (int k = 0; k < 4; k++)
            atomicAdd(&g_G[(c4 + k) * CC + t], acc[k]);
    } else if (b < 24976) {   // edge2: scatterA + <A,SS^T>
        __shared__ float sh[8];
        int warp = t >> 5, lane = t & 31;
        int e = (b - 400) * 8 + warp;
        float acc = 0.f;
        if (e < EE) {
            int s = src[e], q = dst[e];
            float we = w[e];
            if (lane == 0) atomicAdd(&g_Adense[(size_t)s * TWO_N + q], we);
            for (int c = lane; c < CC; c += 32)
                acc += g_sm[(size_t)s * CC + c] * g_sm[(size_t)q * CC + c];
            acc *= we;
        }
        for (int o = 16; o > 0; o >>= 1) acc += __shfl_down_sync(0xffffffff, acc, o);
        if (lane == 0) sh[warp] = acc;
        __syncthreads();
        if (t == 0) {
            float s = 0.f;
            for (int i = 0; i < 8; i++) s += sh[i];
            atomicAdd(&g_acc[1], s);
        }
    } else if (b < 27024) {   // predg zero-fill (flag path)
        if (!g_flag) return;
        float4 z = make_float4(0.f, 0.f, 0.f, 0.f);
        float4* o = reinterpret_cast<float4*>(out_pred);
        size_t total = (size_t)TWO_N * TWO_N / 4;
        for (size_t j = (size_t)(b - 24976) * 256 + t; j < total; j += (size_t)2048 * 256)
            o[j] = z;
    } else {                  // qp2 GEMM (192 blocks)
        sgemm_block(g_emb, g_wt, m2bi, g_qp2, TWO_N, DIM, DIM, DIM, b - 27024, 0);
    }
}

// ----------------------------- stage20: kvproj + normA (merged) -----------------------------------
__global__ void k_stage20(const float* __restrict__ wi, const float* __restrict__ bi,
                          const int* __restrict__ src, const int* __restrict__ dst) {
    int b = blockIdx.x;
    int t = threadIdx.x;  // 256
    if (b < 200) {
        __shared__ float prow[DIM];
        int c = b >> 1, which = b & 1;
        if (t < 128) prow[t] = g_pooled[(size_t)c * DIM + t];
        __syncthreads();
        if (t >= 128) return;
        const float4* row4 = reinterpret_cast<const float4*>(wi + (size_t)(DIM + which * DIM + t) * DIM);
        float acc = bi[DIM + which * DIM + t];
        #pragma unroll
        for (int k = 0; k < 32; k++) {
            float4 r = row4[k];
            acc += r.x * prow[4 * k] + r.y * prow[4 * k + 1]
                 + r.z * prow[4 * k + 2] + r.w * prow[4 * k + 3];
        }
        (which ? g_vp2 : g_kp2)[(size_t)c * DIM + t] = acc;
    } else {
        __shared__ float sh[256];
        int e = (b - 200) * 256 + t;
        float v = 0.f;
        if (e < EE) {
            float old = atomicExch(&g_Adense[(size_t)src[e] * TWO_N + dst[e]], 0.f);
            v = old * old;
        }
        float s = blockReduceSum(v, sh);
        if (t == 0 && s != 0.f) atomicAdd(&g_acc[0], s);
    }
}

// ----------------------------- stage21: mha2 + gramfin (merged, 128 threads) ----------------------
#define K_LD 129
__global__ void k_stage21(const float* __restrict__ wo, const float* __restrict__ bo,
                          float* __restrict__ out_skill, float* __restrict__ out_loss) {
    extern __shared__ float kp_s[];     // [CC][K_LD] — used by mha2 blocks only
    int t = threadIdx.x;  // 128
    if (blockIdx.x == 384) {            // gramfin
        __shared__ float sh[128];
        float acc = 0.f;
        for (int i = t; i < CC * CC; i += 128) { float g = g_G[i]; acc += g * g; }
        sh[t] = acc; __syncthreads();
        for (int s = 64; s > 0; s >>= 1) {
            if (t < s) sh[t] += sh[t + s];
            __syncthreads();
        }
        if (t == 0) {
            float n2 = g_acc[0] - 2.f * g_acc[1] + sh[0];
            float link = sqrtf(fmaxf(n2, 0.f)) / ((float)TWO_N * (float)TWO_N);
            out_loss[0] = link + g_acc[2] / (float)TWO_N;
        }
        return;
    }
    // mha2
    __shared__ float qrow[DIM];
    __shared__ float lg[HH][CC];
    __shared__ float o_s[DIM];
    int w = t >> 5, lane = t & 31;
    for (int i = t; i < CC * DIM; i += 128) {
        int j = i >> 7, d = i & 127;
        kp_s[j * K_LD + d] = g_kp2[i];
    }
    __syncthreads();
    int n0 = blockIdx.x * 16;
    for (int q = 0; q < 16; q++) {
        int n = n0 + q;
        qrow[t] = g_qp2[(size_t)n * DIM + t];
        __syncthreads();
        for (int pos = t; pos < HH * CC; pos += 128) {
            int h = pos / CC, j = pos % CC;
            float acc = 0.f;
            #pragma unroll 8
            for (int d = 0; d < HD; d++)
                acc += qrow[h * HD + d] * kp_s[j * K_LD + h * HD + d];
            lg[h][j] = acc * INV_SQRT_HD;
        }
        __syncthreads();
        {
            float mx = -1e30f;
            for (int j = lane; j < CC; j += 32) mx = fmaxf(mx, lg[w][j]);
            #pragma unroll
            for (int o = 16; o > 0; o >>= 1) mx = fmaxf(mx, __shfl_xor_sync(0xffffffff, mx, o));
            float sm = 0.f;
            for (int j = lane; j < CC; j += 32) { float e = expf(lg[w][j] - mx); lg[w][j] = e; sm += e; }
            #pragma unroll
            for (int o = 16; o > 0; o >>= 1) sm += __shfl_xor_sync(0xffffffff, sm, o);
            float inv = 1.f / sm;
            for (int j = lane; j < CC; j += 32) lg[w][j] *= inv;
        }
        __syncthreads();
        {
            float acc = 0.f;
            for (int j = 0; j < CC; j++) acc += lg[w][j] * g_vp2[(size_t)j * DIM + t];
            o_s[t] = acc;
        }
        __syncthreads();
        {
            const float4* row4 = reinterpret_cast<const float4*>(wo + (size_t)t * DIM);
            float acc = bo[t];
            #pragma unroll
            for (int k = 0; k < 32; k++) {
                float4 r = row4[k];
                acc += r.x * o_s[4 * k] + r.y * o_s[4 * k + 1]
                     + r.z * o_s[4 * k + 2] + r.w * o_s[4 * k + 3];
            }
            out_skill[(size_t)n * DIM + t] = 2.f * g_emb[(size_t)n * DIM + t] + acc;
        }
        __syncthreads();
    }
}

// ----------------------------- host launch -----------------------------
extern "C" void kernel_launch(void* const* d_in, const int* in_sizes, int n_in,
                              void* d_out, int out_size) {
    const float* demand = (const float*)d_in[0];
    const float* supply = (const float*)d_in[1];
    const float* skill  = (const float*)d_in[2];
    const int*   eidx   = (const int*)d_in[3];
    const float* eattr  = (const float*)d_in[4];
    const float* w_fuse = (const float*)d_in[5];
    const float* b_fuse = (const float*)d_in[6];
    const float* m1wi   = (const float*)d_in[7];
    const float* m1bi   = (const float*)d_in[8];
    const float* m1wo   = (const float*)d_in[9];
    const float* m1bo   = (const float*)d_in[10];
    const float* m2wi   = (const float*)d_in[11];
    const float* m2bi   = (const float*)d_in[12];
    const float* m2wo   = (const float*)d_in[13];
    const float* m2bo   = (const float*)d_in[14];
    const float* sender = (const float*)d_in[15];
    const float* recv   = (const float*)d_in[16];
    const float* W0     = (const float*)d_in[17];
    const float* b0     = (const float*)d_in[18];
    const float* W1     = (const float*)d_in[19];
    const float* b1     = (const float*)d_in[20];
    const float* Wp     = (const float*)d_in[21];
    const float* bp     = (const float*)d_in[22];
    float* out = (float*)d_out;
    const int* src = eidx;
    const int* dst = eidx + EE;

    cudaFuncSetAttribute(k_stage21, cudaFuncAttributeMaxDynamicSharedMemorySize,
                         CC * K_LD * (int)sizeof(float) + 1024);

    float *p_qp1, *p_U, *p_c, *p_Mk, *p_Zcat, *p_zb, *p_cat2, *p_fused, *p_emb, *p_sm;
    cudaGetSymbolAddress((void**)&p_qp1, g_qp1);
    cudaGetSymbolAddress((void**)&p_U, g_U);
    cudaGetSymbolAddress((void**)&p_c, g_c);
    cudaGetSymbolAddress((void**)&p_Mk, g_Mk);
    cudaGetSymbolAddress((void**)&p_Zcat, g_Zcat);
    cudaGetSymbolAddress((void**)&p_zb, g_zb);
    cudaGetSymbolAddress((void**)&p_cat2, g_cat2);
    cudaGetSymbolAddress((void**)&p_fused, g_fused);
    cudaGetSymbolAddress((void**)&p_emb, g_emb);
    cudaGetSymbolAddress((void**)&p_sm, g_sm);

    k_init<<<64, 256>>>(sender, recv);
    k_stage1<<<1457, 256>>>(m1wi, m1wo, m1bo, m1bi, m2wi, demand, supply, dst, eattr);
    k_stage2<<<769, 1024>>>(skill, out + OUT_CAT);
    k_stage3<<<960, 256>>>(src, dst, eattr, m1bi);
    k_sgemm<<<dim3(4, TWO_N / 32), 256>>>(p_qp1, p_Mk, nullptr, p_U, TWO_N, 4 * DIM, DIM, 4 * DIM);
    k_attn1<<<TWO_N, 128>>>(demand, supply, m1bi);
    k_sgemm<<<dim3(1, TWO_N / 32), 256>>>(p_c, p_Zcat, p_zb, p_cat2 + DIM, TWO_N, DIM, 4 * DIM, 2 * DIM);
    k_sgemm<<<dim3(1, TWO_N / 32), 256>>>(p_cat2, w_fuse, b_fuse, p_fused, TWO_N, DIM, 2 * DIM, DIM);

    k_stage8<<<3456, 256>>>(sender, recv, W0, W1);
    k_scores<<<1184, 256>>>();
    k_predg_general<<<TWO_N, 256>>>(out + OUT_PRED);
    k_dense_agg<<<TWO_N / 32, 256>>>();
    k_stage12<<<6144, 256>>>(b0, b1);
    k_stage13<<<384, 256>>>(W0, W1);
    k_dense_agg<<<TWO_N / 32, 256>>>();
    k_stage15<<<3072, 256>>>(b0);
    k_stage16<<<3072, 256>>>(b1);

    k_sgemm<<<dim3(1, TWO_N / 32), 256>>>(p_emb, Wp, bp, p_sm, TWO_N, CC, DIM, CC);
    k_softmax_s<<<TWO_N, 128>>>();
    k_stage19<<<27216, 256>>>(src, dst, eattr, m2bi, out + OUT_PRED);
    k_stage20<<<968, 256>>>(m2wi, m2bi, src, dst);
    k_stage21<<<385, 128, CC * K_LD * sizeof(float) + 1024>>>(m2wo, m2bo, out + OUT_SKILL, out + OUT_LOSS);
}

// round 12
// speedup vs baseline: 1.5413x; 1.0919x over previous
#include <cuda_runtime.h>
#include <math.h>

#define NN      3072
#define TWO_N   6144
#define DIM     128
#define SEQ     16
#define EE      196608
#define CC      100
#define HH      4
#define HD      32
#define INV_SQRT_HD 0.17677669529663687f
#define DELTA_T 0.1f
#define PRESERVE 0.1f

#define OUT_CAT   0
#define OUT_SKILL (TWO_N * DIM)
#define OUT_PRED  (2 * TWO_N * DIM)
#define OUT_LOSS  (2 * TWO_N * DIM + TWO_N * TWO_N)

// ----------------------------- device scratch -----------------------------
__device__ float g_dsum[DIM];
__device__ float g_ssum[DIM];
__device__ float g_cat2[(size_t)TWO_N * 2 * DIM];
__device__ float g_fused[(size_t)TWO_N * DIM];
__device__ float g_s1[(size_t)TWO_N * DIM];
__device__ float g_s2[(size_t)TWO_N * DIM];
__device__ float g_scores[(size_t)TWO_N * TWO_N];   // general path only
__device__ float g_Adense[(size_t)TWO_N * TWO_N];   // zero between launches (exch trick)
__device__ float g_deg[TWO_N];
__device__ float g_degsp[TWO_N];
__device__ float g_xw[(size_t)TWO_N * DIM];     // dense chain
__device__ float g_xw2[(size_t)TWO_N * DIM];    // sparse chain
__device__ float g_agg[(size_t)TWO_N * DIM];
__device__ float g_tmpA[(size_t)TWO_N * DIM];
__device__ float g_tmpB[(size_t)TWO_N * DIM];
__device__ float g_emb[(size_t)TWO_N * DIM];
__device__ float g_sm[(size_t)TWO_N * CC];
__device__ float g_pooled[CC * DIM];
__device__ float g_G[CC * CC];
__device__ float g_kp2[CC * DIM];
__device__ float g_vp2[CC * DIM];
__device__ float g_qp2[(size_t)TWO_N * DIM];
__device__ float g_wt[DIM * DIM];
__device__ float g_acc[8];   // [0]=||A||^2 [1]=<A,SS^T> [2]=ent_sum
__device__ int   g_flag;

// MHA1 GEMM-chain buffers
__device__ float g_qv[(size_t)TWO_N * DIM];
__device__ float g_qp1[(size_t)TWO_N * DIM];
__device__ float g_U[(size_t)TWO_N * 4 * DIM];
__device__ float g_c[(size_t)TWO_N * 4 * DIM];
__device__ float g_wqt[DIM * DIM];
__device__ float g_Zcat[4 * DIM * DIM];
__device__ float g_zb[DIM];

// CSR for sparse GCN (+ raw weights for link loss)
__device__ int   g_csr_cnt[TWO_N];
__device__ int   g_csr_off[TWO_N + 1];
__device__ int   g_csr_src[EE];
__device__ float g_csr_coef[EE];
__device__ float g_csr_w[EE];

// ----------------------------- helpers -----------------------------
__device__ __forceinline__ float blockReduceSum(float v, float* sh) {
    int t = threadIdx.x;
    sh[t] = v; __syncthreads();
    for (int s = blockDim.x >> 1; s > 0; s >>= 1) {
        if (t < s) sh[t] += sh[t + s];
        __syncthreads();
    }
    float r = sh[0]; __syncthreads();
    return r;
}
__device__ __forceinline__ float blockReduceMax(float v, float* sh) {
    int t = threadIdx.x;
    sh[t] = v; __syncthreads();
    for (int s = blockDim.x >> 1; s > 0; s >>= 1) {
        if (t < s) sh[t] = fmaxf(sh[t], sh[t + s]);
        __syncthreads();
    }
    float r = sh[0]; __syncthreads();
    return r;
}

// ---------------- SGEMM device block-function: 32x128 tile, double-buffered ----------------
__device__ void sgemm_block(const float* __restrict__ A, const float* __restrict__ B,
                            const float* __restrict__ bias, float* __restrict__ Cmat,
                            int M, int Nn, int K, int lda, int ldc, int bmi, int bni) {
    __shared__ float As[2][16][33];
    __shared__ float Bs[2][16][128];
    int bm = bmi * 32;
    int bn = bni * 128;
    int tid = threadIdx.x;
    int tr = tid >> 5, tc = tid & 31;
    float acc[4][4];
    #pragma unroll
    for (int r = 0; r < 4; r++)
        #pragma unroll
        for (int c = 0; c < 4; c++) acc[r][c] = 0.f;

    #pragma unroll
    for (int j = 0; j < 2; j++) {
        int idx = tid + 256 * j;
        int m = idx >> 4, kk = idx & 15;
        As[0][kk][m] = A[(size_t)(bm + m) * lda + kk];
    }
    #pragma unroll
    for (int j = 0; j < 8; j++) {
        int idx = tid + 256 * j;
        int kk = idx >> 7, n = idx & 127;
        Bs[0][kk][n] = (bn + n < Nn) ? B[(size_t)kk * Nn + bn + n] : 0.f;
    }
    __syncthreads();

    int buf = 0;
    for (int k0 = 0; k0 < K; k0 += 16) {
        int nb = buf ^ 1;
        if (k0 + 16 < K) {
            #pragma unroll
            for (int j = 0; j < 2; j++) {
                int idx = tid + 256 * j;
                int m = idx >> 4, kk = idx & 15;
                As[nb][kk][m] = A[(size_t)(bm + m) * lda + k0 + 16 + kk];
            }
            #pragma unroll
            for (int j = 0; j < 8; j++) {
                int idx = tid + 256 * j;
                int kk = idx >> 7, n = idx & 127;
                Bs[nb][kk][n] = (bn + n < Nn) ? B[(size_t)(k0 + 16 + kk) * Nn + bn + n] : 0.f;
            }
        }
        #pragma unroll
        for (int kk = 0; kk < 16; kk++) {
            float a0 = As[buf][kk][tr * 4 + 0];
            float a1 = As[buf][kk][tr * 4 + 1];
            float a2 = As[buf][kk][tr * 4 + 2];
            float a3 = As[buf][kk][tr * 4 + 3];
            float4 b4 = *reinterpret_cast<const float4*>(&Bs[buf][kk][tc * 4]);
            acc[0][0] += a0 * b4.x; acc[0][1] += a0 * b4.y; acc[0][2] += a0 * b4.z; acc[0][3] += a0 * b4.w;
            acc[1][0] += a1 * b4.x; acc[1][1] += a1 * b4.y; acc[1][2] += a1 * b4.z; acc[1][3] += a1 * b4.w;
            acc[2][0] += a2 * b4.x; acc[2][1] += a2 * b4.y; acc[2][2] += a2 * b4.z; acc[2][3] += a2 * b4.w;
            acc[3][0] += a3 * b4.x; acc[3][1] += a3 * b4.y; acc[3][2] += a3 * b4.z; acc[3][3] += a3 * b4.w;
        }
        __syncthreads();
        buf = nb;
    }
    #pragma unroll
    for (int r = 0; r < 4; r++) {
        int m = bm + tr * 4 + r;
        if (m >= M) continue;
        #pragma unroll
        for (int c = 0; c < 4; c++) {
            int n = bn + tc * 4 + c;
            if (n < Nn) {
                float v = acc[r][c];
                if (bias) v += bias[n];
                Cmat[(size_t)m * ldc + n] = v;
            }
        }
    }
}

__global__ void k_sgemm(const float* __restrict__ A, const float* __restrict__ B,
                        const float* __restrict__ bias, float* __restrict__ Cmat,
                        int M, int Nn, int K, int ldc) {
    sgemm_block(A, B, bias, Cmat, M, Nn, K, K, ldc, blockIdx.y, blockIdx.x);
}

// U projection: per-head K=32 GEMMs. head = b/192, row-tile = b%192.
__global__ void k_ugemm(const float* __restrict__ m1wi) {
    int head = blockIdx.x / 192;
    int bmi = blockIdx.x % 192;
    const float* wk = m1wi + (size_t)DIM * DIM + (size_t)head * 32 * DIM;
    sgemm_block(g_qp1 + head * 32, wk, nullptr, g_U + head * 128,
                TWO_N, DIM, 32, DIM, 4 * DIM, bmi, 0);
}

// ----------------------------- init -----------------------------
__global__ void k_init(const float* __restrict__ sender, const float* __restrict__ receiver) {
    int i = blockIdx.x * blockDim.x + threadIdx.x;
    if (i < TWO_N) { g_deg[i] = 1.0f; g_degsp[i] = 1.0f; g_csr_cnt[i] = 0; }
    if (i < CC * DIM) g_pooled[i] = 0.f;
    if (i < CC * CC) g_G[i] = 0.f;
    if (i < 2 * DIM) (i < DIM ? g_dsum : g_ssum)[i & 127] = 0.f;
    if (i < 8) g_acc[i] = 0.f;
    if (i == 0) g_flag = (sender[0] == receiver[0]) ? 1 : 0;
}

// ----------------------------- stage1: prep + seqsum + edge1 (merged) -----------------------------
__global__ void k_stage1(const float* __restrict__ m1wi, const float* __restrict__ m1wo,
                         const float* __restrict__ m1bo, const float* __restrict__ m1bi,
                         const float* __restrict__ m2wi,
                         const float* __restrict__ demand, const float* __restrict__ supply,
                         const int* __restrict__ dst, const float* __restrict__ w) {
    int b = blockIdx.x;
    int t = threadIdx.x;  // 256
    if (b < 64) {                         // WqT
        int i = b * 256 + t;
        int k = i >> 7, tt = i & 127;
        g_wqt[i] = m1wi[(size_t)tt * DIM + k];
    } else if (b < 320) {                 // Zcat
        int i = (b - 64) * 256 + t;
        int row = i >> 7, tt = i & 127;
        int h = row >> 7, d = row & 127;
        const float* wv = m1wi + (size_t)2 * DIM * DIM;
        float acc = 0.f;
        #pragma unroll 8
        for (int j = 0; j < 32; j++)
            acc += m1wo[(size_t)tt * DIM + h * 32 + j] * wv[(size_t)(h * 32 + j) * DIM + d];
        g_Zcat[(size_t)row * DIM + tt] = acc;
    } else if (b == 320) {                // zb
        if (t < DIM) {
            const float* bv = m1bi + 2 * DIM;
            float acc = m1bo[t];
            #pragma unroll 8
            for (int k = 0; k < DIM; k++) acc += m1wo[(size_t)t * DIM + k] * bv[k];
            g_zb[t] = acc;
        }
    } else if (b < 385) {                 // m2wi transpose (64)
        int i = (b - 321) * 256 + t;
        int n = i >> 7, k = i & 127;
        g_wt[(size_t)k * DIM + n] = m2wi[(size_t)n * DIM + k];
    } else if (b < 433) {                 // seqsum (48)
        if (t < DIM) {
            int sb = b - 385;
            int tensor = sb / 24, chunk = sb % 24;
            const float* base = tensor ? supply : demand;
            float acc = 0.f;
            int n0 = chunk * 128;
            for (int n = n0; n < n0 + 128; n++)
                acc += base[(size_t)n * SEQ * DIM + (size_t)(SEQ - 1) * DIM + t];
            atomicAdd(&(tensor ? g_ssum : g_dsum)[t], acc);
        }
    } else {                              // edge1 (768)
        int e = (b - 433) * 256 + t;
        if (e < EE) {
            int q = dst[e];
            atomicAdd(&g_degsp[q], w[e]);
            atomicAdd(&g_csr_cnt[q], 1);
        }
    }
}

// ----------------------------- stage2: scan (b0) + qv (merged, 1024 threads) ----------------------
__global__ void k_stage2(const float* __restrict__ skill, float* __restrict__ out_cat) {
    int b = blockIdx.x;
    int t = threadIdx.x;  // 1024
    if (b == 0) {         // scan
        __shared__ int sh[1024];
        int base = t * 6;
        int loc[6];
        int s = 0;
        #pragma unroll
        for (int k = 0; k < 6; k++) { loc[k] = s; s += g_csr_cnt[base + k]; }
        sh[t] = s;
        __syncthreads();
        for (int off = 1; off < 1024; off <<= 1) {
            int add = (t >= off) ? sh[t - off] : 0;
            __syncthreads();
            sh[t] += add;
            __syncthreads();
        }
        int excl = sh[t] - s;
        #pragma unroll
        for (int k = 0; k < 6; k++) {
            int o = excl + loc[k];
            g_csr_off[base + k] = o;
            g_csr_cnt[base + k] = o;
        }
        if (t == 1023) g_csr_off[TWO_N] = sh[1023];
    } else {              // qv + cat2 first half + out_cat
        int i = (b - 1) * 1024 + t;
        int bb = i >> 7, tt = i & 127;
        bool dem = bb < NN;
        int idx = dem ? bb : bb - NN;
        float sv = skill[(size_t)idx * DIM + tt];
        g_qv[i] = sv + (dem ? g_dsum : g_ssum)[tt];
        g_cat2[(size_t)bb * 2 * DIM + tt] = sv;
        out_cat[i] = sv;
    }
}

// ----------------------------- stage3: fillcsr + qp1 GEMM (merged) --------------------------------
__global__ void k_stage3(const int* __restrict__ src, const int* __restrict__ dst,
                         const float* __restrict__ w, const float* __restrict__ m1bi) {
    int b = blockIdx.x;
    if (b < 768) {
        int e = b * 256 + threadIdx.x;
        if (e < EE) {
            int s = src[e], q = dst[e];
            float we = w[e];
            int pos = atomicAdd(&g_csr_cnt[q], 1);
            g_csr_src[pos] = s;
            g_csr_coef[pos] = rsqrtf(g_degsp[s]) * rsqrtf(g_degsp[q]) * we;
            g_csr_w[pos] = we;
        }
    } else {
        sgemm_block(g_qv, g_wqt, m1bi, g_qp1, TWO_N, DIM, DIM, DIM, DIM, b - 768, 0);
    }
}

// ----------------------------- MHA1 attention core -----------------------------
__global__ void k_attn1(const float* __restrict__ demand, const float* __restrict__ supply,
                        const float* __restrict__ bi) {
    int b = blockIdx.x;
    int t = threadIdx.x;  // 128
    int w = t >> 5, lane = t & 31;
    bool dem = b < NN;
    int idx = dem ? b : b - NN;
    const float* seq = (dem ? demand : supply) + (size_t)idx * SEQ * DIM;

    __shared__ float sh_seq[SEQ][DIM + 1];
    __shared__ float sh_U[HH][DIM];
    __shared__ float sh_p[HH][SEQ];

    for (int i = t; i < SEQ * DIM; i += 128) sh_seq[i >> 7][i & 127] = seq[i];
    for (int i = t; i < HH * DIM; i += 128) sh_U[i >> 7][i & 127] = g_U[(size_t)b * 512 + i];
    __syncthreads();

    const float* bk = bi + DIM;
    float qb = g_qp1[(size_t)b * DIM + w * HD + lane] * bk[w * HD + lane];
    #pragma unroll
    for (int o = 16; o > 0; o >>= 1) qb += __shfl_xor_sync(0xffffffff, qb, o);

    float myl = -1e30f;
    if (lane < SEQ) {
        float acc = 0.f;
        #pragma unroll 16
        for (int d = 0; d < DIM; d++) acc += sh_U[w][d] * sh_seq[lane][d];
        myl = (acc + qb) * INV_SQRT_HD;
    }
    float mx = myl;
    #pragma unroll
    for (int o = 8; o > 0; o >>= 1) mx = fmaxf(mx, __shfl_xor_sync(0xffffffff, mx, o));
    float e = (lane < SEQ) ? expf(myl - mx) : 0.f;
    float sm = e;
    #pragma unroll
    for (int o = 8; o > 0; o >>= 1) sm += __shfl_xor_sync(0xffffffff, sm, o);
    if (lane < SEQ) sh_p[w][lane] = e / sm;
    __syncthreads();

    #pragma unroll
    for (int k = 0; k < 4; k++) {
        int d = lane + 32 * k;
        float acc = 0.f;
        #pragma unroll
        for (int s = 0; s < SEQ; s++) acc += sh_p[w][s] * sh_seq[s][d];
        g_c[(size_t)b * 512 + w * DIM + d] = acc;
    }
}

// ----------------------------- stage8: tanhprep + dense-l0 GEMM + sparse-l0 GEMM -------------------
__global__ void k_stage8(const float* __restrict__ sender, const float* __restrict__ receiver,
                         const float* __restrict__ W0, const float* __restrict__ W1) {
    int b = blockIdx.x;
    if (b < 3072) {
        if (g_flag) return;
        int i = b * 256 + threadIdx.x;
        float f = g_fused[i];
        g_s1[i] = tanhf(sender[0] * f);
        g_s2[i] = tanhf(receiver[0] * f);
    } else if (b < 3264) {
        sgemm_block(g_fused, W0, nullptr, g_xw, TWO_N, DIM, DIM, DIM, DIM, b - 3072, 0);
    } else {
        sgemm_block(g_fused, W1, nullptr, g_xw2, TWO_N, DIM, DIM, DIM, DIM, b - 3264, 0);
    }
}

// ----------------------------- scores (general path; grid-stride) -----------------------------
__global__ void k_scores() {
    if (g_flag) return;
    __shared__ float A1[16][DIM], A2[16][DIM], B1[16][DIM], B2[16][DIM];
    int t = threadIdx.x;  // 256
    const int TILES = TWO_N / 16;
    for (int tile = blockIdx.x; tile < TILES * TILES; tile += gridDim.x) {
        int i0 = (tile / TILES) * 16, j0 = (tile % TILES) * 16;
        __syncthreads();
        for (int j = 0; j < 8; j++) {
            int idx = t + 256 * j;
            int r = idx >> 7, c = idx & 127;
            A1[r][c] = g_s1[(size_t)(i0 + r) * DIM + c];
            A2[r][c] = g_s2[(size_t)(i0 + r) * DIM + c];
            B1[r][c] = g_s1[(size_t)(j0 + r) * DIM + c];
            B2[r][c] = g_s2[(size_t)(j0 + r) * DIM + c];
        }
        __syncthreads();
        int ti = t >> 4, tj = t & 15;
        float acc = 0.f;
        for (int k = 0; k < DIM; k++)
            acc += A1[ti][k] * B2[tj][k] - A2[ti][k] * B1[tj][k];
        g_scores[(size_t)(i0 + ti) * TWO_N + j0 + tj] = acc;
    }
}

// ----------------------------- predg general (softmax+threshold+deg) ------------------------------
__global__ void k_predg_general(float* __restrict__ out_pred) {
    if (g_flag) return;
    int row = blockIdx.x;
    int t = threadIdx.x;  // 256
    __shared__ float sh[256];
    float* sr = g_scores + (size_t)row * TWO_N;
    float mx = 0.f;
    for (int i = t; i < TWO_N; i += 256) mx = fmaxf(mx, fmaxf(sr[i], 0.f));
    mx = blockReduceMax(mx, sh);
    float sum = 0.f;
    for (int i = t; i < TWO_N; i += 256) sum += expf(fmaxf(sr[i], 0.f) - mx);
    sum = blockReduceSum(sum, sh);
    float inv = 1.f / sum;
    for (int i = t; i < TWO_N; i += 256) {
        float p = expf(fmaxf(sr[i], 0.f) - mx) * inv;
        float pr = fmaxf(p - DELTA_T, 0.f);
        sr[i] = pr;
        out_pred[(size_t)row * TWO_N + i] = pr;
        if (pr != 0.f) atomicAdd(&g_deg[i], pr);
    }
}

// ----------------------------- dense agg (general path) -----------------------------
__global__ void k_dense_agg() {
    if (g_flag) return;
    int i0 = blockIdx.x * 32;
    int t = threadIdx.x;  // 256
    __shared__ float pcol[32];
    __shared__ float xrow[DIM];
    int dbase = t & 127, half = t >> 7;
    float acc[16];
    #pragma unroll
    for (int r = 0; r < 16; r++) acc[r] = 0.f;
    for (int j = 0; j < TWO_N; j++) {
        if (t < 32) pcol[t] = g_scores[(size_t)j * TWO_N + i0 + t];
        else if (t >= 128 && t < 256) {
            float sj = rsqrtf(g_deg[j]);
            xrow[t - 128] = sj * g_xw[(size_t)j * DIM + (t - 128)];
        }
        __syncthreads();
        #pragma unroll
        for (int r = 0; r < 16; r++) acc[r] += pcol[half + 2 * r] * xrow[dbase];
        __syncthreads();
    }
    #pragma unroll
    for (int r = 0; r < 16; r++) {
        int i = i0 + half + 2 * r;
        float di = rsqrtf(g_deg[i]);
        g_agg[(size_t)i * DIM + dbase] = acc[r] + di * g_xw[(size_t)i * DIM + dbase];
    }
}

// ---------------- device bodies: dense combine / sparse gather ----------------
__device__ __forceinline__ void dense_combine_elem(int i, const float* prev, float* dst,
                                                   const float* b0, int layer) {
    float di = rsqrtf(g_deg[i >> 7]);
    float v = g_flag ? (di * di * g_xw[i]) : (di * g_agg[i]);
    float out = v + b0[layer * DIM + (i & 127)];
    dst[i] = (1.f - PRESERVE) * out + PRESERVE * prev[i];
}
__device__ __forceinline__ void spgather_node(int q, int tt, const float* xw, const float* prev,
                                              float* dstb, const float* b1, int layer, int addA) {
    float dv = rsqrtf(g_degsp[q]);
    float acc = dv * dv * xw[(size_t)q * DIM + tt];
    int beg = g_csr_off[q], end = g_csr_off[q + 1];
    int j = beg;
    for (; j + 1 < end; j += 2) {
        float c0 = g_csr_coef[j], c1 = g_csr_coef[j + 1];
        int   s0 = g_csr_src[j],  s1 = g_csr_src[j + 1];
        acc += c0 * xw[(size_t)s0 * DIM + tt] + c1 * xw[(size_t)s1 * DIM + tt];
    }
    if (j < end) acc += g_csr_coef[j] * xw[(size_t)g_csr_src[j] * DIM + tt];
    float outv = acc + b1[layer * DIM + tt];
    float blend = (1.f - PRESERVE) * outv + PRESERVE * prev[(size_t)q * DIM + tt];
    if (addA) blend += g_tmpA[(size_t)q * DIM + tt];
    dstb[(size_t)q * DIM + tt] = blend;
}

// stage12: dense_combine l0 + spgather l0 (merged)
__global__ void k_stage12(const float* __restrict__ b0, const float* __restrict__ b1) {
    int b = blockIdx.x;
    int t = threadIdx.x;  // 256
    if (b < 3072) {
        dense_combine_elem(b * 256 + t, g_fused, g_tmpA, b0, 0);
    } else {
        int q = (b - 3072) * 2 + (t >> 7);
        spgather_node(q, t & 127, g_xw2, g_fused, g_tmpB, b1, 0, 0);
    }
}

// stage13: dense l1 GEMM + sparse l1 GEMM (merged)
__global__ void k_stage13(const float* __restrict__ W0, const float* __restrict__ W1) {
    int b = blockIdx.x;
    if (b < 192) sgemm_block(g_tmpA, W0 + (size_t)DIM * DIM, nullptr, g_xw, TWO_N, DIM, DIM, DIM, DIM, b, 0);
    else         sgemm_block(g_tmpB, W1 + (size_t)DIM * DIM, nullptr, g_xw2, TWO_N, DIM, DIM, DIM, DIM, b - 192, 0);
}

// stage15: dense_combine l1
__global__ void k_stage15(const float* __restrict__ b0) {
    int i = blockIdx.x * 256 + threadIdx.x;
    if (i < TWO_N * DIM) dense_combine_elem(i, g_tmpA, g_tmpA, b0, 1);
}
// stage16: spgather l1 + add tmpA -> emb
__global__ void k_stage16(const float* __restrict__ b1) {
    int t = threadIdx.x;
    int q = blockIdx.x * 2 + (t >> 7);
    spgather_node(q, t & 127, g_xw2, g_tmpB, g_emb, b1, 1, 1);
}

// ----------------------------- sm GEMM with fused softmax + entropy -------------------------------
__global__ void k_sm_gemm(const float* __restrict__ Wp, const float* __restrict__ bp) {
    __shared__ float As[2][16][33];
    __shared__ float Bs[2][16][128];
    int bm = blockIdx.x * 32;
    int tid = threadIdx.x;
    int tr = tid >> 5, tc = tid & 31;
    float acc[4][4];
    #pragma unroll
    for (int r = 0; r < 4; r++)
        #pragma unroll
        for (int c = 0; c < 4; c++) acc[r][c] = 0.f;

    #pragma unroll
    for (int j = 0; j < 2; j++) {
        int idx = tid + 256 * j;
        int m = idx >> 4, kk = idx & 15;
        As[0][kk][m] = g_emb[(size_t)(bm + m) * DIM + kk];
    }
    #pragma unroll
    for (int j = 0; j < 8; j++) {
        int idx = tid + 256 * j;
        int kk = idx >> 7, n = idx & 127;
        Bs[0][kk][n] = (n < CC) ? Wp[(size_t)kk * CC + n] : 0.f;
    }
    __syncthreads();
    int buf = 0;
    for (int k0 = 0; k0 < DIM; k0 += 16) {
        int nb = buf ^ 1;
        if (k0 + 16 < DIM) {
            #pragma unroll
            for (int j = 0; j < 2; j++) {
                int idx = tid + 256 * j;
                int m = idx >> 4, kk = idx & 15;
                As[nb][kk][m] = g_emb[(size_t)(bm + m) * DIM + k0 + 16 + kk];
            }
            #pragma unroll
            for (int j = 0; j < 8; j++) {
                int idx = tid + 256 * j;
                int kk = idx >> 7, n = idx & 127;
                Bs[nb][kk][n] = (n < CC) ? Wp[(size_t)(k0 + 16 + kk) * CC + n] : 0.f;
            }
        }
        #pragma unroll
        for (int kk = 0; kk < 16; kk++) {
            float a0 = As[buf][kk][tr * 4 + 0];
            float a1 = As[buf][kk][tr * 4 + 1];
            float a2 = As[buf][kk][tr * 4 + 2];
            float a3 = As[buf][kk][tr * 4 + 3];
            float4 b4 = *reinterpret_cast<const float4*>(&Bs[buf][kk][tc * 4]);
            acc[0][0] += a0 * b4.x; acc[0][1] += a0 * b4.y; acc[0][2] += a0 * b4.z; acc[0][3] += a0 * b4.w;
            acc[1][0] += a1 * b4.x; acc[1][1] += a1 * b4.y; acc[1][2] += a1 * b4.z; acc[1][3] += a1 * b4.w;
            acc[2][0] += a2 * b4.x; acc[2][1] += a2 * b4.y; acc[2][2] += a2 * b4.z; acc[2][3] += a2 * b4.w;
            acc[3][0] += a3 * b4.x; acc[3][1] += a3 * b4.y; acc[3][2] += a3 * b4.z; acc[3][3] += a3 * b4.w;
        }
        __syncthreads();
        buf = nb;
    }
    float entpart = 0.f;
    #pragma unroll
    for (int r = 0; r < 4; r++) {
        int row = bm + tr * 4 + r;
        float v[4];
        float mx = -1e30f;
        #pragma unroll
        for (int c = 0; c < 4; c++) {
            int n = tc * 4 + c;
            v[c] = (n < CC) ? (acc[r][c] + bp[n]) : -1e30f;
            mx = fmaxf(mx, v[c]);
        }
        #pragma unroll
        for (int o = 16; o > 0; o >>= 1) mx = fmaxf(mx, __shfl_xor_sync(0xffffffff, mx, o));
        float sm = 0.f;
        float ex[4];
        #pragma unroll
        for (int c = 0; c < 4; c++) {
            int n = tc * 4 + c;
            ex[c] = (n < CC) ? expf(v[c] - mx) : 0.f;
            sm += ex[c];
        }
        #pragma unroll
        for (int o = 16; o > 0; o >>= 1) sm += __shfl_xor_sync(0xffffffff, sm, o);
        float inv = 1.f / sm;
        #pragma unroll
        for (int c = 0; c < 4; c++) {
            int n = tc * 4 + c;
            if (n < CC) {
                float p = ex[c] * inv;
                g_sm[(size_t)row * CC + n] = p;
                entpart += -p * logf(p + 1e-15f);
            }
        }
    }
    #pragma unroll
    for (int o = 16; o > 0; o >>= 1) entpart += __shfl_xor_sync(0xffffffff, entpart, o);
    if (tc == 0) atomicAdd(&g_acc[2], entpart);
}

// ----------------------------- stage19: poolgram + cross + predg_zero + qp2 GEMM ------------------
// block classes: [0,192) poolgram | [192,6336) cross | [6336,8384) zero | [8384,8576) qp2
__global__ void k_stage19(const float* __restrict__ m2bi, float* __restrict__ out_pred) {
    extern __shared__ float dyn[];      // poolgram staging: S[32][104] + E[32][128]
    __shared__ float shred[256];
    int b = blockIdx.x;
    int t = threadIdx.x;  // 256
    if (b < 192) {            // poolgram
        float* S_s = dyn;                 // [32][104]
        float* E_s = dyn + 32 * 104;      // [32][128]
        int i0 = b * 32;
        for (int idx = t; idx < 32 * CC; idx += 256) {
            int r = idx / CC, c = idx % CC;
            S_s[r * 104 + c] = g_sm[(size_t)(i0 + r) * CC + c];
        }
        for (int idx = t; idx < 32 * DIM; idx += 256) {
            int r = idx >> 7, d = idx & 127;
            E_s[r * 128 + d] = g_emb[(size_t)(i0 + r) * DIM + d];
        }
        __syncthreads();
        for (int o = t; o < CC * 32; o += 256) {
            int c = o >> 5, d4 = o & 31;
            float4 a = make_float4(0.f, 0.f, 0.f, 0.f);
            for (int r = 0; r < 32; r++) {
                float s = S_s[r * 104 + c];
                float4 e4 = *reinterpret_cast<const float4*>(&E_s[r * 128 + d4 * 4]);
                a.x += s * e4.x; a.y += s * e4.y; a.z += s * e4.z; a.w += s * e4.w;
            }
            atomicAdd(&g_pooled[(size_t)c * DIM + d4 * 4 + 0], a.x);
            atomicAdd(&g_pooled[(size_t)c * DIM + d4 * 4 + 1], a.y);
            atomicAdd(&g_pooled[(size_t)c * DIM + d4 * 4 + 2], a.z);
            atomicAdd(&g_pooled[(size_t)c * DIM + d4 * 4 + 3], a.w);
        }
        for (int o = t; o < CC * 25; o += 256) {
            int c1 = o / 25, c2g = o % 25;
            float4 a = make_float4(0.f, 0.f, 0.f, 0.f);
            for (int r = 0; r < 32; r++) {
                float s = S_s[r * 104 + c1];
                float4 s4 = *reinterpret_cast<const float4*>(&S_s[r * 104 + c2g * 4]);
                a.x += s * s4.x; a.y += s * s4.y; a.z += s * s4.z; a.w += s * s4.w;
            }
            atomicAdd(&g_G[c1 * CC + c2g * 4 + 0], a.x);
            atomicAdd(&g_G[c1 * CC + c2g * 4 + 1], a.y);
            atomicAdd(&g_G[c1 * CC + c2g * 4 + 2], a.z);
            atomicAdd(&g_G[c1 * CC + c2g * 4 + 3], a.w);
        }
    } else if (b < 6336) {    // cross: <A,SS^T> via CSR gather + Adense scatter
        int q = b - 192;
        int beg = g_csr_off[q], end = g_csr_off[q + 1];
        float acc = 0.f;
        if (t < CC) {
            float tsum = 0.f;
            for (int j = beg; j < end; j++)
                tsum += g_csr_w[j] * g_sm[(size_t)g_csr_src[j] * CC + t];
            acc = tsum * g_sm[(size_t)q * CC + t];
        }
        float s = blockReduceSum(acc, shred);
        if (t == 0 && s != 0.f) atomicAdd(&g_acc[1], s);
        for (int j = beg + t; j < end; j += 256)
            atomicAdd(&g_Adense[(size_t)g_csr_src[j] * TWO_N + q], g_csr_w[j]);
    } else if (b < 8384) {    // predg zero-fill (flag path)
        if (!g_flag) return;
        float4 z = make_float4(0.f, 0.f, 0.f, 0.f);
        float4* o = reinterpret_cast<float4*>(out_pred);
        size_t total = (size_t)TWO_N * TWO_N / 4;
        for (size_t j = (size_t)(b - 6336) * 256 + t; j < total; j += (size_t)2048 * 256)
            o[j] = z;
    } else {                  // qp2 GEMM (192 blocks)
        sgemm_block(g_emb, g_wt, m2bi, g_qp2, TWO_N, DIM, DIM, DIM, DIM, b - 8384, 0);
    }
}

// ----------------------------- stage20: kvproj + normA (merged) -----------------------------------
__global__ void k_stage20(const float* __restrict__ wi, const float* __restrict__ bi,
                          const int* __restrict__ src, const int* __restrict__ dst) {
    int b = blockIdx.x;
    int t = threadIdx.x;  // 256
    if (b < 200) {
        __shared__ float prow[DIM];
        int c = b >> 1, which = b & 1;
        if (t < 128) prow[t] = g_pooled[(size_t)c * DIM + t];
        __syncthreads();
        if (t >= 128) return;
        const float4* row4 = reinterpret_cast<const float4*>(wi + (size_t)(DIM + which * DIM + t) * DIM);
        float acc = bi[DIM + which * DIM + t];
        #pragma unroll
        for (int k = 0; k < 32; k++) {
            float4 r = row4[k];
            acc += r.x * prow[4 * k] + r.y * prow[4 * k + 1]
                 + r.z * prow[4 * k + 2] + r.w * prow[4 * k + 3];
        }
        (which ? g_vp2 : g_kp2)[(size_t)c * DIM + t] = acc;
    } else {
        __shared__ float sh[256];
        int e = (b - 200) * 256 + t;
        float v = 0.f;
        if (e < EE) {
            float old = atomicExch(&g_Adense[(size_t)src[e] * TWO_N + dst[e]], 0.f);
            v = old * old;
        }
        float s = blockReduceSum(v, sh);
        if (t == 0 && s != 0.f) atomicAdd(&g_acc[0], s);
    }
}

// ----------------------------- stage21: mha2 + gramfin (merged, 128 threads) ----------------------
#define K_LD 129
__global__ void k_stage21(const float* __restrict__ wo, const float* __restrict__ bo,
                          float* __restrict__ out_skill, float* __restrict__ out_loss) {
    extern __shared__ float kp_s[];     // [CC][K_LD]
    int t = threadIdx.x;  // 128
    if (blockIdx.x == 384) {            // gramfin
        __shared__ float sh[128];
        float acc = 0.f;
        for (int i = t; i < CC * CC; i += 128) { float g = g_G[i]; acc += g * g; }
        sh[t] = acc; __syncthreads();
        for (int s = 64; s > 0; s >>= 1) {
            if (t < s) sh[t] += sh[t + s];
            __syncthreads();
        }
        if (t == 0) {
            float n2 = g_acc[0] - 2.f * g_acc[1] + sh[0];
            float link = sqrtf(fmaxf(n2, 0.f)) / ((float)TWO_N * (float)TWO_N);
            out_loss[0] = link + g_acc[2] / (float)TWO_N;
        }
        return;
    }
    __shared__ float qrow[DIM];
    __shared__ float lg[HH][CC];
    __shared__ float o_s[DIM];
    int w = t >> 5, lane = t & 31;
    for (int i = t; i < CC * DIM; i += 128) {
        int j = i >> 7, d = i & 127;
        kp_s[j * K_LD + d] = g_kp2[i];
    }
    __syncthreads();
    int n0 = blockIdx.x * 16;
    for (int q = 0; q < 16; q++) {
        int n = n0 + q;
        qrow[t] = g_qp2[(size_t)n * DIM + t];
        __syncthreads();
        for (int pos = t; pos < HH * CC; pos += 128) {
            int h = pos / CC, j = pos % CC;
            float acc = 0.f;
            #pragma unroll 8
            for (int d = 0; d < HD; d++)
                acc += qrow[h * HD + d] * kp_s[j * K_LD + h * HD + d];
            lg[h][j] = acc * INV_SQRT_HD;
        }
        __syncthreads();
        {
            float mx = -1e30f;
            for (int j = lane; j < CC; j += 32) mx = fmaxf(mx, lg[w][j]);
            #pragma unroll
            for (int o = 16; o > 0; o >>= 1) mx = fmaxf(mx, __shfl_xor_sync(0xffffffff, mx, o));
            float sm = 0.f;
            for (int j = lane; j < CC; j += 32) { float e = expf(lg[w][j] - mx); lg[w][j] = e; sm += e; }
            #pragma unroll
            for (int o = 16; o > 0; o >>= 1) sm += __shfl_xor_sync(0xffffffff, sm, o);
            float inv = 1.f / sm;
            for (int j = lane; j < CC; j += 32) lg[w][j] *= inv;
        }
        __syncthreads();
        {
            float acc = 0.f;
            for (int j = 0; j < CC; j++) acc += lg[w][j] * g_vp2[(size_t)j * DIM + t];
            o_s[t] = acc;
        }
        __syncthreads();
        {
            const float4* row4 = reinterpret_cast<const float4*>(wo + (size_t)t * DIM);
            float acc = bo[t];
            #pragma unroll
            for (int k = 0; k < 32; k++) {
                float4 r = row4[k];
                acc += r.x * o_s[4 * k] + r.y * o_s[4 * k + 1]
                     + r.z * o_s[4 * k + 2] + r.w * o_s[4 * k + 3];
            }
            out_skill[(size_t)n * DIM + t] = 2.f * g_emb[(size_t)n * DIM + t] + acc;
        }
        __syncthreads();
    }
}

// ----------------------------- host launch -----------------------------
extern "C" void kernel_launch(void* const* d_in, const int* in_sizes, int n_in,
                              void* d_out, int out_size) {
    const float* demand = (const float*)d_in[0];
    const float* supply = (const float*)d_in[1];
    const float* skill  = (const float*)d_in[2];
    const int*   eidx   = (const int*)d_in[3];
    const float* eattr  = (const float*)d_in[4];
    const float* w_fuse = (const float*)d_in[5];
    const float* b_fuse = (const float*)d_in[6];
    const float* m1wi   = (const float*)d_in[7];
    const float* m1bi   = (const float*)d_in[8];
    const float* m1wo   = (const float*)d_in[9];
    const float* m1bo   = (const float*)d_in[10];
    const float* m2wi   = (const float*)d_in[11];
    const float* m2bi   = (const float*)d_in[12];
    const float* m2wo   = (const float*)d_in[13];
    const float* m2bo   = (const float*)d_in[14];
    const float* sender = (const float*)d_in[15];
    const float* recv   = (const float*)d_in[16];
    const float* W0     = (const float*)d_in[17];
    const float* b0     = (const float*)d_in[18];
    const float* W1     = (const float*)d_in[19];
    const float* b1     = (const float*)d_in[20];
    const float* Wp     = (const float*)d_in[21];
    const float* bp     = (const float*)d_in[22];
    float* out = (float*)d_out;
    const int* src = eidx;
    const int* dst = eidx + EE;

    // opt-in dynamic smem: stage19 combines ~21.6KB static (sgemm tiles) + 29.7KB dynamic
    cudaFuncSetAttribute(k_stage19, cudaFuncAttributeMaxDynamicSharedMemorySize,
                         (32 * 104 + 32 * 128) * (int)sizeof(float) + 1024);
    cudaFuncSetAttribute(k_stage21, cudaFuncAttributeMaxDynamicSharedMemorySize,
                         CC * K_LD * (int)sizeof(float) + 1024);

    float *p_c, *p_Zcat, *p_zb, *p_cat2, *p_fused;
    cudaGetSymbolAddress((void**)&p_c, g_c);
    cudaGetSymbolAddress((void**)&p_Zcat, g_Zcat);
    cudaGetSymbolAddress((void**)&p_zb, g_zb);
    cudaGetSymbolAddress((void**)&p_cat2, g_cat2);
    cudaGetSymbolAddress((void**)&p_fused, g_fused);

    k_init<<<64, 256>>>(sender, recv);
    k_stage1<<<1201, 256>>>(m1wi, m1wo, m1bo, m1bi, m2wi, demand, supply, dst, eattr);
    k_stage2<<<769, 1024>>>(skill, out + OUT_CAT);
    k_stage3<<<960, 256>>>(src, dst, eattr, m1bi);
    k_ugemm<<<768, 256>>>(m1wi);
    k_attn1<<<TWO_N, 128>>>(demand, supply, m1bi);
    k_sgemm<<<dim3(1, TWO_N / 32), 256>>>(p_c, p_Zcat, p_zb, p_cat2 + DIM, TWO_N, DIM, 4 * DIM, 2 * DIM);
    k_sgemm<<<dim3(1, TWO_N / 32), 256>>>(p_cat2, w_fuse, b_fuse, p_fused, TWO_N, DIM, 2 * DIM, DIM);

    k_stage8<<<3456, 256>>>(sender, recv, W0, W1);
    k_scores<<<1184, 256>>>();
    k_predg_general<<<TWO_N, 256>>>(out + OUT_PRED);
    k_dense_agg<<<TWO_N / 32, 256>>>();
    k_stage12<<<6144, 256>>>(b0, b1);
    k_stage13<<<384, 256>>>(W0, W1);
    k_dense_agg<<<TWO_N / 32, 256>>>();
    k_stage15<<<3072, 256>>>(b0);
    k_stage16<<<3072, 256>>>(b1);

    k_sm_gemm<<<192, 256>>>(Wp, bp);
    k_stage19<<<8576, 256, (32 * 104 + 32 * 128) * sizeof(float)>>>(m2bi, out + OUT_PRED);
    k_stage20<<<968, 256>>>(m2wi, m2bi, src, dst);
    k_stage21<<<385, 128, CC * K_LD * sizeof(float) + 1024>>>(m2wo, m2bo, out + OUT_SKILL, out + OUT_LOSS);
}

// round 13
// speedup vs baseline: 1.6014x; 1.0390x over previous
#include <cuda_runtime.h>
#include <math.h>

#define NN      3072
#define TWO_N   6144
#define DIM     128
#define SEQ     16
#define EE      196608
#define CC      100
#define HH      4
#define HD      32
#define INV_SQRT_HD 0.17677669529663687f
#define DELTA_T 0.1f
#define PRESERVE 0.1f

#define OUT_CAT   0
#define OUT_SKILL (TWO_N * DIM)
#define OUT_PRED  (2 * TWO_N * DIM)
#define OUT_LOSS  (2 * TWO_N * DIM + TWO_N * TWO_N)

// ----------------------------- device scratch -----------------------------
__device__ float g_dsum[DIM];
__device__ float g_ssum[DIM];
__device__ float g_fused[(size_t)TWO_N * DIM];
__device__ float g_s1[(size_t)TWO_N * DIM];
__device__ float g_s2[(size_t)TWO_N * DIM];
__device__ float g_scores[(size_t)TWO_N * TWO_N];   // general path only
__device__ float g_Adense[(size_t)TWO_N * TWO_N];   // zero between launches (exch trick)
__device__ float g_deg[TWO_N];
__device__ float g_degsp[TWO_N];
__device__ float g_xw[(size_t)TWO_N * DIM];     // dense chain
__device__ float g_xw2[(size_t)TWO_N * DIM];    // sparse chain
__device__ float g_agg[(size_t)TWO_N * DIM];
__device__ float g_tmpA[(size_t)TWO_N * DIM];
__device__ float g_tmpB[(size_t)TWO_N * DIM];
__device__ float g_emb[(size_t)TWO_N * DIM];
__device__ float g_sm[(size_t)TWO_N * CC];
__device__ float g_pooled[CC * DIM];
__device__ float g_G[CC * CC];
__device__ float g_kp2[CC * DIM];
__device__ float g_vp2[CC * DIM];
__device__ float g_qp2[(size_t)TWO_N * DIM];
__device__ float g_wt[DIM * DIM];
__device__ float g_acc[8];   // [0]=||A||^2 [1]=<A,SS^T> [2]=ent_sum
__device__ int   g_flag;

// MHA1 chain buffers
__device__ float g_qv[(size_t)TWO_N * DIM];
__device__ float g_U[(size_t)TWO_N * 4 * DIM];         // [2N, 512]
__device__ float g_cq[(size_t)TWO_N * 640];            // [skill(128) | c(512)] per row
__device__ float g_Zcat[4 * DIM * DIM];                // [512, 128]
__device__ float g_zb[DIM];
__device__ float g_Wcomb[DIM * 4 * DIM];               // [128, 512]
__device__ float g_Ub[4 * DIM];                        // [512]
__device__ float g_vqb[DIM * HH];                      // [128][4]
__device__ float g_cb[HH];
__device__ float g_wbig[640 * DIM];                    // [Wf_top(128); Zf(512)] x 128
__device__ float g_fb[DIM];

// CSR for sparse GCN (+ raw weights for link loss)
__device__ int   g_csr_cnt[TWO_N];
__device__ int   g_csr_off[TWO_N + 1];
__device__ int   g_csr_src[EE];
__device__ float g_csr_coef[EE];
__device__ float g_csr_w[EE];

// ----------------------------- helpers -----------------------------
__device__ __forceinline__ float blockReduceSum(float v, float* sh) {
    int t = threadIdx.x;
    sh[t] = v; __syncthreads();
    for (int s = blockDim.x >> 1; s > 0; s >>= 1) {
        if (t < s) sh[t] += sh[t + s];
        __syncthreads();
    }
    float r = sh[0]; __syncthreads();
    return r;
}
__device__ __forceinline__ float blockReduceMax(float v, float* sh) {
    int t = threadIdx.x;
    sh[t] = v; __syncthreads();
    for (int s = blockDim.x >> 1; s > 0; s >>= 1) {
        if (t < s) sh[t] = fmaxf(sh[t], sh[t + s]);
        __syncthreads();
    }
    float r = sh[0]; __syncthreads();
    return r;
}

// ---------------- SGEMM device block-function: 32x128 tile, double-buffered ----------------
__device__ void sgemm_block(const float* __restrict__ A, const float* __restrict__ B,
                            const float* __restrict__ bias, float* __restrict__ Cmat,
                            int M, int Nn, int K, int lda, int ldc, int bmi, int bni) {
    __shared__ float As[2][16][33];
    __shared__ float Bs[2][16][128];
    int bm = bmi * 32;
    int bn = bni * 128;
    int tid = threadIdx.x;
    int tr = tid >> 5, tc = tid & 31;
    float acc[4][4];
    #pragma unroll
    for (int r = 0; r < 4; r++)
        #pragma unroll
        for (int c = 0; c < 4; c++) acc[r][c] = 0.f;

    #pragma unroll
    for (int j = 0; j < 2; j++) {
        int idx = tid + 256 * j;
        int m = idx >> 4, kk = idx & 15;
        As[0][kk][m] = A[(size_t)(bm + m) * lda + kk];
    }
    #pragma unroll
    for (int j = 0; j < 8; j++) {
        int idx = tid + 256 * j;
        int kk = idx >> 7, n = idx & 127;
        Bs[0][kk][n] = (bn + n < Nn) ? B[(size_t)kk * Nn + bn + n] : 0.f;
    }
    __syncthreads();

    int buf = 0;
    for (int k0 = 0; k0 < K; k0 += 16) {
        int nb = buf ^ 1;
        if (k0 + 16 < K) {
            #pragma unroll
            for (int j = 0; j < 2; j++) {
                int idx = tid + 256 * j;
                int m = idx >> 4, kk = idx & 15;
                As[nb][kk][m] = A[(size_t)(bm + m) * lda + k0 + 16 + kk];
            }
            #pragma unroll
            for (int j = 0; j < 8; j++) {
                int idx = tid + 256 * j;
                int kk = idx >> 7, n = idx & 127;
                Bs[nb][kk][n] = (bn + n < Nn) ? B[(size_t)(k0 + 16 + kk) * Nn + bn + n] : 0.f;
            }
        }
        #pragma unroll
        for (int kk = 0; kk < 16; kk++) {
            float a0 = As[buf][kk][tr * 4 + 0];
            float a1 = As[buf][kk][tr * 4 + 1];
            float a2 = As[buf][kk][tr * 4 + 2];
            float a3 = As[buf][kk][tr * 4 + 3];
            float4 b4 = *reinterpret_cast<const float4*>(&Bs[buf][kk][tc * 4]);
            acc[0][0] += a0 * b4.x; acc[0][1] += a0 * b4.y; acc[0][2] += a0 * b4.z; acc[0][3] += a0 * b4.w;
            acc[1][0] += a1 * b4.x; acc[1][1] += a1 * b4.y; acc[1][2] += a1 * b4.z; acc[1][3] += a1 * b4.w;
            acc[2][0] += a2 * b4.x; acc[2][1] += a2 * b4.y; acc[2][2] += a2 * b4.z; acc[2][3] += a2 * b4.w;
            acc[3][0] += a3 * b4.x; acc[3][1] += a3 * b4.y; acc[3][2] += a3 * b4.z; acc[3][3] += a3 * b4.w;
        }
        __syncthreads();
        buf = nb;
    }
    #pragma unroll
    for (int r = 0; r < 4; r++) {
        int m = bm + tr * 4 + r;
        if (m >= M) continue;
        #pragma unroll
        for (int c = 0; c < 4; c++) {
            int n = bn + tc * 4 + c;
            if (n < Nn) {
                float v = acc[r][c];
                if (bias) v += bias[n];
                Cmat[(size_t)m * ldc + n] = v;
            }
        }
    }
}

__global__ void k_sgemm(const float* __restrict__ A, const float* __restrict__ B,
                        const float* __restrict__ bias, float* __restrict__ Cmat,
                        int M, int Nn, int K, int ldc) {
    sgemm_block(A, B, bias, Cmat, M, Nn, K, K, ldc, blockIdx.y, blockIdx.x);
}

// ----------------------------- init -----------------------------
__global__ void k_init(const float* __restrict__ sender, const float* __restrict__ receiver) {
    int i = blockIdx.x * blockDim.x + threadIdx.x;
    if (i < TWO_N) { g_deg[i] = 1.0f; g_degsp[i] = 1.0f; g_csr_cnt[i] = 0; }
    if (i < CC * DIM) g_pooled[i] = 0.f;
    if (i < CC * CC) g_G[i] = 0.f;
    if (i < 2 * DIM) (i < DIM ? g_dsum : g_ssum)[i & 127] = 0.f;
    if (i < 8) g_acc[i] = 0.f;
    if (i == 0) g_flag = (sender[0] == receiver[0]) ? 1 : 0;
}

// ----------------------------- stage1: prep + seqsum + edge1 + predg_zero -------------------------
// [0,256) Zcat | 256 zb | [257,321) m2 transpose | [321,369) seqsum | [369,1137) edge1
// | [1137,1393) Wcomb | 1393 vqb | 1394 Ub+cb | [1395,3443) predg_zero
__global__ void k_stage1(const float* __restrict__ m1wi, const float* __restrict__ m1wo,
                         const float* __restrict__ m1bo, const float* __restrict__ m1bi,
                         const float* __restrict__ m2wi,
                         const float* __restrict__ demand, const float* __restrict__ supply,
                         const int* __restrict__ dst, const float* __restrict__ w,
                         float* __restrict__ out_pred) {
    int b = blockIdx.x;
    int t = threadIdx.x;  // 256
    if (b < 256) {                        // Zcat
        int i = b * 256 + t;
        int row = i >> 7, tt = i & 127;
        int h = row >> 7, d = row & 127;
        const float* wv = m1wi + (size_t)2 * DIM * DIM;
        float acc = 0.f;
        #pragma unroll 8
        for (int j = 0; j < 32; j++)
            acc += m1wo[(size_t)tt * DIM + h * 32 + j] * wv[(size_t)(h * 32 + j) * DIM + d];
        g_Zcat[(size_t)row * DIM + tt] = acc;
    } else if (b == 256) {                // zb
        if (t < DIM) {
            const float* bv = m1bi + 2 * DIM;
            float acc = m1bo[t];
            #pragma unroll 8
            for (int k = 0; k < DIM; k++) acc += m1wo[(size_t)t * DIM + k] * bv[k];
            g_zb[t] = acc;
        }
    } else if (b < 321) {                 // m2wi transpose (64)
        int i = (b - 257) * 256 + t;
        int n = i >> 7, k = i & 127;
        g_wt[(size_t)k * DIM + n] = m2wi[(size_t)n * DIM + k];
    } else if (b < 369) {                 // seqsum (48)
        if (t < DIM) {
            int sb = b - 321;
            int tensor = sb / 24, chunk = sb % 24;
            const float* base = tensor ? supply : demand;
            float acc = 0.f;
            int n0 = chunk * 128;
            for (int n = n0; n < n0 + 128; n++)
                acc += base[(size_t)n * SEQ * DIM + (size_t)(SEQ - 1) * DIM + t];
            atomicAdd(&(tensor ? g_ssum : g_dsum)[t], acc);
        }
    } else if (b < 1137) {                // edge1 (768)
        int e = (b - 369) * 256 + t;
        if (e < EE) {
            int q = dst[e];
            atomicAdd(&g_degsp[q], w[e]);
            atomicAdd(&g_csr_cnt[q], 1);
        }
    } else if (b < 1393) {                // Wcomb (256): [128,512]
        int i = (b - 1137) * 256 + t;
        int k = i >> 9, col = i & 511;
        int h = col >> 7, d = col & 127;
        const float* wk = m1wi + (size_t)DIM * DIM;
        float acc = 0.f;
        #pragma unroll 8
        for (int j = 0; j < 32; j++)
            acc += m1wi[(size_t)(h * 32 + j) * DIM + k] * wk[(size_t)(h * 32 + j) * DIM + d];
        g_Wcomb[(size_t)k * 512 + col] = acc;
    } else if (b == 1393) {               // vqb [128][4]
        for (int i = t; i < DIM * HH; i += 256) {
            int k = i >> 2, h = i & 3;
            const float* bk = m1bi + DIM;
            float acc = 0.f;
            #pragma unroll 8
            for (int j = 0; j < 32; j++)
                acc += m1wi[(size_t)(h * 32 + j) * DIM + k] * bk[h * 32 + j];
            g_vqb[i] = acc;
        }
    } else if (b == 1394) {               // Ub [512] + cb[4]
        const float* wk = m1wi + (size_t)DIM * DIM;
        const float* bk = m1bi + DIM;
        for (int col = t; col < 512; col += 256) {
            int h = col >> 7, d = col & 127;
            float acc = 0.f;
            #pragma unroll 8
            for (int j = 0; j < 32; j++)
                acc += m1bi[h * 32 + j] * wk[(size_t)(h * 32 + j) * DIM + d];
            g_Ub[col] = acc;
        }
        if (t < HH) {
            float acc = 0.f;
            for (int j = 0; j < 32; j++) acc += m1bi[t * 32 + j] * bk[t * 32 + j];
            g_cb[t] = acc;
        }
    } else {                              // predg zero-fill (flag path) (2048)
        if (!g_flag) return;
        float4 z = make_float4(0.f, 0.f, 0.f, 0.f);
        float4* o = reinterpret_cast<float4*>(out_pred);
        size_t total = (size_t)TWO_N * TWO_N / 4;
        for (size_t j = (size_t)(b - 1395) * 256 + t; j < total; j += (size_t)2048 * 256)
            o[j] = z;
    }
}

// ----------------------------- stage2: scan (b0) + qv (merged, 1024 threads) ----------------------
__global__ void k_stage2(const float* __restrict__ skill, float* __restrict__ out_cat) {
    int b = blockIdx.x;
    int t = threadIdx.x;  // 1024
    if (b == 0) {         // scan
        __shared__ int sh[1024];
        int base = t * 6;
        int loc[6];
        int s = 0;
        #pragma unroll
        for (int k = 0; k < 6; k++) { loc[k] = s; s += g_csr_cnt[base + k]; }
        sh[t] = s;
        __syncthreads();
        for (int off = 1; off < 1024; off <<= 1) {
            int add = (t >= off) ? sh[t - off] : 0;
            __syncthreads();
            sh[t] += add;
            __syncthreads();
        }
        int excl = sh[t] - s;
        #pragma unroll
        for (int k = 0; k < 6; k++) {
            int o = excl + loc[k];
            g_csr_off[base + k] = o;
            g_csr_cnt[base + k] = o;
        }
        if (t == 1023) g_csr_off[TWO_N] = sh[1023];
    } else {              // qv + cq skill half + out_cat
        int i = (b - 1) * 1024 + t;
        int bb = i >> 7, tt = i & 127;
        bool dem = bb < NN;
        int idx = dem ? bb : bb - NN;
        float sv = skill[(size_t)idx * DIM + tt];
        g_qv[i] = sv + (dem ? g_dsum : g_ssum)[tt];
        g_cq[(size_t)bb * 640 + tt] = sv;
        out_cat[i] = sv;
    }
}

// ----------------------------- stage3: fillcsr + Wtop + Zf GEMM + fb + U GEMM ---------------------
// [0,768) fillcsr | [768,832) Wtop copy | [832,848) Zf GEMM | 848 fb | [849,1617) U GEMM
__global__ void k_stage3(const int* __restrict__ src, const int* __restrict__ dst,
                         const float* __restrict__ w, const float* __restrict__ w_fuse,
                         const float* __restrict__ b_fuse) {
    int b = blockIdx.x;
    int t = threadIdx.x;  // 256
    if (b < 768) {
        int e = b * 256 + t;
        if (e < EE) {
            int s = src[e], q = dst[e];
            float we = w[e];
            int pos = atomicAdd(&g_csr_cnt[q], 1);
            g_csr_src[pos] = s;
            g_csr_coef[pos] = rsqrtf(g_degsp[s]) * rsqrtf(g_degsp[q]) * we;
            g_csr_w[pos] = we;
        }
    } else if (b < 832) {     // Wtop copy (first 128 rows of w_fuse -> wbig rows 0..127)
        int i = (b - 768) * 256 + t;
        g_wbig[i] = w_fuse[i];
    } else if (b < 848) {     // Zf = Zcat @ Wf_bot -> wbig rows 128..639
        sgemm_block(g_Zcat, w_fuse + (size_t)DIM * DIM, nullptr, g_wbig + (size_t)DIM * DIM,
                    512, DIM, DIM, DIM, DIM, b - 832, 0);
    } else if (b == 848) {    // fb[t] = b_fuse[t] + sum_k zb[k]*Wf_bot[k][t]
        if (t < DIM) {
            float acc = b_fuse[t];
            #pragma unroll 8
            for (int k = 0; k < DIM; k++) acc += g_zb[k] * w_fuse[(size_t)(DIM + k) * DIM + t];
            g_fb[t] = acc;
        }
    } else {                  // U = qv @ Wcomb + Ub   (768 blocks: bni=idx/192, bmi=idx%192)
        int idx = b - 849;
        sgemm_block(g_qv, g_Wcomb, g_Ub, g_U, TWO_N, 4 * DIM, DIM, DIM, 4 * DIM,
                    idx % 192, idx / 192);
    }
}

// ----------------------------- MHA1 attention core (qb from qv; c -> cq) --------------------------
__global__ void k_attn1(const float* __restrict__ demand, const float* __restrict__ supply) {
    int b = blockIdx.x;
    int t = threadIdx.x;  // 128
    int w = t >> 5, lane = t & 31;
    bool dem = b < NN;
    int idx = dem ? b : b - NN;
    const float* seq = (dem ? demand : supply) + (size_t)idx * SEQ * DIM;

    __shared__ float sh_seq[SEQ][DIM + 1];
    __shared__ float sh_U[HH][DIM];
    __shared__ float sh_p[HH][SEQ];

    for (int i = t; i < SEQ * DIM; i += 128) sh_seq[i >> 7][i & 127] = seq[i];
    for (int i = t; i < HH * DIM; i += 128) sh_U[i >> 7][i & 127] = g_U[(size_t)b * 512 + i];
    __syncthreads();

    // qb[h] = sum_k qv[b,k]*vqb[k][h] + cb[h]   (warp w = head w)
    float qb = 0.f;
    #pragma unroll
    for (int m = 0; m < 4; m++) {
        int k = lane + 32 * m;
        qb += g_qv[(size_t)b * DIM + k] * g_vqb[k * HH + w];
    }
    #pragma unroll
    for (int o = 16; o > 0; o >>= 1) qb += __shfl_xor_sync(0xffffffff, qb, o);
    qb += g_cb[w];

    float myl = -1e30f;
    if (lane < SEQ) {
        float acc = 0.f;
        #pragma unroll 16
        for (int d = 0; d < DIM; d++) acc += sh_U[w][d] * sh_seq[lane][d];
        myl = (acc + qb) * INV_SQRT_HD;
    }
    float mx = myl;
    #pragma unroll
    for (int o = 8; o > 0; o >>= 1) mx = fmaxf(mx, __shfl_xor_sync(0xffffffff, mx, o));
    float e = (lane < SEQ) ? expf(myl - mx) : 0.f;
    float sm = e;
    #pragma unroll
    for (int o = 8; o > 0; o >>= 1) sm += __shfl_xor_sync(0xffffffff, sm, o);
    if (lane < SEQ) sh_p[w][lane] = e / sm;
    __syncthreads();

    #pragma unroll
    for (int k = 0; k < 4; k++) {
        int d = lane + 32 * k;
        float acc = 0.f;
        #pragma unroll
        for (int s = 0; s < SEQ; s++) acc += sh_p[w][s] * sh_seq[s][d];
        g_cq[(size_t)b * 640 + 128 + w * DIM + d] = acc;
    }
}

// ----------------------------- stage8: tanhprep + dense-l0 GEMM + sparse-l0 GEMM -------------------
__global__ void k_stage8(const float* __restrict__ sender, const float* __restrict__ receiver,
                         const float* __restrict__ W0, const float* __restrict__ W1) {
    int b = blockIdx.x;
    if (b < 3072) {
        if (g_flag) return;
        int i = b * 256 + threadIdx.x;
        float f = g_fused[i];
        g_s1[i] = tanhf(sender[0] * f);
        g_s2[i] = tanhf(receiver[0] * f);
    } else if (b < 3264) {
        sgemm_block(g_fused, W0, nullptr, g_xw, TWO_N, DIM, DIM, DIM, DIM, b - 3072, 0);
    } else {
        sgemm_block(g_fused, W1, nullptr, g_xw2, TWO_N, DIM, DIM, DIM, DIM, b - 3264, 0);
    }
}

// ----------------------------- scores (general path; grid-stride) -----------------------------
__global__ void k_scores() {
    if (g_flag) return;
    __shared__ float A1[16][DIM], A2[16][DIM], B1[16][DIM], B2[16][DIM];
    int t = threadIdx.x;  // 256
    const int TILES = TWO_N / 16;
    for (int tile = blockIdx.x; tile < TILES * TILES; tile += gridDim.x) {
        int i0 = (tile / TILES) * 16, j0 = (tile % TILES) * 16;
        __syncthreads();
        for (int j = 0; j < 8; j++) {
            int idx = t + 256 * j;
            int r = idx >> 7, c = idx & 127;
            A1[r][c] = g_s1[(size_t)(i0 + r) * DIM + c];
            A2[r][c] = g_s2[(size_t)(i0 + r) * DIM + c];
            B1[r][c] = g_s1[(size_t)(j0 + r) * DIM + c];
            B2[r][c] = g_s2[(size_t)(j0 + r) * DIM + c];
        }
        __syncthreads();
        int ti = t >> 4, tj = t & 15;
        float acc = 0.f;
        for (int k = 0; k < DIM; k++)
            acc += A1[ti][k] * B2[tj][k] - A2[ti][k] * B1[tj][k];
        g_scores[(size_t)(i0 + ti) * TWO_N + j0 + tj] = acc;
    }
}

// ----------------------------- predg general (softmax+threshold+deg) ------------------------------
__global__ void k_predg_general(float* __restrict__ out_pred) {
    if (g_flag) return;
    int row = blockIdx.x;
    int t = threadIdx.x;  // 256
    __shared__ float sh[256];
    float* sr = g_scores + (size_t)row * TWO_N;
    float mx = 0.f;
    for (int i = t; i < TWO_N; i += 256) mx = fmaxf(mx, fmaxf(sr[i], 0.f));
    mx = blockReduceMax(mx, sh);
    float sum = 0.f;
    for (int i = t; i < TWO_N; i += 256) sum += expf(fmaxf(sr[i], 0.f) - mx);
    sum = blockReduceSum(sum, sh);
    float inv = 1.f / sum;
    for (int i = t; i < TWO_N; i += 256) {
        float p = expf(fmaxf(sr[i], 0.f) - mx) * inv;
        float pr = fmaxf(p - DELTA_T, 0.f);
        sr[i] = pr;
        out_pred[(size_t)row * TWO_N + i] = pr;
        if (pr != 0.f) atomicAdd(&g_deg[i], pr);
    }
}

// ----------------------------- dense agg (general path) -----------------------------
__global__ void k_dense_agg() {
    if (g_flag) return;
    int i0 = blockIdx.x * 32;
    int t = threadIdx.x;  // 256
    __shared__ float pcol[32];
    __shared__ float xrow[DIM];
    int dbase = t & 127, half = t >> 7;
    float acc[16];
    #pragma unroll
    for (int r = 0; r < 16; r++) acc[r] = 0.f;
    for (int j = 0; j < TWO_N; j++) {
        if (t < 32) pcol[t] = g_scores[(size_t)j * TWO_N + i0 + t];
        else if (t >= 128 && t < 256) {
            float sj = rsqrtf(g_deg[j]);
            xrow[t - 128] = sj * g_xw[(size_t)j * DIM + (t - 128)];
        }
        __syncthreads();
        #pragma unroll
        for (int r = 0; r < 16; r++) acc[r] += pcol[half + 2 * r] * xrow[dbase];
        __syncthreads();
    }
    #pragma unroll
    for (int r = 0; r < 16; r++) {
        int i = i0 + half + 2 * r;
        float di = rsqrtf(g_deg[i]);
        g_agg[(size_t)i * DIM + dbase] = acc[r] + di * g_xw[(size_t)i * DIM + dbase];
    }
}

// ---------------- device bodies: dense combine / sparse gather ----------------
__device__ __forceinline__ void dense_combine_elem(int i, const float* prev, float* dst,
                                                   const float* b0, int layer) {
    float di = rsqrtf(g_deg[i >> 7]);
    float v = g_flag ? (di * di * g_xw[i]) : (di * g_agg[i]);
    float out = v + b0[layer * DIM + (i & 127)];
    dst[i] = (1.f - PRESERVE) * out + PRESERVE * prev[i];
}
__device__ __forceinline__ void spgather_node(int q, int tt, const float* xw, const float* prev,
                                              float* dstb, const float* b1, int layer, int addA) {
    float dv = rsqrtf(g_degsp[q]);
    float acc = dv * dv * xw[(size_t)q * DIM + tt];
    int beg = g_csr_off[q], end = g_csr_off[q + 1];
    int j = beg;
    for (; j + 1 < end; j += 2) {
        float c0 = g_csr_coef[j], c1 = g_csr_coef[j + 1];
        int   s0 = g_csr_src[j],  s1 = g_csr_src[j + 1];
        acc += c0 * xw[(size_t)s0 * DIM + tt] + c1 * xw[(size_t)s1 * DIM + tt];
    }
    if (j < end) acc += g_csr_coef[j] * xw[(size_t)g_csr_src[j] * DIM + tt];
    float outv = acc + b1[layer * DIM + tt];
    float blend = (1.f - PRESERVE) * outv + PRESERVE * prev[(size_t)q * DIM + tt];
    if (addA) blend += g_tmpA[(size_t)q * DIM + tt];
    dstb[(size_t)q * DIM + tt] = blend;
}

// stage12: dense_combine l0 + spgather l0 (merged)
__global__ void k_stage12(const float* __restrict__ b0, const float* __restrict__ b1) {
    int b = blockIdx.x;
    int t = threadIdx.x;  // 256
    if (b < 3072) {
        dense_combine_elem(b * 256 + t, g_fused, g_tmpA, b0, 0);
    } else {
        int q = (b - 3072) * 2 + (t >> 7);
        spgather_node(q, t & 127, g_xw2, g_fused, g_tmpB, b1, 0, 0);
    }
}

// stage13: dense l1 GEMM + sparse l1 GEMM (merged)
__global__ void k_stage13(const float* __restrict__ W0, const float* __restrict__ W1) {
    int b = blockIdx.x;
    if (b < 192) sgemm_block(g_tmpA, W0 + (size_t)DIM * DIM, nullptr, g_xw, TWO_N, DIM, DIM, DIM, DIM, b, 0);
    else         sgemm_block(g_tmpB, W1 + (size_t)DIM * DIM, nullptr, g_xw2, TWO_N, DIM, DIM, DIM, DIM, b - 192, 0);
}

// stage15: dense_combine l1
__global__ void k_stage15(const float* __restrict__ b0) {
    int i = blockIdx.x * 256 + threadIdx.x;
    if (i < TWO_N * DIM) dense_combine_elem(i, g_tmpA, g_tmpA, b0, 1);
}
// stage16: spgather l1 + add tmpA -> emb
__global__ void k_stage16(const float* __restrict__ b1) {
    int t = threadIdx.x;
    int q = blockIdx.x * 2 + (t >> 7);
    spgather_node(q, t & 127, g_xw2, g_tmpB, g_emb, b1, 1, 1);
}

// ----------------------------- sm GEMM with fused softmax + entropy -------------------------------
__global__ void k_sm_gemm(const float* __restrict__ Wp, const float* __restrict__ bp) {
    __shared__ float As[2][16][33];
    __shared__ float Bs[2][16][128];
    int bm = blockIdx.x * 32;
    int tid = threadIdx.x;
    int tr = tid >> 5, tc = tid & 31;
    float acc[4][4];
    #pragma unroll
    for (int r = 0; r < 4; r++)
        #pragma unroll
        for (int c = 0; c < 4; c++) acc[r][c] = 0.f;

    #pragma unroll
    for (int j = 0; j < 2; j++) {
        int idx = tid + 256 * j;
        int m = idx >> 4, kk = idx & 15;
        As[0][kk][m] = g_emb[(size_t)(bm + m) * DIM + kk];
    }
    #pragma unroll
    for (int j = 0; j < 8; j++) {
        int idx = tid + 256 * j;
        int kk = idx >> 7, n = idx & 127;
        Bs[0][kk][n] = (n < CC) ? Wp[(size_t)kk * CC + n] : 0.f;
    }
    __syncthreads();
    int buf = 0;
    for (int k0 = 0; k0 < DIM; k0 += 16) {
        int nb = buf ^ 1;
        if (k0 + 16 < DIM) {
            #pragma unroll
            for (int j = 0; j < 2; j++) {
                int idx = tid + 256 * j;
                int m = idx >> 4, kk = idx & 15;
                As[nb][kk][m] = g_emb[(size_t)(bm + m) * DIM + k0 + 16 + kk];
            }
            #pragma unroll
            for (int j = 0; j < 8; j++) {
                int idx = tid + 256 * j;
                int kk = idx >> 7, n = idx & 127;
                Bs[nb][kk][n] = (n < CC) ? Wp[(size_t)(k0 + 16 + kk) * CC + n] : 0.f;
            }
        }
        #pragma unroll
        for (int kk = 0; kk < 16; kk++) {
            float a0 = As[buf][kk][tr * 4 + 0];
            float a1 = As[buf][kk][tr * 4 + 1];
            float a2 = As[buf][kk][tr * 4 + 2];
            float a3 = As[buf][kk][tr * 4 + 3];
            float4 b4 = *reinterpret_cast<const float4*>(&Bs[buf][kk][tc * 4]);
            acc[0][0] += a0 * b4.x; acc[0][1] += a0 * b4.y; acc[0][2] += a0 * b4.z; acc[0][3] += a0 * b4.w;
            acc[1][0] += a1 * b4.x; acc[1][1] += a1 * b4.y; acc[1][2] += a1 * b4.z; acc[1][3] += a1 * b4.w;
            acc[2][0] += a2 * b4.x; acc[2][1] += a2 * b4.y; acc[2][2] += a2 * b4.z; acc[2][3] += a2 * b4.w;
            acc[3][0] += a3 * b4.x; acc[3][1] += a3 * b4.y; acc[3][2] += a3 * b4.z; acc[3][3] += a3 * b4.w;
        }
        __syncthreads();
        buf = nb;
    }
    float entpart = 0.f;
    #pragma unroll
    for (int r = 0; r < 4; r++) {
        int row = bm + tr * 4 + r;
        float v[4];
        float mx = -1e30f;
        #pragma unroll
        for (int c = 0; c < 4; c++) {
            int n = tc * 4 + c;
            v[c] = (n < CC) ? (acc[r][c] + bp[n]) : -1e30f;
            mx = fmaxf(mx, v[c]);
        }
        #pragma unroll
        for (int o = 16; o > 0; o >>= 1) mx = fmaxf(mx, __shfl_xor_sync(0xffffffff, mx, o));
        float sm = 0.f;
        float ex[4];
        #pragma unroll
        for (int c = 0; c < 4; c++) {
            int n = tc * 4 + c;
            ex[c] = (n < CC) ? expf(v[c] - mx) : 0.f;
            sm += ex[c];
        }
        #pragma unroll
        for (int o = 16; o > 0; o >>= 1) sm += __shfl_xor_sync(0xffffffff, sm, o);
        float inv = 1.f / sm;
        #pragma unroll
        for (int c = 0; c < 4; c++) {
            int n = tc * 4 + c;
            if (n < CC) {
                float p = ex[c] * inv;
                g_sm[(size_t)row * CC + n] = p;
                entpart += -p * logf(p + 1e-15f);
            }
        }
    }
    #pragma unroll
    for (int o = 16; o > 0; o >>= 1) entpart += __shfl_xor_sync(0xffffffff, entpart, o);
    if (tc == 0) atomicAdd(&g_acc[2], entpart);
}

// ----------------------------- stage19: poolgram + cross + qp2 GEMM -------------------------------
// [0,192) poolgram | [192,6336) cross | [6336,6528) qp2
__global__ void k_stage19(const float* __restrict__ m2bi) {
    extern __shared__ float dyn[];      // poolgram staging: S[32][104] + E[32][128]
    __shared__ float shred[256];
    int b = blockIdx.x;
    int t = threadIdx.x;  // 256
    if (b < 192) {            // poolgram
        float* S_s = dyn;                 // [32][104]
        float* E_s = dyn + 32 * 104;      // [32][128]
        int i0 = b * 32;
        for (int idx = t; idx < 32 * CC; idx += 256) {
            int r = idx / CC, c = idx % CC;
            S_s[r * 104 + c] = g_sm[(size_t)(i0 + r) * CC + c];
        }
        for (int idx = t; idx < 32 * DIM; idx += 256) {
            int r = idx >> 7, d = idx & 127;
            E_s[r * 128 + d] = g_emb[(size_t)(i0 + r) * DIM + d];
        }
        __syncthreads();
        for (int o = t; o < CC * 32; o += 256) {
            int c = o >> 5, d4 = o & 31;
            float4 a = make_float4(0.f, 0.f, 0.f, 0.f);
            for (int r = 0; r < 32; r++) {
                float s = S_s[r * 104 + c];
                float4 e4 = *reinterpret_cast<const float4*>(&E_s[r * 128 + d4 * 4]);
                a.x += s * e4.x; a.y += s * e4.y; a.z += s * e4.z; a.w += s * e4.w;
            }
            atomicAdd(&g_pooled[(size_t)c * DIM + d4 * 4 + 0], a.x);
            atomicAdd(&g_pooled[(size_t)c * DIM + d4 * 4 + 1], a.y);
            atomicAdd(&g_pooled[(size_t)c * DIM + d4 * 4 + 2], a.z);
            atomicAdd(&g_pooled[(size_t)c * DIM + d4 * 4 + 3], a.w);
        }
        for (int o = t; o < CC * 25; o += 256) {
            int c1 = o / 25, c2g = o % 25;
            float4 a = make_float4(0.f, 0.f, 0.f, 0.f);
            for (int r = 0; r < 32; r++) {
                float s = S_s[r * 104 + c1];
                float4 s4 = *reinterpret_cast<const float4*>(&S_s[r * 104 + c2g * 4]);
                a.x += s * s4.x; a.y += s * s4.y; a.z += s * s4.z; a.w += s * s4.w;
            }
            atomicAdd(&g_G[c1 * CC + c2g * 4 + 0], a.x);
            atomicAdd(&g_G[c1 * CC + c2g * 4 + 1], a.y);
            atomicAdd(&g_G[c1 * CC + c2g * 4 + 2], a.z);
            atomicAdd(&g_G[c1 * CC + c2g * 4 + 3], a.w);
        }
    } else if (b < 6336) {    // cross: <A,SS^T> via CSR gather + Adense scatter
        int q = b - 192;
        int beg = g_csr_off[q], end = g_csr_off[q + 1];
        float acc = 0.f;
        if (t < CC) {
            float tsum = 0.f;
            for (int j = beg; j < end; j++)
                tsum += g_csr_w[j] * g_sm[(size_t)g_csr_src[j] * CC + t];
            acc = tsum * g_sm[(size_t)q * CC + t];
        }
        float s = blockReduceSum(acc, shred);
        if (t == 0 && s != 0.f) atomicAdd(&g_acc[1], s);
        for (int j = beg + t; j < end; j += 256)
            atomicAdd(&g_Adense[(size_t)g_csr_src[j] * TWO_N + q], g_csr_w[j]);
    } else {                  // qp2 GEMM (192 blocks)
        sgemm_block(g_emb, g_wt, m2bi, g_qp2, TWO_N, DIM, DIM, DIM, DIM, b - 6336, 0);
    }
}

// ----------------------------- stage20: kvproj + normA (merged) -----------------------------------
__global__ void k_stage20(const float* __restrict__ wi, const float* __restrict__ bi,
                          const int* __restrict__ src, const int* __restrict__ dst) {
    int b = blockIdx.x;
    int t = threadIdx.x;  // 256
    if (b < 200) {
        __shared__ float prow[DIM];
        int c = b >> 1, which = b & 1;
        if (t < 128) prow[t] = g_pooled[(size_t)c * DIM + t];
        __syncthreads();
        if (t >= 128) return;
        const float4* row4 = reinterpret_cast<const float4*>(wi + (size_t)(DIM + which * DIM + t) * DIM);
        float acc = bi[DIM + which * DIM + t];
        #pragma unroll
        for (int k = 0; k < 32; k++) {
            float4 r = row4[k];
            acc += r.x * prow[4 * k] + r.y * prow[4 * k + 1]
                 + r.z * prow[4 * k + 2] + r.w * prow[4 * k + 3];
        }
        (which ? g_vp2 : g_kp2)[(size_t)c * DIM + t] = acc;
    } else {
        __shared__ float sh[256];
        int e = (b - 200) * 256 + t;
        float v = 0.f;
        if (e < EE) {
            float old = atomicExch(&g_Adense[(size_t)src[e] * TWO_N + dst[e]], 0.f);
            v = old * old;
        }
        float s = blockReduceSum(v, sh);
        if (t == 0 && s != 0.f) atomicAdd(&g_acc[0], s);
    }
}

// ----------------------------- stage21: mha2 + gramfin (merged, 128 threads) ----------------------
#define K_LD 129
__global__ void k_stage21(const float* __restrict__ wo, const float* __restrict__ bo,
                          float* __restrict__ out_skill, float* __restrict__ out_loss) {
    extern __shared__ float kp_s[];     // [CC][K_LD]
    int t = threadIdx.x;  // 128
    if (blockIdx.x == 384) {            // gramfin
        __shared__ float sh[128];
        float acc = 0.f;
        for (int i = t; i < CC * CC; i += 128) { float g = g_G[i]; acc += g * g; }
        sh[t] = acc; __syncthreads();
        for (int s = 64; s > 0; s >>= 1) {
            if (t < s) sh[t] += sh[t + s];
            __syncthreads();
        }
        if (t == 0) {
            float n2 = g_acc[0] - 2.f * g_acc[1] + sh[0];
            float link = sqrtf(fmaxf(n2, 0.f)) / ((float)TWO_N * (float)TWO_N);
            out_loss[0] = link + g_acc[2] / (float)TWO_N;
        }
        return;
    }
    __shared__ float qrow[DIM];
    __shared__ float lg[HH][CC];
    __shared__ float o_s[DIM];
    int w = t >> 5, lane = t & 31;
    for (int i = t; i < CC * DIM; i += 128) {
        int j = i >> 7, d = i & 127;
        kp_s[j * K_LD + d] = g_kp2[i];
    }
    __syncthreads();
    int n0 = blockIdx.x * 16;
    for (int q = 0; q < 16; q++) {
        int n = n0 + q;
        qrow[t] = g_qp2[(size_t)n * DIM + t];
        __syncthreads();
        for (int pos = t; pos < HH * CC; pos += 128) {
            int h = pos / CC, j = pos % CC;
            float acc = 0.f;
            #pragma unroll 8
            for (int d = 0; d < HD; d++)
                acc += qrow[h * HD + d] * kp_s[j * K_LD + h * HD + d];
            lg[h][j] = acc * INV_SQRT_HD;
        }
        __syncthreads();
        {
            float mx = -1e30f;
            for (int j = lane; j < CC; j += 32) mx = fmaxf(mx, lg[w][j]);
            #pragma unroll
            for (int o = 16; o > 0; o >>= 1) mx = fmaxf(mx, __shfl_xor_sync(0xffffffff, mx, o));
            float sm = 0.f;
            for (int j = lane; j < CC; j += 32) { float e = expf(lg[w][j] - mx); lg[w][j] = e; sm += e; }
            #pragma unroll
            for (int o = 16; o > 0; o >>= 1) sm += __shfl_xor_sync(0xffffffff, sm, o);
            float inv = 1.f / sm;
            for (int j = lane; j < CC; j += 32) lg[w][j] *= inv;
        }
        __syncthreads();
        {
            float acc = 0.f;
            for (int j = 0; j < CC; j++) acc += lg[w][j] * g_vp2[(size_t)j * DIM + t];
            o_s[t] = acc;
        }
        __syncthreads();
        {
            const float4* row4 = reinterpret_cast<const float4*>(wo + (size_t)t * DIM);
            float acc = bo[t];
            #pragma unroll
            for (int k = 0; k < 32; k++) {
                float4 r = row4[k];
                acc += r.x * o_s[4 * k] + r.y * o_s[4 * k + 1]
                     + r.z * o_s[4 * k + 2] + r.w * o_s[4 * k + 3];
            }
            out_skill[(size_t)n * DIM + t] = 2.f * g_emb[(size_t)n * DIM + t] + acc;
        }
        __syncthreads();
    }
}

// ----------------------------- host launch -----------------------------
extern "C" void kernel_launch(void* const* d_in, const int* in_sizes, int n_in,
                              void* d_out, int out_size) {
    const float* demand = (const float*)d_in[0];
    const float* supply = (const float*)d_in[1];
    const float* skill  = (const float*)d_in[2];
    const int*   eidx   = (const int*)d_in[3];
    const float* eattr  = (const float*)d_in[4];
    const float* w_fuse = (const float*)d_in[5];
    const float* b_fuse = (const float*)d_in[6];
    const float* m1wi   = (const float*)d_in[7];
    const float* m1bi   = (const float*)d_in[8];
    const float* m1wo   = (const float*)d_in[9];
    const float* m1bo   = (const float*)d_in[10];
    const float* m2wi   = (const float*)d_in[11];
    const float* m2bi   = (const float*)d_in[12];
    const float* m2wo   = (const float*)d_in[13];
    const float* m2bo   = (const float*)d_in[14];
    const float* sender = (const float*)d_in[15];
    const float* recv   = (const float*)d_in[16];
    const float* W0     = (const float*)d_in[17];
    const float* b0     = (const float*)d_in[18];
    const float* W1     = (const float*)d_in[19];
    const float* b1     = (const float*)d_in[20];
    const float* Wp     = (const float*)d_in[21];
    const float* bp     = (const float*)d_in[22];
    float* out = (float*)d_out;
    const int* src = eidx;
    const int* dst = eidx + EE;

    cudaFuncSetAttribute(k_stage19, cudaFuncAttributeMaxDynamicSharedMemorySize,
                         (32 * 104 + 32 * 128) * (int)sizeof(float) + 1024);
    cudaFuncSetAttribute(k_stage21, cudaFuncAttributeMaxDynamicSharedMemorySize,
                         CC * K_LD * (int)sizeof(float) + 1024);

    float *p_cq, *p_wbig, *p_fb, *p_fused;
    cudaGetSymbolAddress((void**)&p_cq, g_cq);
    cudaGetSymbolAddress((void**)&p_wbig, g_wbig);
    cudaGetSymbolAddress((void**)&p_fb, g_fb);
    cudaGetSymbolAddress((void**)&p_fused, g_fused);

    k_init<<<64, 256>>>(sender, recv);
    k_stage1<<<3443, 256>>>(m1wi, m1wo, m1bo, m1bi, m2wi, demand, supply, dst, eattr,
                            out + OUT_PRED);
    k_stage2<<<769, 1024>>>(skill, out + OUT_CAT);
    k_stage3<<<1617, 256>>>(src, dst, eattr, w_fuse, b_fuse);
    k_attn1<<<TWO_N, 128>>>(demand, supply);
    k_sgemm<<<dim3(1, TWO_N / 32), 256>>>(p_cq, p_wbig, p_fb, p_fused, TWO_N, DIM, 640, DIM);

    k_stage8<<<3456, 256>>>(sender, recv, W0, W1);
    k_scores<<<1184, 256>>>();
    k_predg_general<<<TWO_N, 256>>>(out + OUT_PRED);
    k_dense_agg<<<TWO_N / 32, 256>>>();
    k_stage12<<<6144, 256>>>(b0, b1);
    k_stage13<<<384, 256>>>(W0, W1);
    k_dense_agg<<<TWO_N / 32, 256>>>();
    k_stage15<<<3072, 256>>>(b0);
    k_stage16<<<3072, 256>>>(b1);

    k_sm_gemm<<<192, 256>>>(Wp, bp);
    k_stage19<<<6528, 256, (32 * 104 + 32 * 128) * sizeof(float)>>>(m2bi);
    k_stage20<<<968, 256>>>(m2wi, m2bi, src, dst);
    k_stage21<<<385, 128, CC * K_LD * sizeof(float) + 1024>>>(m2wo, m2bo, out + OUT_SKILL, out + OUT_LOSS);
}

// round 14
// speedup vs baseline: 1.7009x; 1.0621x over previous
#include <cuda_runtime.h>
#include <math.h>

#define NN      3072
#define TWO_N   6144
#define DIM     128
#define SEQ     16
#define EE      196608
#define CC      100
#define HH      4
#define HD      32
#define INV_SQRT_HD 0.17677669529663687f
#define DELTA_T 0.1f
#define PRESERVE 0.1f

#define OUT_CAT   0
#define OUT_SKILL (TWO_N * DIM)
#define OUT_PRED  (2 * TWO_N * DIM)
#define OUT_LOSS  (2 * TWO_N * DIM + TWO_N * TWO_N)

// ----------------------------- device scratch -----------------------------
__device__ float g_dsum[DIM];
__device__ float g_ssum[DIM];
__device__ float g_fused[(size_t)TWO_N * DIM];
__device__ float g_s1[(size_t)TWO_N * DIM];
__device__ float g_s2[(size_t)TWO_N * DIM];
__device__ float g_scores[(size_t)TWO_N * TWO_N];   // general path only
__device__ float g_Adense[(size_t)TWO_N * TWO_N];   // zero between launches (exch trick)
__device__ float g_deg[TWO_N];
__device__ float g_degsp[TWO_N];
__device__ float g_xw[(size_t)TWO_N * DIM];     // dense chain
__device__ float g_xw2[(size_t)TWO_N * DIM];    // sparse chain
__device__ float g_agg[(size_t)TWO_N * DIM];
__device__ float g_tmpA[(size_t)TWO_N * DIM];
__device__ float g_tmpB[(size_t)TWO_N * DIM];
__device__ float g_emb[(size_t)TWO_N * DIM];
__device__ float g_sm[(size_t)TWO_N * CC];
__device__ float g_pooled[CC * DIM];
__device__ float g_G[CC * CC];
__device__ float g_kp2[CC * DIM];
__device__ float g_vp2[CC * DIM];
__device__ float g_qp2[(size_t)TWO_N * DIM];
__device__ float g_wt[DIM * DIM];
__device__ float g_acc[8];   // [0]=||A||^2 [1]=<A,SS^T> [2]=ent_sum
__device__ int   g_flag;

// MHA1 chain buffers
__device__ float g_qv[(size_t)TWO_N * DIM];
__device__ float g_U[(size_t)TWO_N * 4 * DIM];         // [2N, 512]
__device__ float g_cq[(size_t)TWO_N * 640];            // [skill(128) | c(512)] per row
__device__ float g_Zcat[4 * DIM * DIM];                // [512, 128]
__device__ float g_zb[DIM];
__device__ float g_Wcomb[DIM * 4 * DIM];               // [128, 512]
__device__ float g_Ub[4 * DIM];                        // [512]
__device__ float g_vqb[DIM * HH];                      // [128][4]
__device__ float g_cb[HH];
__device__ float g_wbig[640 * DIM];                    // [Wf_top(128); Zf(512)] x 128
__device__ float g_fb[DIM];

// CSR for sparse GCN (+ raw weights for link loss)
__device__ int   g_csr_cnt[TWO_N];
__device__ int   g_csr_off[TWO_N + 1];
__device__ int   g_csr_src[EE];
__device__ float g_csr_coef[EE];
__device__ float g_csr_w[EE];

// ----------------------------- helpers -----------------------------
__device__ __forceinline__ float blockReduceSum(float v, float* sh) {
    int t = threadIdx.x;
    sh[t] = v; __syncthreads();
    for (int s = blockDim.x >> 1; s > 0; s >>= 1) {
        if (t < s) sh[t] += sh[t + s];
        __syncthreads();
    }
    float r = sh[0]; __syncthreads();
    return r;
}
__device__ __forceinline__ float blockReduceMax(float v, float* sh) {
    int t = threadIdx.x;
    sh[t] = v; __syncthreads();
    for (int s = blockDim.x >> 1; s > 0; s >>= 1) {
        if (t < s) sh[t] = fmaxf(sh[t], sh[t + s]);
        __syncthreads();
    }
    float r = sh[0]; __syncthreads();
    return r;
}

// ---------------- SGEMM device block-function: 32x128 tile, double-buffered ----------------
__device__ void sgemm_block(const float* __restrict__ A, const float* __restrict__ B,
                            const float* __restrict__ bias, float* __restrict__ Cmat,
                            int M, int Nn, int K, int lda, int ldc, int bmi, int bni) {
    __shared__ float As[2][16][33];
    __shared__ float Bs[2][16][128];
    int bm = bmi * 32;
    int bn = bni * 128;
    int tid = threadIdx.x;
    int tr = tid >> 5, tc = tid & 31;
    float acc[4][4];
    #pragma unroll
    for (int r = 0; r < 4; r++)
        #pragma unroll
        for (int c = 0; c < 4; c++) acc[r][c] = 0.f;

    #pragma unroll
    for (int j = 0; j < 2; j++) {
        int idx = tid + 256 * j;
        int m = idx >> 4, kk = idx & 15;
        As[0][kk][m] = A[(size_t)(bm + m) * lda + kk];
    }
    #pragma unroll
    for (int j = 0; j < 8; j++) {
        int idx = tid + 256 * j;
        int kk = idx >> 7, n = idx & 127;
        Bs[0][kk][n] = (bn + n < Nn) ? B[(size_t)kk * Nn + bn + n] : 0.f;
    }
    __syncthreads();

    int buf = 0;
    for (int k0 = 0; k0 < K; k0 += 16) {
        int nb = buf ^ 1;
        if (k0 + 16 < K) {
            #pragma unroll
            for (int j = 0; j < 2; j++) {
                int idx = tid + 256 * j;
                int m = idx >> 4, kk = idx & 15;
                As[nb][kk][m] = A[(size_t)(bm + m) * lda + k0 + 16 + kk];
            }
            #pragma unroll
            for (int j = 0; j < 8; j++) {
                int idx = tid + 256 * j;
                int kk = idx >> 7, n = idx & 127;
                Bs[nb][kk][n] = (bn + n < Nn) ? B[(size_t)(k0 + 16 + kk) * Nn + bn + n] : 0.f;
            }
        }
        #pragma unroll
        for (int kk = 0; kk < 16; kk++) {
            float a0 = As[buf][kk][tr * 4 + 0];
            float a1 = As[buf][kk][tr * 4 + 1];
            float a2 = As[buf][kk][tr * 4 + 2];
            float a3 = As[buf][kk][tr * 4 + 3];
            float4 b4 = *reinterpret_cast<const float4*>(&Bs[buf][kk][tc * 4]);
            acc[0][0] += a0 * b4.x; acc[0][1] += a0 * b4.y; acc[0][2] += a0 * b4.z; acc[0][3] += a0 * b4.w;
            acc[1][0] += a1 * b4.x; acc[1][1] += a1 * b4.y; acc[1][2] += a1 * b4.z; acc[1][3] += a1 * b4.w;
            acc[2][0] += a2 * b4.x; acc[2][1] += a2 * b4.y; acc[2][2] += a2 * b4.z; acc[2][3] += a2 * b4.w;
            acc[3][0] += a3 * b4.x; acc[3][1] += a3 * b4.y; acc[3][2] += a3 * b4.z; acc[3][3] += a3 * b4.w;
        }
        __syncthreads();
        buf = nb;
    }
    #pragma unroll
    for (int r = 0; r < 4; r++) {
        int m = bm + tr * 4 + r;
        if (m >= M) continue;
        #pragma unroll
        for (int c = 0; c < 4; c++) {
            int n = bn + tc * 4 + c;
            if (n < Nn) {
                float v = acc[r][c];
                if (bias) v += bias[n];
                Cmat[(size_t)m * ldc + n] = v;
            }
        }
    }
}

__global__ void k_sgemm(const float* __restrict__ A, const float* __restrict__ B,
                        const float* __restrict__ bias, float* __restrict__ Cmat,
                        int M, int Nn, int K, int ldc) {
    sgemm_block(A, B, bias, Cmat, M, Nn, K, K, ldc, blockIdx.y, blockIdx.x);
}

// ----------------------------- init -----------------------------
__global__ void k_init(const float* __restrict__ sender, const float* __restrict__ receiver) {
    int i = blockIdx.x * blockDim.x + threadIdx.x;
    if (i < TWO_N) { g_deg[i] = 1.0f; g_degsp[i] = 1.0f; g_csr_cnt[i] = 0; }
    if (i < CC * DIM) g_pooled[i] = 0.f;
    if (i < CC * CC) g_G[i] = 0.f;
    if (i < 2 * DIM) (i < DIM ? g_dsum : g_ssum)[i & 127] = 0.f;
    if (i < 8) g_acc[i] = 0.f;
    if (i == 0) g_flag = (sender[0] == receiver[0]) ? 1 : 0;
}

// ----------------------------- stage1: prep + seqsum + edge1 + predg_zero -------------------------
__global__ void k_stage1(const float* __restrict__ m1wi, const float* __restrict__ m1wo,
                         const float* __restrict__ m1bo, const float* __restrict__ m1bi,
                         const float* __restrict__ m2wi,
                         const float* __restrict__ demand, const float* __restrict__ supply,
                         const int* __restrict__ dst, const float* __restrict__ w,
                         float* __restrict__ out_pred) {
    int b = blockIdx.x;
    int t = threadIdx.x;  // 256
    if (b < 256) {                        // Zcat
        int i = b * 256 + t;
        int row = i >> 7, tt = i & 127;
        int h = row >> 7, d = row & 127;
        const float* wv = m1wi + (size_t)2 * DIM * DIM;
        float acc = 0.f;
        #pragma unroll 8
        for (int j = 0; j < 32; j++)
            acc += m1wo[(size_t)tt * DIM + h * 32 + j] * wv[(size_t)(h * 32 + j) * DIM + d];
        g_Zcat[(size_t)row * DIM + tt] = acc;
    } else if (b == 256) {                // zb
        if (t < DIM) {
            const float* bv = m1bi + 2 * DIM;
            float acc = m1bo[t];
            #pragma unroll 8
            for (int k = 0; k < DIM; k++) acc += m1wo[(size_t)t * DIM + k] * bv[k];
            g_zb[t] = acc;
        }
    } else if (b < 321) {                 // m2wi transpose (64)
        int i = (b - 257) * 256 + t;
        int n = i >> 7, k = i & 127;
        g_wt[(size_t)k * DIM + n] = m2wi[(size_t)n * DIM + k];
    } else if (b < 369) {                 // seqsum (48)
        if (t < DIM) {
            int sb = b - 321;
            int tensor = sb / 24, chunk = sb % 24;
            const float* base = tensor ? supply : demand;
            float acc = 0.f;
            int n0 = chunk * 128;
            for (int n = n0; n < n0 + 128; n++)
                acc += base[(size_t)n * SEQ * DIM + (size_t)(SEQ - 1) * DIM + t];
            atomicAdd(&(tensor ? g_ssum : g_dsum)[t], acc);
        }
    } else if (b < 1137) {                // edge1 (768)
        int e = (b - 369) * 256 + t;
        if (e < EE) {
            int q = dst[e];
            atomicAdd(&g_degsp[q], w[e]);
            atomicAdd(&g_csr_cnt[q], 1);
        }
    } else if (b < 1393) {                // Wcomb (256): [128,512]
        int i = (b - 1137) * 256 + t;
        int k = i >> 9, col = i & 511;
        int h = col >> 7, d = col & 127;
        const float* wk = m1wi + (size_t)DIM * DIM;
        float acc = 0.f;
        #pragma unroll 8
        for (int j = 0; j < 32; j++)
            acc += m1wi[(size_t)(h * 32 + j) * DIM + k] * wk[(size_t)(h * 32 + j) * DIM + d];
        g_Wcomb[(size_t)k * 512 + col] = acc;
    } else if (b == 1393) {               // vqb [128][4]
        for (int i = t; i < DIM * HH; i += 256) {
            int k = i >> 2, h = i & 3;
            const float* bk = m1bi + DIM;
            float acc = 0.f;
            #pragma unroll 8
            for (int j = 0; j < 32; j++)
                acc += m1wi[(size_t)(h * 32 + j) * DIM + k] * bk[h * 32 + j];
            g_vqb[i] = acc;
        }
    } else if (b == 1394) {               // Ub [512] + cb[4]
        const float* wk = m1wi + (size_t)DIM * DIM;
        const float* bk = m1bi + DIM;
        for (int col = t; col < 512; col += 256) {
            int h = col >> 7, d = col & 127;
            float acc = 0.f;
            #pragma unroll 8
            for (int j = 0; j < 32; j++)
                acc += m1bi[h * 32 + j] * wk[(size_t)(h * 32 + j) * DIM + d];
            g_Ub[col] = acc;
        }
        if (t < HH) {
            float acc = 0.f;
            for (int j = 0; j < 32; j++) acc += m1bi[t * 32 + j] * bk[t * 32 + j];
            g_cb[t] = acc;
        }
    } else {                              // predg zero-fill (flag path) (2048)
        if (!g_flag) return;
        float4 z = make_float4(0.f, 0.f, 0.f, 0.f);
        float4* o = reinterpret_cast<float4*>(out_pred);
        size_t total = (size_t)TWO_N * TWO_N / 4;
        for (size_t j = (size_t)(b - 1395) * 256 + t; j < total; j += (size_t)2048 * 256)
            o[j] = z;
    }
}

// ----------------------------- stage2: scan (b0) + qv (merged, 1024 threads) ----------------------
__global__ void k_stage2(const float* __restrict__ skill, float* __restrict__ out_cat) {
    int b = blockIdx.x;
    int t = threadIdx.x;  // 1024
    if (b == 0) {         // scan
        __shared__ int sh[1024];
        int base = t * 6;
        int loc[6];
        int s = 0;
        #pragma unroll
        for (int k = 0; k < 6; k++) { loc[k] = s; s += g_csr_cnt[base + k]; }
        sh[t] = s;
        __syncthreads();
        for (int off = 1; off < 1024; off <<= 1) {
            int add = (t >= off) ? sh[t - off] : 0;
            __syncthreads();
            sh[t] += add;
            __syncthreads();
        }
        int excl = sh[t] - s;
        #pragma unroll
        for (int k = 0; k < 6; k++) {
            int o = excl + loc[k];
            g_csr_off[base + k] = o;
            g_csr_cnt[base + k] = o;
        }
        if (t == 1023) g_csr_off[TWO_N] = sh[1023];
    } else {              // qv + cq skill half + out_cat
        int i = (b - 1) * 1024 + t;
        int bb = i >> 7, tt = i & 127;
        bool dem = bb < NN;
        int idx = dem ? bb : bb - NN;
        float sv = skill[(size_t)idx * DIM + tt];
        g_qv[i] = sv + (dem ? g_dsum : g_ssum)[tt];
        g_cq[(size_t)bb * 640 + tt] = sv;
        out_cat[i] = sv;
    }
}

// ----------------------------- stage3: Wtop + Zf GEMM + fb + U GEMM -------------------------------
// [0,64) Wtop copy | [64,80) Zf GEMM | 80 fb | [81,849) U GEMM
__global__ void k_stage3(const float* __restrict__ w_fuse, const float* __restrict__ b_fuse) {
    int b = blockIdx.x;
    int t = threadIdx.x;  // 256
    if (b < 64) {             // Wtop copy
        int i = b * 256 + t;
        g_wbig[i] = w_fuse[i];
    } else if (b < 80) {      // Zf = Zcat @ Wf_bot -> wbig rows 128..639
        sgemm_block(g_Zcat, w_fuse + (size_t)DIM * DIM, nullptr, g_wbig + (size_t)DIM * DIM,
                    512, DIM, DIM, DIM, DIM, b - 64, 0);
    } else if (b == 80) {     // fb
        if (t < DIM) {
            float acc = b_fuse[t];
            #pragma unroll 8
            for (int k = 0; k < DIM; k++) acc += g_zb[k] * w_fuse[(size_t)(DIM + k) * DIM + t];
            g_fb[t] = acc;
        }
    } else {                  // U = qv @ Wcomb + Ub (768 blocks)
        int idx = b - 81;
        sgemm_block(g_qv, g_Wcomb, g_Ub, g_U, TWO_N, 4 * DIM, DIM, DIM, 4 * DIM,
                    idx % 192, idx / 192);
    }
}

// ----------------------------- attn1 + fillcsr (merged, 128 threads) ------------------------------
// [0, TWO_N) attention | [TWO_N, TWO_N+1536) fillcsr (128 edges/block)
__global__ void k_attn1(const float* __restrict__ demand, const float* __restrict__ supply,
                        const int* __restrict__ src, const int* __restrict__ dst,
                        const float* __restrict__ w) {
    int b = blockIdx.x;
    int t = threadIdx.x;  // 128
    if (b >= TWO_N) {     // fillcsr
        int e = (b - TWO_N) * 128 + t;
        if (e < EE) {
            int s = src[e], q = dst[e];
            float we = w[e];
            int pos = atomicAdd(&g_csr_cnt[q], 1);
            g_csr_src[pos] = s;
            g_csr_coef[pos] = rsqrtf(g_degsp[s]) * rsqrtf(g_degsp[q]) * we;
            g_csr_w[pos] = we;
        }
        return;
    }
    int wd = t >> 5, lane = t & 31;
    bool dem = b < NN;
    int idx = dem ? b : b - NN;
    const float* seq = (dem ? demand : supply) + (size_t)idx * SEQ * DIM;

    __shared__ float sh_seq[SEQ][DIM + 1];
    __shared__ float sh_U[HH][DIM];
    __shared__ float sh_p[HH][SEQ];

    for (int i = t; i < SEQ * DIM; i += 128) sh_seq[i >> 7][i & 127] = seq[i];
    for (int i = t; i < HH * DIM; i += 128) sh_U[i >> 7][i & 127] = g_U[(size_t)b * 512 + i];
    __syncthreads();

    float qb = 0.f;
    #pragma unroll
    for (int m = 0; m < 4; m++) {
        int k = lane + 32 * m;
        qb += g_qv[(size_t)b * DIM + k] * g_vqb[k * HH + wd];
    }
    #pragma unroll
    for (int o = 16; o > 0; o >>= 1) qb += __shfl_xor_sync(0xffffffff, qb, o);
    qb += g_cb[wd];

    float myl = -1e30f;
    if (lane < SEQ) {
        float acc = 0.f;
        #pragma unroll 16
        for (int d = 0; d < DIM; d++) acc += sh_U[wd][d] * sh_seq[lane][d];
        myl = (acc + qb) * INV_SQRT_HD;
    }
    float mx = myl;
    #pragma unroll
    for (int o = 8; o > 0; o >>= 1) mx = fmaxf(mx, __shfl_xor_sync(0xffffffff, mx, o));
    float e = (lane < SEQ) ? expf(myl - mx) : 0.f;
    float sm = e;
    #pragma unroll
    for (int o = 8; o > 0; o >>= 1) sm += __shfl_xor_sync(0xffffffff, sm, o);
    if (lane < SEQ) sh_p[wd][lane] = e / sm;
    __syncthreads();

    #pragma unroll
    for (int k = 0; k < 4; k++) {
        int d = lane + 32 * k;
        float acc = 0.f;
        #pragma unroll
        for (int s = 0; s < SEQ; s++) acc += sh_p[wd][s] * sh_seq[s][d];
        g_cq[(size_t)b * 640 + 128 + wd * DIM + d] = acc;
    }
}

// ----------------------------- stage8: tanhprep + dense-l0 GEMM + sparse-l0 GEMM -------------------
__global__ void k_stage8(const float* __restrict__ sender, const float* __restrict__ receiver,
                         const float* __restrict__ W0, const float* __restrict__ W1) {
    int b = blockIdx.x;
    if (b < 3072) {
        if (g_flag) return;
        int i = b * 256 + threadIdx.x;
        float f = g_fused[i];
        g_s1[i] = tanhf(sender[0] * f);
        g_s2[i] = tanhf(receiver[0] * f);
    } else if (b < 3264) {
        sgemm_block(g_fused, W0, nullptr, g_xw, TWO_N, DIM, DIM, DIM, DIM, b - 3072, 0);
    } else {
        sgemm_block(g_fused, W1, nullptr, g_xw2, TWO_N, DIM, DIM, DIM, DIM, b - 3264, 0);
    }
}

// ----------------------------- scores (general path; grid-stride) -----------------------------
__global__ void k_scores() {
    if (g_flag) return;
    __shared__ float A1[16][DIM], A2[16][DIM], B1[16][DIM], B2[16][DIM];
    int t = threadIdx.x;  // 256
    const int TILES = TWO_N / 16;
    for (int tile = blockIdx.x; tile < TILES * TILES; tile += gridDim.x) {
        int i0 = (tile / TILES) * 16, j0 = (tile % TILES) * 16;
        __syncthreads();
        for (int j = 0; j < 8; j++) {
            int idx = t + 256 * j;
            int r = idx >> 7, c = idx & 127;
            A1[r][c] = g_s1[(size_t)(i0 + r) * DIM + c];
            A2[r][c] = g_s2[(size_t)(i0 + r) * DIM + c];
            B1[r][c] = g_s1[(size_t)(j0 + r) * DIM + c];
            B2[r][c] = g_s2[(size_t)(j0 + r) * DIM + c];
        }
        __syncthreads();
        int ti = t >> 4, tj = t & 15;
        float acc = 0.f;
        for (int k = 0; k < DIM; k++)
            acc += A1[ti][k] * B2[tj][k] - A2[ti][k] * B1[tj][k];
        g_scores[(size_t)(i0 + ti) * TWO_N + j0 + tj] = acc;
    }
}

// ----------------------------- predg general (softmax+threshold+deg) ------------------------------
__global__ void k_predg_general(float* __restrict__ out_pred) {
    if (g_flag) return;
    int row = blockIdx.x;
    int t = threadIdx.x;  // 256
    __shared__ float sh[256];
    float* sr = g_scores + (size_t)row * TWO_N;
    float mx = 0.f;
    for (int i = t; i < TWO_N; i += 256) mx = fmaxf(mx, fmaxf(sr[i], 0.f));
    mx = blockReduceMax(mx, sh);
    float sum = 0.f;
    for (int i = t; i < TWO_N; i += 256) sum += expf(fmaxf(sr[i], 0.f) - mx);
    sum = blockReduceSum(sum, sh);
    float inv = 1.f / sum;
    for (int i = t; i < TWO_N; i += 256) {
        float p = expf(fmaxf(sr[i], 0.f) - mx) * inv;
        float pr = fmaxf(p - DELTA_T, 0.f);
        sr[i] = pr;
        out_pred[(size_t)row * TWO_N + i] = pr;
        if (pr != 0.f) atomicAdd(&g_deg[i], pr);
    }
}

// ----------------------------- dense agg (general path) -----------------------------
__global__ void k_dense_agg() {
    if (g_flag) return;
    int i0 = blockIdx.x * 32;
    int t = threadIdx.x;  // 256
    __shared__ float pcol[32];
    __shared__ float xrow[DIM];
    int dbase = t & 127, half = t >> 7;
    float acc[16];
    #pragma unroll
    for (int r = 0; r < 16; r++) acc[r] = 0.f;
    for (int j = 0; j < TWO_N; j++) {
        if (t < 32) pcol[t] = g_scores[(size_t)j * TWO_N + i0 + t];
        else if (t >= 128 && t < 256) {
            float sj = rsqrtf(g_deg[j]);
            xrow[t - 128] = sj * g_xw[(size_t)j * DIM + (t - 128)];
        }
        __syncthreads();
        #pragma unroll
        for (int r = 0; r < 16; r++) acc[r] += pcol[half + 2 * r] * xrow[dbase];
        __syncthreads();
    }
    #pragma unroll
    for (int r = 0; r < 16; r++) {
        int i = i0 + half + 2 * r;
        float di = rsqrtf(g_deg[i]);
        g_agg[(size_t)i * DIM + dbase] = acc[r] + di * g_xw[(size_t)i * DIM + dbase];
    }
}

// ---------------- device bodies: dense combine / sparse gather ----------------
__device__ __forceinline__ float dense_combine_val(int i, const float* prev,
                                                   const float* b0, int layer) {
    float di = rsqrtf(g_deg[i >> 7]);
    float v = g_flag ? (di * di * g_xw[i]) : (di * g_agg[i]);
    float out = v + b0[layer * DIM + (i & 127)];
    return (1.f - PRESERVE) * out + PRESERVE * prev[i];
}
__device__ __forceinline__ float spgather_val(int q, int tt, const float* xw, const float* prev,
                                              const float* b1, int layer) {
    float dv = rsqrtf(g_degsp[q]);
    float acc = dv * dv * xw[(size_t)q * DIM + tt];
    int beg = g_csr_off[q], end = g_csr_off[q + 1];
    int j = beg;
    for (; j + 1 < end; j += 2) {
        float c0 = g_csr_coef[j], c1 = g_csr_coef[j + 1];
        int   s0 = g_csr_src[j],  s1 = g_csr_src[j + 1];
        acc += c0 * xw[(size_t)s0 * DIM + tt] + c1 * xw[(size_t)s1 * DIM + tt];
    }
    if (j < end) acc += g_csr_coef[j] * xw[(size_t)g_csr_src[j] * DIM + tt];
    float outv = acc + b1[layer * DIM + tt];
    return (1.f - PRESERVE) * outv + PRESERVE * prev[(size_t)q * DIM + tt];
}

// stage12: dense_combine l0 + spgather l0 (merged)
__global__ void k_stage12(const float* __restrict__ b0, const float* __restrict__ b1) {
    int b = blockIdx.x;
    int t = threadIdx.x;  // 256
    if (b < 3072) {
        int i = b * 256 + t;
        g_tmpA[i] = dense_combine_val(i, g_fused, b0, 0);
    } else {
        int q = (b - 3072) * 2 + (t >> 7);
        int tt = t & 127;
        g_tmpB[(size_t)q * DIM + tt] = spgather_val(q, tt, g_xw2, g_fused, b1, 0);
    }
}

// stage13: dense l1 GEMM + sparse l1 GEMM (merged)
__global__ void k_stage13(const float* __restrict__ W0, const float* __restrict__ W1) {
    int b = blockIdx.x;
    if (b < 192) sgemm_block(g_tmpA, W0 + (size_t)DIM * DIM, nullptr, g_xw, TWO_N, DIM, DIM, DIM, DIM, b, 0);
    else         sgemm_block(g_tmpB, W1 + (size_t)DIM * DIM, nullptr, g_xw2, TWO_N, DIM, DIM, DIM, DIM, b - 192, 0);
}

// stage16: fused dense_combine l1 + spgather l1 -> emb (one pass)
__global__ void k_stage16(const float* __restrict__ b0, const float* __restrict__ b1) {
    int t = threadIdx.x;  // 256
    int q = blockIdx.x * 2 + (t >> 7);
    int tt = t & 127;
    int i = q * DIM + tt;
    float dense = dense_combine_val(i, g_tmpA, b0, 1);
    float sp = spgather_val(q, tt, g_xw2, g_tmpB, b1, 1);
    g_emb[i] = dense + sp;
}

// ----------------------------- sm GEMM with fused softmax + entropy -------------------------------
__global__ void k_sm_gemm(const float* __restrict__ Wp, const float* __restrict__ bp) {
    __shared__ float As[2][16][33];
    __shared__ float Bs[2][16][128];
    int bm = blockIdx.x * 32;
    int tid = threadIdx.x;
    int tr = tid >> 5, tc = tid & 31;
    float acc[4][4];
    #pragma unroll
    for (int r = 0; r < 4; r++)
        #pragma unroll
        for (int c = 0; c < 4; c++) acc[r][c] = 0.f;

    #pragma unroll
    for (int j = 0; j < 2; j++) {
        int idx = tid + 256 * j;
        int m = idx >> 4, kk = idx & 15;
        As[0][kk][m] = g_emb[(size_t)(bm + m) * DIM + kk];
    }
    #pragma unroll
    for (int j = 0; j < 8; j++) {
        int idx = tid + 256 * j;
        int kk = idx >> 7, n = idx & 127;
        Bs[0][kk][n] = (n < CC) ? Wp[(size_t)kk * CC + n] : 0.f;
    }
    __syncthreads();
    int buf = 0;
    for (int k0 = 0; k0 < DIM; k0 += 16) {
        int nb = buf ^ 1;
        if (k0 + 16 < DIM) {
            #pragma unroll
            for (int j = 0; j < 2; j++) {
                int idx = tid + 256 * j;
                int m = idx >> 4, kk = idx & 15;
                As[nb][kk][m] = g_emb[(size_t)(bm + m) * DIM + k0 + 16 + kk];
            }
            #pragma unroll
            for (int j = 0; j < 8; j++) {
                int idx = tid + 256 * j;
                int kk = idx >> 7, n = idx & 127;
                Bs[nb][kk][n] = (n < CC) ? Wp[(size_t)(k0 + 16 + kk) * CC + n] : 0.f;
            }
        }
        #pragma unroll
        for (int kk = 0; kk < 16; kk++) {
            float a0 = As[buf][kk][tr * 4 + 0];
            float a1 = As[buf][kk][tr * 4 + 1];
            float a2 = As[buf][kk][tr * 4 + 2];
            float a3 = As[buf][kk][tr * 4 + 3];
            float4 b4 = *reinterpret_cast<const float4*>(&Bs[buf][kk][tc * 4]);
            acc[0][0] += a0 * b4.x; acc[0][1] += a0 * b4.y; acc[0][2] += a0 * b4.z; acc[0][3] += a0 * b4.w;
            acc[1][0] += a1 * b4.x; acc[1][1] += a1 * b4.y; acc[1][2] += a1 * b4.z; acc[1][3] += a1 * b4.w;
            acc[2][0] += a2 * b4.x; acc[2][1] += a2 * b4.y; acc[2][2] += a2 * b4.z; acc[2][3] += a2 * b4.w;
            acc[3][0] += a3 * b4.x; acc[3][1] += a3 * b4.y; acc[3][2] += a3 * b4.z; acc[3][3] += a3 * b4.w;
        }
        __syncthreads();
        buf = nb;
    }
    float entpart = 0.f;
    #pragma unroll
    for (int r = 0; r < 4; r++) {
        int row = bm + tr * 4 + r;
        float v[4];
        float mx = -1e30f;
        #pragma unroll
        for (int c = 0; c < 4; c++) {
            int n = tc * 4 + c;
            v[c] = (n < CC) ? (acc[r][c] + bp[n]) : -1e30f;
            mx = fmaxf(mx, v[c]);
        }
        #pragma unroll
        for (int o = 16; o > 0; o >>= 1) mx = fmaxf(mx, __shfl_xor_sync(0xffffffff, mx, o));
        float sm = 0.f;
        float ex[4];
        #pragma unroll
        for (int c = 0; c < 4; c++) {
            int n = tc * 4 + c;
            ex[c] = (n < CC) ? expf(v[c] - mx) : 0.f;
            sm += ex[c];
        }
        #pragma unroll
        for (int o = 16; o > 0; o >>= 1) sm += __shfl_xor_sync(0xffffffff, sm, o);
        float inv = 1.f / sm;
        #pragma unroll
        for (int c = 0; c < 4; c++) {
            int n = tc * 4 + c;
            if (n < CC) {
                float p = ex[c] * inv;
                g_sm[(size_t)row * CC + n] = p;
                entpart += -p * logf(p + 1e-15f);
            }
        }
    }
    #pragma unroll
    for (int o = 16; o > 0; o >>= 1) entpart += __shfl_xor_sync(0xffffffff, entpart, o);
    if (tc == 0) atomicAdd(&g_acc[2], entpart);
}

// ----------------------------- stage19: poolgram + cross + qp2 GEMM -------------------------------
// [0,192) poolgram | [192,6336) cross | [6336,6528) qp2
__global__ void k_stage19(const float* __restrict__ m2bi) {
    extern __shared__ float dyn[];      // poolgram staging: S[32][104] + E[32][128]
    __shared__ float shred[256];
    int b = blockIdx.x;
    int t = threadIdx.x;  // 256
    if (b < 192) {            // poolgram
        float* S_s = dyn;
        float* E_s = dyn + 32 * 104;
        int i0 = b * 32;
        for (int idx = t; idx < 32 * CC; idx += 256) {
            int r = idx / CC, c = idx % CC;
            S_s[r * 104 + c] = g_sm[(size_t)(i0 + r) * CC + c];
        }
        for (int idx = t; idx < 32 * DIM; idx += 256) {
            int r = idx >> 7, d = idx & 127;
            E_s[r * 128 + d] = g_emb[(size_t)(i0 + r) * DIM + d];
        }
        __syncthreads();
        for (int o = t; o < CC * 32; o += 256) {
            int c = o >> 5, d4 = o & 31;
            float4 a = make_float4(0.f, 0.f, 0.f, 0.f);
            for (int r = 0; r < 32; r++) {
                float s = S_s[r * 104 + c];
                float4 e4 = *reinterpret_cast<const float4*>(&E_s[r * 128 + d4 * 4]);
                a.x += s * e4.x; a.y += s * e4.y; a.z += s * e4.z; a.w += s * e4.w;
            }
            atomicAdd(&g_pooled[(size_t)c * DIM + d4 * 4 + 0], a.x);
            atomicAdd(&g_pooled[(size_t)c * DIM + d4 * 4 + 1], a.y);
            atomicAdd(&g_pooled[(size_t)c * DIM + d4 * 4 + 2], a.z);
            atomicAdd(&g_pooled[(size_t)c * DIM + d4 * 4 + 3], a.w);
        }
        for (int o = t; o < CC * 25; o += 256) {
            int c1 = o / 25, c2g = o % 25;
            float4 a = make_float4(0.f, 0.f, 0.f, 0.f);
            for (int r = 0; r < 32; r++) {
                float s = S_s[r * 104 + c1];
                float4 s4 = *reinterpret_cast<const float4*>(&S_s[r * 104 + c2g * 4]);
                a.x += s * s4.x; a.y += s * s4.y; a.z += s * s4.z; a.w += s * s4.w;
            }
            atomicAdd(&g_G[c1 * CC + c2g * 4 + 0], a.x);
            atomicAdd(&g_G[c1 * CC + c2g * 4 + 1], a.y);
            atomicAdd(&g_G[c1 * CC + c2g * 4 + 2], a.z);
            atomicAdd(&g_G[c1 * CC + c2g * 4 + 3], a.w);
        }
    } else if (b < 6336) {    // cross: <A,SS^T> via CSR gather + Adense scatter
        int q = b - 192;
        int beg = g_csr_off[q], end = g_csr_off[q + 1];
        float acc = 0.f;
        if (t < CC) {
            float tsum = 0.f;
            for (int j = beg; j < end; j++)
                tsum += g_csr_w[j] * g_sm[(size_t)g_csr_src[j] * CC + t];
            acc = tsum * g_sm[(size_t)q * CC + t];
        }
        float s = blockReduceSum(acc, shred);
        if (t == 0 && s != 0.f) atomicAdd(&g_acc[1], s);
        for (int j = beg + t; j < end; j += 256)
            atomicAdd(&g_Adense[(size_t)g_csr_src[j] * TWO_N + q], g_csr_w[j]);
    } else {                  // qp2 GEMM (192 blocks)
        sgemm_block(g_emb, g_wt, m2bi, g_qp2, TWO_N, DIM, DIM, DIM, DIM, b - 6336, 0);
    }
}

// ----------------------------- stage20: kvproj + normA (merged) -----------------------------------
__global__ void k_stage20(const float* __restrict__ wi, const float* __restrict__ bi,
                          const int* __restrict__ src, const int* __restrict__ dst) {
    int b = blockIdx.x;
    int t = threadIdx.x;  // 256
    if (b < 200) {
        __shared__ float prow[DIM];
        int c = b >> 1, which = b & 1;
        if (t < 128) prow[t] = g_pooled[(size_t)c * DIM + t];
        __syncthreads();
        if (t >= 128) return;
        const float4* row4 = reinterpret_cast<const float4*>(wi + (size_t)(DIM + which * DIM + t) * DIM);
        float acc = bi[DIM + which * DIM + t];
        #pragma unroll
        for (int k = 0; k < 32; k++) {
            float4 r = row4[k];
            acc += r.x * prow[4 * k] + r.y * prow[4 * k + 1]
                 + r.z * prow[4 * k + 2] + r.w * prow[4 * k + 3];
        }
        (which ? g_vp2 : g_kp2)[(size_t)c * DIM + t] = acc;
    } else {
        __shared__ float sh[256];
        int e = (b - 200) * 256 + t;
        float v = 0.f;
        if (e < EE) {
            float old = atomicExch(&g_Adense[(size_t)src[e] * TWO_N + dst[e]], 0.f);
            v = old * old;
        }
        float s = blockReduceSum(v, sh);
        if (t == 0 && s != 0.f) atomicAdd(&g_acc[0], s);
    }
}

// ----------------------------- stage21: mha2 (2 queries/iter, 256 thr) + gramfin ------------------
#define K_LD 129
__global__ void k_stage21(const float* __restrict__ wo, const float* __restrict__ bo,
                          float* __restrict__ out_skill, float* __restrict__ out_loss) {
    extern __shared__ float kp_s[];     // [CC][K_LD]
    int t = threadIdx.x;  // 256
    if (blockIdx.x == 384) {            // gramfin
        __shared__ float sh[256];
        float acc = 0.f;
        for (int i = t; i < CC * CC; i += 256) { float g = g_G[i]; acc += g * g; }
        float s = blockReduceSum(acc, sh);
        if (t == 0) {
            float n2 = g_acc[0] - 2.f * g_acc[1] + s;
            float link = sqrtf(fmaxf(n2, 0.f)) / ((float)TWO_N * (float)TWO_N);
            out_loss[0] = link + g_acc[2] / (float)TWO_N;
        }
        return;
    }
    __shared__ float qrow[2][DIM];
    __shared__ float lg[2][HH][CC];
    __shared__ float o_s[2][DIM];
    int g = t >> 7;            // query group 0/1
    int tg = t & 127;
    int w = tg >> 5, lane = tg & 31;
    for (int i = t; i < CC * DIM; i += 256) {
        int j = i >> 7, d = i & 127;
        kp_s[j * K_LD + d] = g_kp2[i];
    }
    __syncthreads();
    int n0 = blockIdx.x * 16;
    for (int q = 0; q < 16; q += 2) {
        int n = n0 + q + g;
        qrow[g][tg] = g_qp2[(size_t)n * DIM + tg];
        __syncthreads();
        for (int pos = tg; pos < HH * CC; pos += 128) {
            int h = pos / CC, j = pos % CC;
            float acc = 0.f;
            #pragma unroll 8
            for (int d = 0; d < HD; d++)
                acc += qrow[g][h * HD + d] * kp_s[j * K_LD + h * HD + d];
            lg[g][h][j] = acc * INV_SQRT_HD;
        }
        __syncthreads();
        {
            float mx = -1e30f;
            for (int j = lane; j < CC; j += 32) mx = fmaxf(mx, lg[g][w][j]);
            #pragma unroll
            for (int o = 16; o > 0; o >>= 1) mx = fmaxf(mx, __shfl_xor_sync(0xffffffff, mx, o));
            float sm = 0.f;
            for (int j = lane; j < CC; j += 32) { float e = expf(lg[g][w][j] - mx); lg[g][w][j] = e; sm += e; }
            #pragma unroll
            for (int o = 16; o > 0; o >>= 1) sm += __shfl_xor_sync(0xffffffff, sm, o);
            float inv = 1.f / sm;
            for (int j = lane; j < CC; j += 32) lg[g][w][j] *= inv;
        }
        __syncthreads();
        {
            float acc = 0.f;
            for (int j = 0; j < CC; j++) acc += lg[g][w][j] * g_vp2[(size_t)j * DIM + tg];
            o_s[g][tg] = acc;
        }
        __syncthreads();
        {
            const float4* row4 = reinterpret_cast<const float4*>(wo + (size_t)tg * DIM);
            float acc = bo[tg];
            #pragma unroll
            for (int k = 0; k < 32; k++) {
                float4 r = row4[k];
                acc += r.x * o_s[g][4 * k] + r.y * o_s[g][4 * k + 1]
                     + r.z * o_s[g][4 * k + 2] + r.w * o_s[g][4 * k + 3];
            }
            out_skill[(size_t)n * DIM + tg] = 2.f * g_emb[(size_t)n * DIM + tg] + acc;
        }
        __syncthreads();
    }
}

// ----------------------------- host launch -----------------------------
extern "C" void kernel_launch(void* const* d_in, const int* in_sizes, int n_in,
                              void* d_out, int out_size) {
    const float* demand = (const float*)d_in[0];
    const float* supply = (const float*)d_in[1];
    const float* skill  = (const float*)d_in[2];
    const int*   eidx   = (const int*)d_in[3];
    const float* eattr  = (const float*)d_in[4];
    const float* w_fuse = (const float*)d_in[5];
    const float* b_fuse = (const float*)d_in[6];
    const float* m1wi   = (const float*)d_in[7];
    const float* m1bi   = (const float*)d_in[8];
    const float* m1wo   = (const float*)d_in[9];
    const float* m1bo   = (const float*)d_in[10];
    const float* m2wi   = (const float*)d_in[11];
    const float* m2bi   = (const float*)d_in[12];
    const float* m2wo   = (const float*)d_in[13];
    const float* m2bo   = (const float*)d_in[14];
    const float* sender = (const float*)d_in[15];
    const float* recv   = (const float*)d_in[16];
    const float* W0     = (const float*)d_in[17];
    const float* b0     = (const float*)d_in[18];
    const float* W1     = (const float*)d_in[19];
    const float* b1     = (const float*)d_in[20];
    const float* Wp     = (const float*)d_in[21];
    const float* bp     = (const float*)d_in[22];
    float* out = (float*)d_out;
    const int* src = eidx;
    const int* dst = eidx + EE;

    cudaFuncSetAttribute(k_stage19, cudaFuncAttributeMaxDynamicSharedMemorySize,
                         (32 * 104 + 32 * 128) * (int)sizeof(float) + 1024);
    cudaFuncSetAttribute(k_stage21, cudaFuncAttributeMaxDynamicSharedMemorySize,
                         CC * K_LD * (int)sizeof(float) + 2048);

    float *p_cq, *p_wbig, *p_fb, *p_fused;
    cudaGetSymbolAddress((void**)&p_cq, g_cq);
    cudaGetSymbolAddress((void**)&p_wbig, g_wbig);
    cudaGetSymbolAddress((void**)&p_fb, g_fb);
    cudaGetSymbolAddress((void**)&p_fused, g_fused);

    k_init<<<64, 256>>>(sender, recv);
    k_stage1<<<3443, 256>>>(m1wi, m1wo, m1bo, m1bi, m2wi, demand, supply, dst, eattr,
                            out + OUT_PRED);
    k_stage2<<<769, 1024>>>(skill, out + OUT_CAT);
    k_stage3<<<849, 256>>>(w_fuse, b_fuse);
    k_attn1<<<TWO_N + 1536, 128>>>(demand, supply, src, dst, eattr);
    k_sgemm<<<dim3(1, TWO_N / 32), 256>>>(p_cq, p_wbig, p_fb, p_fused, TWO_N, DIM, 640, DIM);

    k_stage8<<<3456, 256>>>(sender, recv, W0, W1);
    k_scores<<<1184, 256>>>();
    k_predg_general<<<TWO_N, 256>>>(out + OUT_PRED);
    k_dense_agg<<<TWO_N / 32, 256>>>();
    k_stage12<<<6144, 256>>>(b0, b1);
    k_stage13<<<384, 256>>>(W0, W1);
    k_dense_agg<<<TWO_N / 32, 256>>>();
    k_stage16<<<3072, 256>>>(b0, b1);

    k_sm_gemm<<<192, 256>>>(Wp, bp);
    k_stage19<<<6528, 256, (32 * 104 + 32 * 128) * sizeof(float)>>>(m2bi);
    k_stage20<<<968, 256>>>(m2wi, m2bi, src, dst);
    k_stage21<<<385, 256, CC * K_LD * sizeof(float) + 2048>>>(m2wo, m2bo, out + OUT_SKILL, out + OUT_LOSS);
}

// round 15
// speedup vs baseline: 1.7237x; 1.0134x over previous
#include <cuda_runtime.h>
#include <math.h>

#define NN      3072
#define TWO_N   6144
#define DIM     128
#define SEQ     16
#define EE      196608
#define CC      100
#define HH      4
#define HD      32
#define INV_SQRT_HD 0.17677669529663687f
#define DELTA_T 0.1f
#define PRESERVE 0.1f

#define OUT_CAT   0
#define OUT_SKILL (TWO_N * DIM)
#define OUT_PRED  (2 * TWO_N * DIM)
#define OUT_LOSS  (2 * TWO_N * DIM + TWO_N * TWO_N)

// ----------------------------- device scratch -----------------------------
__device__ float g_dsum[DIM];
__device__ float g_ssum[DIM];
__device__ float g_fused[(size_t)TWO_N * DIM];
__device__ float g_s1[(size_t)TWO_N * DIM];
__device__ float g_s2[(size_t)TWO_N * DIM];
__device__ float g_scores[(size_t)TWO_N * TWO_N];   // general path only
__device__ float g_Adense[(size_t)TWO_N * TWO_N];   // zero between launches (exch trick)
__device__ float g_deg[TWO_N];
__device__ float g_degsp[TWO_N];
__device__ float g_xw[(size_t)TWO_N * DIM];     // dense chain
__device__ float g_xw2[(size_t)TWO_N * DIM];    // sparse chain
__device__ float g_agg[(size_t)TWO_N * DIM];
__device__ float g_tmpA[(size_t)TWO_N * DIM];
__device__ float g_tmpB[(size_t)TWO_N * DIM];
__device__ float g_emb[(size_t)TWO_N * DIM];
__device__ float g_sm[(size_t)TWO_N * CC];
__device__ float g_pooled[CC * DIM];
__device__ float g_G[CC * CC];
__device__ float g_kp2[CC * DIM];
__device__ float g_vp2[CC * DIM];
__device__ float g_qp2[(size_t)TWO_N * DIM];
__device__ float g_wt[DIM * DIM];
__device__ float g_acc[8];   // [0]=||A||^2 [1]=<A,SS^T> [2]=ent_sum
__device__ int   g_flag;

// MHA1 chain buffers
__device__ float g_qv[(size_t)TWO_N * DIM];
__device__ float g_U[(size_t)TWO_N * 4 * DIM];         // [2N, 512]
__device__ float g_cq[(size_t)TWO_N * 640];            // [skill(128) | c(512)] per row
__device__ float g_Zcat[4 * DIM * DIM];                // [512, 128]
__device__ float g_zb[DIM];
__device__ float g_Wcomb[DIM * 4 * DIM];               // [128, 512]
__device__ float g_Ub[4 * DIM];                        // [512]
__device__ float g_vqb[DIM * HH];                      // [128][4]
__device__ float g_cb[HH];
__device__ float g_wbig[640 * DIM];                    // [Wf_top(128); Zf(512)] x 128
__device__ float g_fb[DIM];

// CSR for sparse GCN (+ raw weights for link loss)
__device__ int   g_csr_cnt[TWO_N];
__device__ int   g_csr_off[TWO_N + 1];
__device__ int   g_csr_src[EE];
__device__ float g_csr_coef[EE];
__device__ float g_csr_w[EE];

// ----------------------------- helpers -----------------------------
__device__ __forceinline__ float blockReduceSum(float v, float* sh) {
    int t = threadIdx.x;
    sh[t] = v; __syncthreads();
    for (int s = blockDim.x >> 1; s > 0; s >>= 1) {
        if (t < s) sh[t] += sh[t + s];
        __syncthreads();
    }
    float r = sh[0]; __syncthreads();
    return r;
}
__device__ __forceinline__ float blockReduceMax(float v, float* sh) {
    int t = threadIdx.x;
    sh[t] = v; __syncthreads();
    for (int s = blockDim.x >> 1; s > 0; s >>= 1) {
        if (t < s) sh[t] = fmaxf(sh[t], sh[t + s]);
        __syncthreads();
    }
    float r = sh[0]; __syncthreads();
    return r;
}

// ---------------- SGEMM device block-function: 64x128 tile, 8x4/thread, double-buffered ----------
__device__ void sgemm_block(const float* __restrict__ A, const float* __restrict__ B,
                            const float* __restrict__ bias, float* __restrict__ Cmat,
                            int M, int Nn, int K, int lda, int ldc, int bmi, int bni) {
    __shared__ float As[2][16][65];
    __shared__ float Bs[2][16][128];
    int bm = bmi * 64;
    int bn = bni * 128;
    int tid = threadIdx.x;
    int tr = tid >> 5, tc = tid & 31;
    float acc[8][4];
    #pragma unroll
    for (int r = 0; r < 8; r++)
        #pragma unroll
        for (int c = 0; c < 4; c++) acc[r][c] = 0.f;

    #pragma unroll
    for (int j = 0; j < 4; j++) {
        int idx = tid + 256 * j;                 // 0..1023
        int m = idx >> 4, kk = idx & 15;
        int row = bm + m; if (row >= M) row = M - 1;
        As[0][kk][m] = A[(size_t)row * lda + kk];
    }
    #pragma unroll
    for (int j = 0; j < 8; j++) {
        int idx = tid + 256 * j;                 // 0..2047
        int kk = idx >> 7, n = idx & 127;
        Bs[0][kk][n] = (bn + n < Nn) ? B[(size_t)kk * Nn + bn + n] : 0.f;
    }
    __syncthreads();

    int buf = 0;
    for (int k0 = 0; k0 < K; k0 += 16) {
        int nb = buf ^ 1;
        if (k0 + 16 < K) {
            #pragma unroll
            for (int j = 0; j < 4; j++) {
                int idx = tid + 256 * j;
                int m = idx >> 4, kk = idx & 15;
                int row = bm + m; if (row >= M) row = M - 1;
                As[nb][kk][m] = A[(size_t)row * lda + k0 + 16 + kk];
            }
            #pragma unroll
            for (int j = 0; j < 8; j++) {
                int idx = tid + 256 * j;
                int kk = idx >> 7, n = idx & 127;
                Bs[nb][kk][n] = (bn + n < Nn) ? B[(size_t)(k0 + 16 + kk) * Nn + bn + n] : 0.f;
            }
        }
        #pragma unroll
        for (int kk = 0; kk < 16; kk++) {
            float4 b4 = *reinterpret_cast<const float4*>(&Bs[buf][kk][tc * 4]);
            #pragma unroll
            for (int r = 0; r < 8; r++) {
                float a = As[buf][kk][tr * 8 + r];
                acc[r][0] += a * b4.x; acc[r][1] += a * b4.y;
                acc[r][2] += a * b4.z; acc[r][3] += a * b4.w;
            }
        }
        __syncthreads();
        buf = nb;
    }
    #pragma unroll
    for (int r = 0; r < 8; r++) {
        int m = bm + tr * 8 + r;
        if (m >= M) continue;
        #pragma unroll
        for (int c = 0; c < 4; c++) {
            int n = bn + tc * 4 + c;
            if (n < Nn) {
                float v = acc[r][c];
                if (bias) v += bias[n];
                Cmat[(size_t)m * ldc + n] = v;
            }
        }
    }
}

__global__ void k_sgemm(const float* __restrict__ A, const float* __restrict__ B,
                        const float* __restrict__ bias, float* __restrict__ Cmat,
                        int M, int Nn, int K, int ldc) {
    sgemm_block(A, B, bias, Cmat, M, Nn, K, K, ldc, blockIdx.y, blockIdx.x);
}

// ----------------------------- init -----------------------------
__global__ void k_init(const float* __restrict__ sender, const float* __restrict__ receiver) {
    int i = blockIdx.x * blockDim.x + threadIdx.x;
    if (i < TWO_N) { g_deg[i] = 1.0f; g_degsp[i] = 1.0f; g_csr_cnt[i] = 0; }
    if (i < CC * DIM) g_pooled[i] = 0.f;
    if (i < CC * CC) g_G[i] = 0.f;
    if (i < 2 * DIM) (i < DIM ? g_dsum : g_ssum)[i & 127] = 0.f;
    if (i < 8) g_acc[i] = 0.f;
    if (i == 0) g_flag = (sender[0] == receiver[0]) ? 1 : 0;
}

// ----------------------------- stage1: prep + seqsum + edge1 + predg_zero -------------------------
__global__ void k_stage1(const float* __restrict__ m1wi, const float* __restrict__ m1wo,
                         const float* __restrict__ m1bo, const float* __restrict__ m1bi,
                         const float* __restrict__ m2wi,
                         const float* __restrict__ demand, const float* __restrict__ supply,
                         const int* __restrict__ dst, const float* __restrict__ w,
                         float* __restrict__ out_pred) {
    int b = blockIdx.x;
    int t = threadIdx.x;  // 256
    if (b < 256) {                        // Zcat
        int i = b * 256 + t;
        int row = i >> 7, tt = i & 127;
        int h = row >> 7, d = row & 127;
        const float* wv = m1wi + (size_t)2 * DIM * DIM;
        float acc = 0.f;
        #pragma unroll 8
        for (int j = 0; j < 32; j++)
            acc += m1wo[(size_t)tt * DIM + h * 32 + j] * wv[(size_t)(h * 32 + j) * DIM + d];
        g_Zcat[(size_t)row * DIM + tt] = acc;
    } else if (b == 256) {                // zb
        if (t < DIM) {
            const float* bv = m1bi + 2 * DIM;
            float acc = m1bo[t];
            #pragma unroll 8
            for (int k = 0; k < DIM; k++) acc += m1wo[(size_t)t * DIM + k] * bv[k];
            g_zb[t] = acc;
        }
    } else if (b < 321) {                 // m2wi transpose (64)
        int i = (b - 257) * 256 + t;
        int n = i >> 7, k = i & 127;
        g_wt[(size_t)k * DIM + n] = m2wi[(size_t)n * DIM + k];
    } else if (b < 369) {                 // seqsum (48)
        if (t < DIM) {
            int sb = b - 321;
            int tensor = sb / 24, chunk = sb % 24;
            const float* base = tensor ? supply : demand;
            float acc = 0.f;
            int n0 = chunk * 128;
            for (int n = n0; n < n0 + 128; n++)
                acc += base[(size_t)n * SEQ * DIM + (size_t)(SEQ - 1) * DIM + t];
            atomicAdd(&(tensor ? g_ssum : g_dsum)[t], acc);
        }
    } else if (b < 1137) {                // edge1 (768)
        int e = (b - 369) * 256 + t;
        if (e < EE) {
            int q = dst[e];
            atomicAdd(&g_degsp[q], w[e]);
            atomicAdd(&g_csr_cnt[q], 1);
        }
    } else if (b < 1393) {                // Wcomb (256): [128,512]
        int i = (b - 1137) * 256 + t;
        int k = i >> 9, col = i & 511;
        int h = col >> 7, d = col & 127;
        const float* wk = m1wi + (size_t)DIM * DIM;
        float acc = 0.f;
        #pragma unroll 8
        for (int j = 0; j < 32; j++)
            acc += m1wi[(size_t)(h * 32 + j) * DIM + k] * wk[(size_t)(h * 32 + j) * DIM + d];
        g_Wcomb[(size_t)k * 512 + col] = acc;
    } else if (b == 1393) {               // vqb [128][4]
        for (int i = t; i < DIM * HH; i += 256) {
            int k = i >> 2, h = i & 3;
            const float* bk = m1bi + DIM;
            float acc = 0.f;
            #pragma unroll 8
            for (int j = 0; j < 32; j++)
                acc += m1wi[(size_t)(h * 32 + j) * DIM + k] * bk[h * 32 + j];
            g_vqb[i] = acc;
        }
    } else if (b == 1394) {               // Ub [512] + cb[4]
        const float* wk = m1wi + (size_t)DIM * DIM;
        const float* bk = m1bi + DIM;
        for (int col = t; col < 512; col += 256) {
            int h = col >> 7, d = col & 127;
            float acc = 0.f;
            #pragma unroll 8
            for (int j = 0; j < 32; j++)
                acc += m1bi[h * 32 + j] * wk[(size_t)(h * 32 + j) * DIM + d];
            g_Ub[col] = acc;
        }
        if (t < HH) {
            float acc = 0.f;
            for (int j = 0; j < 32; j++) acc += m1bi[t * 32 + j] * bk[t * 32 + j];
            g_cb[t] = acc;
        }
    } else {                              // predg zero-fill (flag path) (2048)
        if (!g_flag) return;
        float4 z = make_float4(0.f, 0.f, 0.f, 0.f);
        float4* o = reinterpret_cast<float4*>(out_pred);
        size_t total = (size_t)TWO_N * TWO_N / 4;
        for (size_t j = (size_t)(b - 1395) * 256 + t; j < total; j += (size_t)2048 * 256)
            o[j] = z;
    }
}

// ----------------------------- stage2: scan (b0) + qv (merged, 1024 threads) ----------------------
__global__ void k_stage2(const float* __restrict__ skill, float* __restrict__ out_cat) {
    int b = blockIdx.x;
    int t = threadIdx.x;  // 1024
    if (b == 0) {         // scan
        __shared__ int sh[1024];
        int base = t * 6;
        int loc[6];
        int s = 0;
        #pragma unroll
        for (int k = 0; k < 6; k++) { loc[k] = s; s += g_csr_cnt[base + k]; }
        sh[t] = s;
        __syncthreads();
        for (int off = 1; off < 1024; off <<= 1) {
            int add = (t >= off) ? sh[t - off] : 0;
            __syncthreads();
            sh[t] += add;
            __syncthreads();
        }
        int excl = sh[t] - s;
        #pragma unroll
        for (int k = 0; k < 6; k++) {
            int o = excl + loc[k];
            g_csr_off[base + k] = o;
            g_csr_cnt[base + k] = o;
        }
        if (t == 1023) g_csr_off[TWO_N] = sh[1023];
    } else {              // qv + cq skill half + out_cat
        int i = (b - 1) * 1024 + t;
        int bb = i >> 7, tt = i & 127;
        bool dem = bb < NN;
        int idx = dem ? bb : bb - NN;
        float sv = skill[(size_t)idx * DIM + tt];
        g_qv[i] = sv + (dem ? g_dsum : g_ssum)[tt];
        g_cq[(size_t)bb * 640 + tt] = sv;
        out_cat[i] = sv;
    }
}

// ----------------------------- stage3: Wtop + Zf GEMM + fb + U GEMM -------------------------------
// [0,64) Wtop copy | [64,72) Zf GEMM | 72 fb | [73,457) U GEMM
__global__ void k_stage3(const float* __restrict__ w_fuse, const float* __restrict__ b_fuse) {
    int b = blockIdx.x;
    int t = threadIdx.x;  // 256
    if (b < 64) {             // Wtop copy
        int i = b * 256 + t;
        g_wbig[i] = w_fuse[i];
    } else if (b < 72) {      // Zf = Zcat @ Wf_bot -> wbig rows 128..639 (8 tiles of 64)
        sgemm_block(g_Zcat, w_fuse + (size_t)DIM * DIM, nullptr, g_wbig + (size_t)DIM * DIM,
                    512, DIM, DIM, DIM, DIM, b - 64, 0);
    } else if (b == 72) {     // fb
        if (t < DIM) {
            float acc = b_fuse[t];
            #pragma unroll 8
            for (int k = 0; k < DIM; k++) acc += g_zb[k] * w_fuse[(size_t)(DIM + k) * DIM + t];
            g_fb[t] = acc;
        }
    } else {                  // U = qv @ Wcomb + Ub (384 blocks: 96 M-tiles x 4 N-tiles)
        int idx = b - 73;
        sgemm_block(g_qv, g_Wcomb, g_Ub, g_U, TWO_N, 4 * DIM, DIM, DIM, 4 * DIM,
                    idx % 96, idx / 96);
    }
}

// ----------------------------- attn1 + fillcsr (merged, 128 threads) ------------------------------
__global__ void k_attn1(const float* __restrict__ demand, const float* __restrict__ supply,
                        const int* __restrict__ src, const int* __restrict__ dst,
                        const float* __restrict__ w) {
    int b = blockIdx.x;
    int t = threadIdx.x;  // 128
    if (b >= TWO_N) {     // fillcsr
        int e = (b - TWO_N) * 128 + t;
        if (e < EE) {
            int s = src[e], q = dst[e];
            float we = w[e];
            int pos = atomicAdd(&g_csr_cnt[q], 1);
            g_csr_src[pos] = s;
            g_csr_coef[pos] = rsqrtf(g_degsp[s]) * rsqrtf(g_degsp[q]) * we;
            g_csr_w[pos] = we;
        }
        return;
    }
    int wd = t >> 5, lane = t & 31;
    bool dem = b < NN;
    int idx = dem ? b : b - NN;
    const float* seq = (dem ? demand : supply) + (size_t)idx * SEQ * DIM;

    __shared__ float sh_seq[SEQ][DIM + 1];
    __shared__ float sh_U[HH][DIM];
    __shared__ float sh_p[HH][SEQ];

    for (int i = t; i < SEQ * DIM; i += 128) sh_seq[i >> 7][i & 127] = seq[i];
    for (int i = t; i < HH * DIM; i += 128) sh_U[i >> 7][i & 127] = g_U[(size_t)b * 512 + i];
    __syncthreads();

    float qb = 0.f;
    #pragma unroll
    for (int m = 0; m < 4; m++) {
        int k = lane + 32 * m;
        qb += g_qv[(size_t)b * DIM + k] * g_vqb[k * HH + wd];
    }
    #pragma unroll
    for (int o = 16; o > 0; o >>= 1) qb += __shfl_xor_sync(0xffffffff, qb, o);
    qb += g_cb[wd];

    float myl = -1e30f;
    if (lane < SEQ) {
        float acc = 0.f;
        #pragma unroll 16
        for (int d = 0; d < DIM; d++) acc += sh_U[wd][d] * sh_seq[lane][d];
        myl = (acc + qb) * INV_SQRT_HD;
    }
    float mx = myl;
    #pragma unroll
    for (int o = 8; o > 0; o >>= 1) mx = fmaxf(mx, __shfl_xor_sync(0xffffffff, mx, o));
    float e = (lane < SEQ) ? expf(myl - mx) : 0.f;
    float sm = e;
    #pragma unroll
    for (int o = 8; o > 0; o >>= 1) sm += __shfl_xor_sync(0xffffffff, sm, o);
    if (lane < SEQ) sh_p[wd][lane] = e / sm;
    __syncthreads();

    #pragma unroll
    for (int k = 0; k < 4; k++) {
        int d = lane + 32 * k;
        float acc = 0.f;
        #pragma unroll
        for (int s = 0; s < SEQ; s++) acc += sh_p[wd][s] * sh_seq[s][d];
        g_cq[(size_t)b * 640 + 128 + wd * DIM + d] = acc;
    }
}

// ----------------------------- stage8: tanhprep + dense-l0 GEMM + sparse-l0 GEMM -------------------
__global__ void k_stage8(const float* __restrict__ sender, const float* __restrict__ receiver,
                         const float* __restrict__ W0, const float* __restrict__ W1) {
    int b = blockIdx.x;
    if (b < 3072) {
        if (g_flag) return;
        int i = b * 256 + threadIdx.x;
        float f = g_fused[i];
        g_s1[i] = tanhf(sender[0] * f);
        g_s2[i] = tanhf(receiver[0] * f);
    } else if (b < 3168) {
        sgemm_block(g_fused, W0, nullptr, g_xw, TWO_N, DIM, DIM, DIM, DIM, b - 3072, 0);
    } else {
        sgemm_block(g_fused, W1, nullptr, g_xw2, TWO_N, DIM, DIM, DIM, DIM, b - 3168, 0);
    }
}

// ----------------------------- scores (general path; grid-stride) -----------------------------
__global__ void k_scores() {
    if (g_flag) return;
    __shared__ float A1[16][DIM], A2[16][DIM], B1[16][DIM], B2[16][DIM];
    int t = threadIdx.x;  // 256
    const int TILES = TWO_N / 16;
    for (int tile = blockIdx.x; tile < TILES * TILES; tile += gridDim.x) {
        int i0 = (tile / TILES) * 16, j0 = (tile % TILES) * 16;
        __syncthreads();
        for (int j = 0; j < 8; j++) {
            int idx = t + 256 * j;
            int r = idx >> 7, c = idx & 127;
            A1[r][c] = g_s1[(size_t)(i0 + r) * DIM + c];
            A2[r][c] = g_s2[(size_t)(i0 + r) * DIM + c];
            B1[r][c] = g_s1[(size_t)(j0 + r) * DIM + c];
            B2[r][c] = g_s2[(size_t)(j0 + r) * DIM + c];
        }
        __syncthreads();
        int ti = t >> 4, tj = t & 15;
        float acc = 0.f;
        for (int k = 0; k < DIM; k++)
            acc += A1[ti][k] * B2[tj][k] - A2[ti][k] * B1[tj][k];
        g_scores[(size_t)(i0 + ti) * TWO_N + j0 + tj] = acc;
    }
}

// ----------------------------- predg general (softmax+threshold+deg) ------------------------------
__global__ void k_predg_general(float* __restrict__ out_pred) {
    if (g_flag) return;
    int row = blockIdx.x;
    int t = threadIdx.x;  // 256
    __shared__ float sh[256];
    float* sr = g_scores + (size_t)row * TWO_N;
    float mx = 0.f;
    for (int i = t; i < TWO_N; i += 256) mx = fmaxf(mx, fmaxf(sr[i], 0.f));
    mx = blockReduceMax(mx, sh);
    float sum = 0.f;
    for (int i = t; i < TWO_N; i += 256) sum += expf(fmaxf(sr[i], 0.f) - mx);
    sum = blockReduceSum(sum, sh);
    float inv = 1.f / sum;
    for (int i = t; i < TWO_N; i += 256) {
        float p = expf(fmaxf(sr[i], 0.f) - mx) * inv;
        float pr = fmaxf(p - DELTA_T, 0.f);
        sr[i] = pr;
        out_pred[(size_t)row * TWO_N + i] = pr;
        if (pr != 0.f) atomicAdd(&g_deg[i], pr);
    }
}

// ----------------------------- dense agg (general path) -----------------------------
__global__ void k_dense_agg() {
    if (g_flag) return;
    int i0 = blockIdx.x * 32;
    int t = threadIdx.x;  // 256
    __shared__ float pcol[32];
    __shared__ float xrow[DIM];
    int dbase = t & 127, half = t >> 7;
    float acc[16];
    #pragma unroll
    for (int r = 0; r < 16; r++) acc[r] = 0.f;
    for (int j = 0; j < TWO_N; j++) {
        if (t < 32) pcol[t] = g_scores[(size_t)j * TWO_N + i0 + t];
        else if (t >= 128 && t < 256) {
            float sj = rsqrtf(g_deg[j]);
            xrow[t - 128] = sj * g_xw[(size_t)j * DIM + (t - 128)];
        }
        __syncthreads();
        #pragma unroll
        for (int r = 0; r < 16; r++) acc[r] += pcol[half + 2 * r] * xrow[dbase];
        __syncthreads();
    }
    #pragma unroll
    for (int r = 0; r < 16; r++) {
        int i = i0 + half + 2 * r;
        float di = rsqrtf(g_deg[i]);
        g_agg[(size_t)i * DIM + dbase] = acc[r] + di * g_xw[(size_t)i * DIM + dbase];
    }
}

// ---------------- device bodies: float4 dense combine / sparse gather ----------------
__device__ __forceinline__ float4 dense_combine_val4(int i4, const float* __restrict__ prev,
                                                     const float* __restrict__ b0, int layer) {
    int i = i4 * 4;
    int row = i >> 7, cb = i & 127;
    float di = rsqrtf(g_deg[row]);
    const float4* xw4 = reinterpret_cast<const float4*>(g_xw);
    const float4* agg4 = reinterpret_cast<const float4*>(g_agg);
    float4 v;
    if (g_flag) {
        float s = di * di;
        float4 x = xw4[i4];
        v = make_float4(s * x.x, s * x.y, s * x.z, s * x.w);
    } else {
        float4 a = agg4[i4];
        v = make_float4(di * a.x, di * a.y, di * a.z, di * a.w);
    }
    const float4* b4p = reinterpret_cast<const float4*>(b0 + layer * DIM + cb);
    float4 bb = *b4p;
    const float4* p4 = reinterpret_cast<const float4*>(prev);
    float4 pv = p4[i4];
    float4 r;
    r.x = (1.f - PRESERVE) * (v.x + bb.x) + PRESERVE * pv.x;
    r.y = (1.f - PRESERVE) * (v.y + bb.y) + PRESERVE * pv.y;
    r.z = (1.f - PRESERVE) * (v.z + bb.z) + PRESERVE * pv.z;
    r.w = (1.f - PRESERVE) * (v.w + bb.w) + PRESERVE * pv.w;
    return r;
}
__device__ __forceinline__ float4 spgather_val4(int q, int c4, const float* __restrict__ xw,
                                                const float* __restrict__ prev,
                                                const float* __restrict__ b1, int layer) {
    const float4* xw4 = reinterpret_cast<const float4*>(xw);
    float dv = rsqrtf(g_degsp[q]);
    float s0c = dv * dv;
    float4 x0 = xw4[(size_t)q * 32 + c4];
    float4 acc = make_float4(s0c * x0.x, s0c * x0.y, s0c * x0.z, s0c * x0.w);
    int beg = g_csr_off[q], end = g_csr_off[q + 1];
    for (int j = beg; j < end; j++) {
        float cf = g_csr_coef[j];
        int s = g_csr_src[j];
        float4 x = xw4[(size_t)s * 32 + c4];
        acc.x += cf * x.x; acc.y += cf * x.y; acc.z += cf * x.z; acc.w += cf * x.w;
    }
    const float4* b4p = reinterpret_cast<const float4*>(b1 + layer * DIM + c4 * 4);
    float4 bb = *b4p;
    const float4* p4 = reinterpret_cast<const float4*>(prev);
    float4 pv = p4[(size_t)q * 32 + c4];
    float4 r;
    r.x = (1.f - PRESERVE) * (acc.x + bb.x) + PRESERVE * pv.x;
    r.y = (1.f - PRESERVE) * (acc.y + bb.y) + PRESERVE * pv.y;
    r.z = (1.f - PRESERVE) * (acc.z + bb.z) + PRESERVE * pv.z;
    r.w = (1.f - PRESERVE) * (acc.w + bb.w) + PRESERVE * pv.w;
    return r;
}

// stage12: dense_combine l0 (float4) + spgather l0 (float4, 8 nodes/block)
__global__ void k_stage12(const float* __restrict__ b0, const float* __restrict__ b1) {
    int b = blockIdx.x;
    int t = threadIdx.x;  // 256
    if (b < 768) {
        int i4 = b * 256 + t;
        reinterpret_cast<float4*>(g_tmpA)[i4] = dense_combine_val4(i4, g_fused, b0, 0);
    } else {
        int q = (b - 768) * 8 + (t >> 5);
        int c4 = t & 31;
        reinterpret_cast<float4*>(g_tmpB)[(size_t)q * 32 + c4] =
            spgather_val4(q, c4, g_xw2, g_fused, b1, 0);
    }
}

// stage13: dense l1 GEMM + sparse l1 GEMM (merged, 96+96 blocks)
__global__ void k_stage13(const float* __restrict__ W0, const float* __restrict__ W1) {
    int b = blockIdx.x;
    if (b < 96) sgemm_block(g_tmpA, W0 + (size_t)DIM * DIM, nullptr, g_xw, TWO_N, DIM, DIM, DIM, DIM, b, 0);
    else        sgemm_block(g_tmpB, W1 + (size_t)DIM * DIM, nullptr, g_xw2, TWO_N, DIM, DIM, DIM, DIM, b - 96, 0);
}

// stage16: fused dense_combine l1 + spgather l1 -> emb (float4, 8 nodes/block)
__global__ void k_stage16(const float* __restrict__ b0, const float* __restrict__ b1) {
    int t = threadIdx.x;  // 256
    int q = blockIdx.x * 8 + (t >> 5);
    int c4 = t & 31;
    int i4 = q * 32 + c4;
    float4 dense = dense_combine_val4(i4, g_tmpA, b0, 1);
    float4 sp = spgather_val4(q, c4, g_xw2, g_tmpB, b1, 1);
    reinterpret_cast<float4*>(g_emb)[i4] =
        make_float4(dense.x + sp.x, dense.y + sp.y, dense.z + sp.z, dense.w + sp.w);
}

// ----------------------------- sm GEMM with fused softmax + entropy -------------------------------
__global__ void k_sm_gemm(const float* __restrict__ Wp, const float* __restrict__ bp) {
    __shared__ float As[2][16][33];
    __shared__ float Bs[2][16][128];
    int bm = blockIdx.x * 32;
    int tid = threadIdx.x;
    int tr = tid >> 5, tc = tid & 31;
    float acc[4][4];
    #pragma unroll
    for (int r = 0; r < 4; r++)
        #pragma unroll
        for (int c = 0; c < 4; c++) acc[r][c] = 0.f;

    #pragma unroll
    for (int j = 0; j < 2; j++) {
        int idx = tid + 256 * j;
        int m = idx >> 4, kk = idx & 15;
        As[0][kk][m] = g_emb[(size_t)(bm + m) * DIM + kk];
    }
    #pragma unroll
    for (int j = 0; j < 8; j++) {
        int idx = tid + 256 * j;
        int kk = idx >> 7, n = idx & 127;
        Bs[0][kk][n] = (n < CC) ? Wp[(size_t)kk * CC + n] : 0.f;
    }
    __syncthreads();
    int buf = 0;
    for (int k0 = 0; k0 < DIM; k0 += 16) {
        int nb = buf ^ 1;
        if (k0 + 16 < DIM) {
            #pragma unroll
            for (int j = 0; j < 2; j++) {
                int idx = tid + 256 * j;
                int m = idx >> 4, kk = idx & 15;
                As[nb][kk][m] = g_emb[(size_t)(bm + m) * DIM + k0 + 16 + kk];
            }
            #pragma unroll
            for (int j = 0; j < 8; j++) {
                int idx = tid + 256 * j;
                int kk = idx >> 7, n = idx & 127;
                Bs[nb][kk][n] = (n < CC) ? Wp[(size_t)(k0 + 16 + kk) * CC + n] : 0.f;
            }
        }
        #pragma unroll
        for (int kk = 0; kk < 16; kk++) {
            float a0 = As[buf][kk][tr * 4 + 0];
            float a1 = As[buf][kk][tr * 4 + 1];
            float a2 = As[buf][kk][tr * 4 + 2];
            float a3 = As[buf][kk][tr * 4 + 3];
            float4 b4 = *reinterpret_cast<const float4*>(&Bs[buf][kk][tc * 4]);
            acc[0][0] += a0 * b4.x; acc[0][1] += a0 * b4.y; acc[0][2] += a0 * b4.z; acc[0][3] += a0 * b4.w;
            acc[1][0] += a1 * b4.x; acc[1][1] += a1 * b4.y; acc[1][2] += a1 * b4.z; acc[1][3] += a1 * b4.w;
            acc[2][0] += a2 * b4.x; acc[2][1] += a2 * b4.y; acc[2][2] += a2 * b4.z; acc[2][3] += a2 * b4.w;
            acc[3][0] += a3 * b4.x; acc[3][1] += a3 * b4.y; acc[3][2] += a3 * b4.z; acc[3][3] += a3 * b4.w;
        }
        __syncthreads();
        buf = nb;
    }
    float entpart = 0.f;
    #pragma unroll
    for (int r = 0; r < 4; r++) {
        int row = bm + tr * 4 + r;
        float v[4];
        float mx = -1e30f;
        #pragma unroll
        for (int c = 0; c < 4; c++) {
            int n = tc * 4 + c;
            v[c] = (n < CC) ? (acc[r][c] + bp[n]) : -1e30f;
            mx = fmaxf(mx, v[c]);
        }
        #pragma unroll
        for (int o = 16; o > 0; o >>= 1) mx = fmaxf(mx, __shfl_xor_sync(0xffffffff, mx, o));
        float sm = 0.f;
        float ex[4];
        #pragma unroll
        for (int c = 0; c < 4; c++) {
            int n = tc * 4 + c;
            ex[c] = (n < CC) ? expf(v[c] - mx) : 0.f;
            sm += ex[c];
        }
        #pragma unroll
        for (int o = 16; o > 0; o >>= 1) sm += __shfl_xor_sync(0xffffffff, sm, o);
        float inv = 1.f / sm;
        #pragma unroll
        for (int c = 0; c < 4; c++) {
            int n = tc * 4 + c;
            if (n < CC) {
                float p = ex[c] * inv;
                g_sm[(size_t)row * CC + n] = p;
                entpart += -p * logf(p + 1e-15f);
            }
        }
    }
    #pragma unroll
    for (int o = 16; o > 0; o >>= 1) entpart += __shfl_xor_sync(0xffffffff, entpart, o);
    if (tc == 0) atomicAdd(&g_acc[2], entpart);
}

// ----------------------------- stage19: poolgram + cross + qp2 GEMM -------------------------------
// [0,192) poolgram | [192,6336) cross | [6336,6432) qp2
__global__ void k_stage19(const float* __restrict__ m2bi) {
    extern __shared__ float dyn[];      // poolgram staging: S[32][104] + E[32][128]
    __shared__ float shred[256];
    int b = blockIdx.x;
    int t = threadIdx.x;  // 256
    if (b < 192) {            // poolgram
        float* S_s = dyn;
        float* E_s = dyn + 32 * 104;
        int i0 = b * 32;
        for (int idx = t; idx < 32 * CC; idx += 256) {
            int r = idx / CC, c = idx % CC;
            S_s[r * 104 + c] = g_sm[(size_t)(i0 + r) * CC + c];
        }
        for (int idx = t; idx < 32 * DIM; idx += 256) {
            int r = idx >> 7, d = idx & 127;
            E_s[r * 128 + d] = g_emb[(size_t)(i0 + r) * DIM + d];
        }
        __syncthreads();
        for (int o = t; o < CC * 32; o += 256) {
            int c = o >> 5, d4 = o & 31;
            float4 a = make_float4(0.f, 0.f, 0.f, 0.f);
            for (int r = 0; r < 32; r++) {
                float s = S_s[r * 104 + c];
                float4 e4 = *reinterpret_cast<const float4*>(&E_s[r * 128 + d4 * 4]);
                a.x += s * e4.x; a.y += s * e4.y; a.z += s * e4.z; a.w += s * e4.w;
            }
            atomicAdd(&g_pooled[(size_t)c * DIM + d4 * 4 + 0], a.x);
            atomicAdd(&g_pooled[(size_t)c * DIM + d4 * 4 + 1], a.y);
            atomicAdd(&g_pooled[(size_t)c * DIM + d4 * 4 + 2], a.z);
            atomicAdd(&g_pooled[(size_t)c * DIM + d4 * 4 + 3], a.w);
        }
        for (int o = t; o < CC * 25; o += 256) {
            int c1 = o / 25, c2g = o % 25;
            float4 a = make_float4(0.f, 0.f, 0.f, 0.f);
            for (int r = 0; r < 32; r++) {
                float s = S_s[r * 104 + c1];
                float4 s4 = *reinterpret_cast<const float4*>(&S_s[r * 104 + c2g * 4]);
                a.x += s * s4.x; a.y += s * s4.y; a.z += s * s4.z; a.w += s * s4.w;
            }
            atomicAdd(&g_G[c1 * CC + c2g * 4 + 0], a.x);
            atomicAdd(&g_G[c1 * CC + c2g * 4 + 1], a.y);
            atomicAdd(&g_G[c1 * CC + c2g * 4 + 2], a.z);
            atomicAdd(&g_G[c1 * CC + c2g * 4 + 3], a.w);
        }
    } else if (b < 6336) {    // cross: <A,SS^T> via CSR gather + Adense scatter
        int q = b - 192;
        int beg = g_csr_off[q], end = g_csr_off[q + 1];
        float acc = 0.f;
        if (t < CC) {
            float tsum = 0.f;
            for (int j = beg; j < end; j++)
                tsum += g_csr_w[j] * g_sm[(size_t)g_csr_src[j] * CC + t];
            acc = tsum * g_sm[(size_t)q * CC + t];
        }
        float s = blockReduceSum(acc, shred);
        if (t == 0 && s != 0.f) atomicAdd(&g_acc[1], s);
        for (int j = beg + t; j < end; j += 256)
            atomicAdd(&g_Adense[(size_t)g_csr_src[j] * TWO_N + q], g_csr_w[j]);
    } else {                  // qp2 GEMM (96 blocks)
        sgemm_block(g_emb, g_wt, m2bi, g_qp2, TWO_N, DIM, DIM, DIM, DIM, b - 6336, 0);
    }
}

// ----------------------------- stage20: kvproj + normA (merged) -----------------------------------
__global__ void k_stage20(const float* __restrict__ wi, const float* __restrict__ bi,
                          const int* __restrict__ src, const int* __restrict__ dst) {
    int b = blockIdx.x;
    int t = threadIdx.x;  // 256
    if (b < 200) {
        __shared__ float prow[DIM];
        int c = b >> 1, which = b & 1;
        if (t < 128) prow[t] = g_pooled[(size_t)c * DIM + t];
        __syncthreads();
        if (t >= 128) return;
        const float4* row4 = reinterpret_cast<const float4*>(wi + (size_t)(DIM + which * DIM + t) * DIM);
        float acc = bi[DIM + which * DIM + t];
        #pragma unroll
        for (int k = 0; k < 32; k++) {
            float4 r = row4[k];
            acc += r.x * prow[4 * k] + r.y * prow[4 * k + 1]
                 + r.z * prow[4 * k + 2] + r.w * prow[4 * k + 3];
        }
        (which ? g_vp2 : g_kp2)[(size_t)c * DIM + t] = acc;
    } else {
        __shared__ float sh[256];
        int e = (b - 200) * 256 + t;
        float v = 0.f;
        if (e < EE) {
            float old = atomicExch(&g_Adense[(size_t)src[e] * TWO_N + dst[e]], 0.f);
            v = old * old;
        }
        float s = blockReduceSum(v, sh);
        if (t == 0 && s != 0.f) atomicAdd(&g_acc[0], s);
    }
}

// ----------------------------- stage21: mha2 (2 queries/iter, 256 thr) + gramfin ------------------
#define K_LD 129
__global__ void k_stage21(const float* __restrict__ wo, const float* __restrict__ bo,
                          float* __restrict__ out_skill, float* __restrict__ out_loss) {
    extern __shared__ float kp_s[];     // [CC][K_LD]
    int t = threadIdx.x;  // 256
    if (blockIdx.x == 384) {            // gramfin
        __shared__ float sh[256];
        float acc = 0.f;
        for (int i = t; i < CC * CC; i += 256) { float g = g_G[i]; acc += g * g; }
        float s = blockReduceSum(acc, sh);
        if (t == 0) {
            float n2 = g_acc[0] - 2.f * g_acc[1] + s;
            float link = sqrtf(fmaxf(n2, 0.f)) / ((float)TWO_N * (float)TWO_N);
            out_loss[0] = link + g_acc[2] / (float)TWO_N;
        }
        return;
    }
    __shared__ float qrow[2][DIM];
    __shared__ float lg[2][HH][CC];
    __shared__ float o_s[2][DIM];
    int g = t >> 7;            // query group 0/1
    int tg = t & 127;
    int w = tg >> 5, lane = tg & 31;
    for (int i = t; i < CC * DIM; i += 256) {
        int j = i >> 7, d = i & 127;
        kp_s[j * K_LD + d] = g_kp2[i];
    }
    __syncthreads();
    int n0 = blockIdx.x * 16;
    for (int q = 0; q < 16; q += 2) {
        int n = n0 + q + g;
        qrow[g][tg] = g_qp2[(size_t)n * DIM + tg];
        __syncthreads();
        for (int pos = tg; pos < HH * CC; pos += 128) {
            int h = pos / CC, j = pos % CC;
            float acc = 0.f;
            #pragma unroll 8
            for (int d = 0; d < HD; d++)
                acc += qrow[g][h * HD + d] * kp_s[j * K_LD + h * HD + d];
            lg[g][h][j] = acc * INV_SQRT_HD;
        }
        __syncthreads();
        {
            float mx = -1e30f;
            for (int j = lane; j < CC; j += 32) mx = fmaxf(mx, lg[g][w][j]);
            #pragma unroll
            for (int o = 16; o > 0; o >>= 1) mx = fmaxf(mx, __shfl_xor_sync(0xffffffff, mx, o));
            float sm = 0.f;
            for (int j = lane; j < CC; j += 32) { float e = expf(lg[g][w][j] - mx); lg[g][w][j] = e; sm += e; }
            #pragma unroll
            for (int o = 16; o > 0; o >>= 1) sm += __shfl_xor_sync(0xffffffff, sm, o);
            float inv = 1.f / sm;
            for (int j = lane; j < CC; j += 32) lg[g][w][j] *= inv;
        }
        __syncthreads();
        {
            float acc = 0.f;
            for (int j = 0; j < CC; j++) acc += lg[g][w][j] * g_vp2[(size_t)j * DIM + tg];
            o_s[g][tg] = acc;
        }
        __syncthreads();
        {
            const float4* row4 = reinterpret_cast<const float4*>(wo + (size_t)tg * DIM);
            float acc = bo[tg];
            #pragma unroll
            for (int k = 0; k < 32; k++) {
                float4 r = row4[k];
                acc += r.x * o_s[g][4 * k] + r.y * o_s[g][4 * k + 1]
                     + r.z * o_s[g][4 * k + 2] + r.w * o_s[g][4 * k + 3];
            }
            out_skill[(size_t)n * DIM + tg] = 2.f * g_emb[(size_t)n * DIM + tg] + acc;
        }
        __syncthreads();
    }
}

// ----------------------------- host launch -----------------------------
extern "C" void kernel_launch(void* const* d_in, const int* in_sizes, int n_in,
                              void* d_out, int out_size) {
    const float* demand = (const float*)d_in[0];
    const float* supply = (const float*)d_in[1];
    const float* skill  = (const float*)d_in[2];
    const int*   eidx   = (const int*)d_in[3];
    const float* eattr  = (const float*)d_in[4];
    const float* w_fuse = (const float*)d_in[5];
    const float* b_fuse = (const float*)d_in[6];
    const float* m1wi   = (const float*)d_in[7];
    const float* m1bi   = (const float*)d_in[8];
    const float* m1wo   = (const float*)d_in[9];
    const float* m1bo   = (const float*)d_in[10];
    const float* m2wi   = (const float*)d_in[11];
    const float* m2bi   = (const float*)d_in[12];
    const float* m2wo   = (const float*)d_in[13];
    const float* m2bo   = (const float*)d_in[14];
    const float* sender = (const float*)d_in[15];
    const float* recv   = (const float*)d_in[16];
    const float* W0     = (const float*)d_in[17];
    const float* b0     = (const float*)d_in[18];
    const float* W1     = (const float*)d_in[19];
    const float* b1     = (const float*)d_in[20];
    const float* Wp     = (const float*)d_in[21];
    const float* bp     = (const float*)d_in[22];
    float* out = (float*)d_out;
    const int* src = eidx;
    const int* dst = eidx + EE;

    cudaFuncSetAttribute(k_stage19, cudaFuncAttributeMaxDynamicSharedMemorySize,
                         (32 * 104 + 32 * 128) * (int)sizeof(float) + 1024);
    cudaFuncSetAttribute(k_stage21, cudaFuncAttributeMaxDynamicSharedMemorySize,
                         CC * K_LD * (int)sizeof(float) + 2048);

    float *p_cq, *p_wbig, *p_fb, *p_fused;
    cudaGetSymbolAddress((void**)&p_cq, g_cq);
    cudaGetSymbolAddress((void**)&p_wbig, g_wbig);
    cudaGetSymbolAddress((void**)&p_fb, g_fb);
    cudaGetSymbolAddress((void**)&p_fused, g_fused);

    k_init<<<64, 256>>>(sender, recv);
    k_stage1<<<3443, 256>>>(m1wi, m1wo, m1bo, m1bi, m2wi, demand, supply, dst, eattr,
                            out + OUT_PRED);
    k_stage2<<<769, 1024>>>(skill, out + OUT_CAT);
    k_stage3<<<457, 256>>>(w_fuse, b_fuse);
    k_attn1<<<TWO_N + 1536, 128>>>(demand, supply, src, dst, eattr);
    k_sgemm<<<dim3(1, 96), 256>>>(p_cq, p_wbig, p_fb, p_fused, TWO_N, DIM, 640, DIM);

    k_stage8<<<3264, 256>>>(sender, recv, W0, W1);
    k_scores<<<1184, 256>>>();
    k_predg_general<<<TWO_N, 256>>>(out + OUT_PRED);
    k_dense_agg<<<TWO_N / 32, 256>>>();
    k_stage12<<<1536, 256>>>(b0, b1);
    k_stage13<<<192, 256>>>(W0, W1);
    k_dense_agg<<<TWO_N / 32, 256>>>();
    k_stage16<<<768, 256>>>(b0, b1);

    k_sm_gemm<<<192, 256>>>(Wp, bp);
    k_stage19<<<6432, 256, (32 * 104 + 32 * 128) * sizeof(float)>>>(m2bi);
    k_stage20<<<968, 256>>>(m2wi, m2bi, src, dst);
    k_stage21<<<385, 256, CC * K_LD * sizeof(float) + 2048>>>(m2wo, m2bo, out + OUT_SKILL, out + OUT_LOSS);
}